// round 4
// baseline (speedup 1.0000x reference)
#include <cuda_runtime.h>
#include <cuda_bf16.h>
#include <cstdint>

// ---------------- problem constants ----------------
#define NLAYERS 4
#define INSZ    80
#define DMODEL  512
#define NHEAD   8
#define DH      64
#define DFF     2048
#define BATCH   16
#define SMAX    512
#define NTOK    (BATCH * SMAX)   // 8192

typedef __nv_bfloat16 bf16;

// ---------------- scratch (device globals; no allocs allowed) ----------------
__device__ float g_h   [NTOK * DMODEL];
__device__ float g_qkv [NTOK * 3 * DMODEL];
__device__ float g_pool[BATCH * 8 * DMODEL];

__device__ bf16 g_h_hi [NTOK * DMODEL],  g_h_lo [NTOK * DMODEL];
__device__ bf16 g_ctx_hi[NTOK * DMODEL], g_ctx_lo[NTOK * DMODEL];
__device__ bf16 g_ff_hi[NTOK * DFF],     g_ff_lo[NTOK * DFF];

__device__ bf16 g_wqkv_hi[NLAYERS * 3 * DMODEL * DMODEL], g_wqkv_lo[NLAYERS * 3 * DMODEL * DMODEL];
__device__ bf16 g_wo_hi  [NLAYERS * DMODEL * DMODEL],     g_wo_lo  [NLAYERS * DMODEL * DMODEL];
__device__ bf16 g_w1_hi  [NLAYERS * DFF * DMODEL],        g_w1_lo  [NLAYERS * DFF * DMODEL];
__device__ bf16 g_w2_hi  [NLAYERS * DMODEL * DFF],        g_w2_lo  [NLAYERS * DMODEL * DFF];

enum { EPI_NONE = 0, EPI_RELU = 2, EPI_RES = 3 };

// ---------------- helpers -----------------------------------------------------
__device__ __forceinline__ void mma16816(float* d, const uint32_t* a, const uint32_t* b) {
    asm volatile(
        "mma.sync.aligned.m16n8k16.row.col.f32.bf16.bf16.f32 "
        "{%0,%1,%2,%3},{%4,%5,%6,%7},{%8,%9},{%0,%1,%2,%3};\n"
        : "+f"(d[0]), "+f"(d[1]), "+f"(d[2]), "+f"(d[3])
        : "r"(a[0]), "r"(a[1]), "r"(a[2]), "r"(a[3]), "r"(b[0]), "r"(b[1]));
}

__device__ __forceinline__ void ldm4(uint32_t* r, uint32_t addr) {
    asm volatile("ldmatrix.sync.aligned.m8n8.x4.shared.b16 {%0,%1,%2,%3}, [%4];"
                 : "=r"(r[0]), "=r"(r[1]), "=r"(r[2]), "=r"(r[3]) : "r"(addr));
}

__device__ __forceinline__ void split1(float v, bf16& h, bf16& l) {
    h = __float2bfloat16(v);
    l = __float2bfloat16(v - __bfloat162float(h));
}

__device__ __forceinline__ void split4(float4 v, bf16* dh, bf16* dl) {
    union { bf16 b[4]; uint2 u; } H, L;
    split1(v.x, H.b[0], L.b[0]);
    split1(v.y, H.b[1], L.b[1]);
    split1(v.z, H.b[2], L.b[2]);
    split1(v.w, H.b[3], L.b[3]);
    *reinterpret_cast<uint2*>(dh) = H.u;
    *reinterpret_cast<uint2*>(dl) = L.u;
}

__device__ __forceinline__ void cp16(uint32_t saddr, const void* g) {
    asm volatile("cp.async.cg.shared.global [%0], [%1], 16;\n" :: "r"(saddr), "l"(g));
}
__device__ __forceinline__ void cp_commit() {
    asm volatile("cp.async.commit_group;\n");
}
template <int N>
__device__ __forceinline__ void cp_wait() {
    asm volatile("cp.async.wait_group %0;\n" :: "n"(N));
}

// ---------------- fp32 -> hi/lo split kernel ---------------------------------
__global__ __launch_bounds__(256) void split_kernel(
    const float* __restrict__ src, bf16* __restrict__ hi, bf16* __restrict__ lo)
{
    const int i = (blockIdx.x * 256 + threadIdx.x) * 4;
    float4 v = *(const float4*)(src + i);
    split4(v, hi + i, lo + i);
}

// =============================================================================
// bf16 split-precision tensor-core GEMM (pre-split operands):
//   C[M,N] = (Ah+Al)[M,K] * (Bh+Bl)[N,K]^T + bias (+epilogue)
//   acc += Ah*Bh + Ah*Bl + Al*Bh  (fp32 accum)
// 512 threads, 128x128x32 tile, warp tile 32x32, 3-stage cp.async,
// ldmatrix fragment loads (conflict-free with 80B padded rows).
// =============================================================================
#define BK    32
#define LDSK  40                    // padded k-stride (elems) = 80 B rows
#define PLE   (128 * LDSK)          // elems per plane  (10 KB)
#define BUFE  (4 * PLE)             // elems per stage  (40 KB)
#define NSTG  3
#define GSMEM (NSTG * BUFE * 2)     // 122880 B

template <int EPI>
__global__ __launch_bounds__(512, 1) void bgemm_kernel(
    const bf16* __restrict__ Ah, const bf16* __restrict__ Al,
    const bf16* __restrict__ Bh, const bf16* __restrict__ Bl,
    const float* __restrict__ bias, const float* __restrict__ res,
    float* __restrict__ Cf, bf16* __restrict__ Chi, bf16* __restrict__ Clo,
    int M, int N, int K)
{
    extern __shared__ bf16 sm[];
    const uint32_t smbase = (uint32_t)__cvta_generic_to_shared(sm);

    const int tid = threadIdx.x;
    const int bm = blockIdx.y * 128;
    const int bn = blockIdx.x * 128;

    const int wid  = tid >> 5;
    const int wm   = wid & 3;        // m warp 0..3 (32 rows each)
    const int wn   = wid >> 2;       // n warp 0..3 (32 cols each)
    const int lane = tid & 31;
    const int g    = lane >> 2;
    const int tg   = lane & 3;

    // ldmatrix lane-address components
    const int arow = (lane & 7) | (((lane >> 3) & 1) << 3);  // A: row-within-16
    const int akh  = (lane >> 4) * 8;                        // A: k half
    const int brow = (lane & 7) | (((lane >> 4) & 1) << 3);  // B: row-within-16
    const int bkh  = ((lane >> 3) & 1) * 8;                  // B: k half

    // elem offsets within a plane
    const int aoff0 = (wm * 32 + 0  + arow) * LDSK + akh;
    const int aoff1 = (wm * 32 + 16 + arow) * LDSK + akh;
    const int boff0 = (wn * 32 + 0  + brow) * LDSK + bkh;
    const int boff1 = (wn * 32 + 16 + brow) * LDSK + bkh;

    // cp.async loader: thread -> (plane, row), 4x16B per tile (64B contiguous)
    const int lplane = tid >> 7;      // 0:Ah 1:Al 2:Bh 3:Bl
    const int lrow   = tid & 127;
    const bf16* gbase = (lplane == 0) ? Ah : (lplane == 1) ? Al : (lplane == 2) ? Bh : Bl;
    const size_t grst = (size_t)((lplane < 2 ? bm : bn) + lrow) * K;
    const uint32_t srow = smbase + 2 * (lplane * PLE + lrow * LDSK);

    float acc[2][4][4];
#pragma unroll
    for (int i = 0; i < 2; i++)
#pragma unroll
        for (int j = 0; j < 4; j++)
#pragma unroll
            for (int r = 0; r < 4; r++) acc[i][j][r] = 0.0f;

    const int nt = K / BK;

#define LOAD_TILE(T, STG)                                      \
    {                                                          \
        const bf16* gp = gbase + grst + (T) * BK;              \
        const uint32_t sp = srow + (STG) * (BUFE * 2);         \
        cp16(sp,      gp);                                     \
        cp16(sp + 16, gp + 8);                                 \
        cp16(sp + 32, gp + 16);                                \
        cp16(sp + 48, gp + 24);                                \
    }

    LOAD_TILE(0, 0); cp_commit();
    LOAD_TILE(1, 1); cp_commit();

    int stg = 0;
    for (int t = 0; t < nt; t++) {
        if (t == nt - 1) cp_wait<0>(); else cp_wait<1>();
        __syncthreads();

        if (t + 2 < nt) {
            const int s2 = (stg + 2) % NSTG;
            LOAD_TILE(t + 2, s2);
            cp_commit();
        }

        const uint32_t sb = smbase + stg * (BUFE * 2);

#pragma unroll
        for (int ks = 0; ks < 2; ks++) {
            const int ko = ks * 16;
            uint32_t fAh[2][4], fAl[2][4], fBh[2][4], fBl[2][4];
            ldm4(fAh[0], sb + 2 * (aoff0 + ko));
            ldm4(fAh[1], sb + 2 * (aoff1 + ko));
            ldm4(fAl[0], sb + 2 * (PLE + aoff0 + ko));
            ldm4(fAl[1], sb + 2 * (PLE + aoff1 + ko));
            ldm4(fBh[0], sb + 2 * (2 * PLE + boff0 + ko));
            ldm4(fBh[1], sb + 2 * (2 * PLE + boff1 + ko));
            ldm4(fBl[0], sb + 2 * (3 * PLE + boff0 + ko));
            ldm4(fBl[1], sb + 2 * (3 * PLE + boff1 + ko));

#pragma unroll
            for (int mi = 0; mi < 2; mi++)
#pragma unroll
                for (int nj = 0; nj < 2; nj++) {
                    mma16816(acc[mi][2 * nj],     fAh[mi], &fBh[nj][0]);
                    mma16816(acc[mi][2 * nj + 1], fAh[mi], &fBh[nj][2]);
                    mma16816(acc[mi][2 * nj],     fAh[mi], &fBl[nj][0]);
                    mma16816(acc[mi][2 * nj + 1], fAh[mi], &fBl[nj][2]);
                    mma16816(acc[mi][2 * nj],     fAl[mi], &fBh[nj][0]);
                    mma16816(acc[mi][2 * nj + 1], fAl[mi], &fBh[nj][2]);
                }
        }
        stg = (stg + 1) % NSTG;
    }
#undef LOAD_TILE

    // ---- epilogue ----
#pragma unroll
    for (int mi = 0; mi < 2; mi++) {
#pragma unroll
        for (int ni = 0; ni < 4; ni++) {
            const int m = bm + wm * 32 + mi * 16 + g;
            const int n = bn + wn * 32 + ni * 8 + tg * 2;
            const float b0 = bias[n], b1 = bias[n + 1];
#pragma unroll
            for (int h = 0; h < 2; h++) {
                const int mm = m + h * 8;
                float v0 = acc[mi][ni][h * 2 + 0] + b0;
                float v1 = acc[mi][ni][h * 2 + 1] + b1;
                const size_t ix = (size_t)mm * N + n;
                if (EPI == EPI_RELU) {
                    v0 = fmaxf(v0, 0.0f); v1 = fmaxf(v1, 0.0f);
                    bf16 h0, l0, h1, l1;
                    split1(v0, h0, l0); split1(v1, h1, l1);
                    Chi[ix] = h0; Chi[ix + 1] = h1;
                    Clo[ix] = l0; Clo[ix + 1] = l1;
                } else {
                    if (EPI == EPI_RES) { v0 += res[ix]; v1 += res[ix + 1]; }
                    Cf[ix] = v0; Cf[ix + 1] = v1;
                }
            }
        }
    }
}

// ---------------- fp32 SGEMM for embed (K=80) + PE + split output ------------
__global__ __launch_bounds__(256) void embed_kernel(
    const float* __restrict__ A, const float* __restrict__ B,
    const float* __restrict__ bias,
    float* __restrict__ C, bf16* __restrict__ Chi, bf16* __restrict__ Clo,
    int M, int N, int K)
{
    __shared__ float As[16][132];
    __shared__ float Bs[16][132];

    const int tid = threadIdx.x;
    const int bm = blockIdx.y * 128;
    const int bn = blockIdx.x * 128;

    const int lr = tid >> 2;
    const int lc = (tid & 3) * 4;
    const int ty = tid >> 4;
    const int tx = tid & 15;

    float acc[8][8];
#pragma unroll
    for (int i = 0; i < 8; i++)
#pragma unroll
        for (int j = 0; j < 8; j++) acc[i][j] = 0.0f;

    for (int k0 = 0; k0 < K; k0 += 16) {
#pragma unroll
        for (int p = 0; p < 2; p++) {
            const int row = lr + p * 64;
            float4 a = *(const float4*)(A + (size_t)(bm + row) * K + k0 + lc);
            float4 b = *(const float4*)(B + (size_t)(bn + row) * K + k0 + lc);
            As[lc + 0][row] = a.x; As[lc + 1][row] = a.y;
            As[lc + 2][row] = a.z; As[lc + 3][row] = a.w;
            Bs[lc + 0][row] = b.x; Bs[lc + 1][row] = b.y;
            Bs[lc + 2][row] = b.z; Bs[lc + 3][row] = b.w;
        }
        __syncthreads();
#pragma unroll
        for (int kk = 0; kk < 16; kk++) {
            float a[8], b[8];
            *(float4*)(a)     = *(const float4*)&As[kk][ty * 8];
            *(float4*)(a + 4) = *(const float4*)&As[kk][ty * 8 + 4];
            *(float4*)(b)     = *(const float4*)&Bs[kk][tx * 8];
            *(float4*)(b + 4) = *(const float4*)&Bs[kk][tx * 8 + 4];
#pragma unroll
            for (int i = 0; i < 8; i++)
#pragma unroll
                for (int j = 0; j < 8; j++)
                    acc[i][j] += a[i] * b[j];
        }
        __syncthreads();
    }

    const int m0 = bm + ty * 8;
    const int n0 = bn + tx * 8;
    float bv[8];
#pragma unroll
    for (int j = 0; j < 8; j++) bv[j] = bias[n0 + j];

#pragma unroll
    for (int i = 0; i < 8; i++) {
        const int m = m0 + i;
        const int s = m & (SMAX - 1);
#pragma unroll
        for (int j = 0; j < 8; j++) {
            const int n = n0 + j;
            float v = acc[i][j] + bv[j];
            const int de = n & ~1;
            float ang = (float)s * expf((float)de * (-9.210340371976184f / 512.0f));
            v += (n & 1) ? cosf(ang) : sinf(ang);
            const size_t ix = (size_t)m * N + n;
            C[ix] = v;
            bf16 hh, ll; split1(v, hh, ll);
            Chi[ix] = hh; Clo[ix] = ll;
        }
    }
}

// ---------------- fused attention (fp32), epilogue writes ctx splits ---------
#define AQ   32
#define SPAD 516
#define KPAD 68
#define ATTN_SMEM ((AQ * SPAD + AQ * KPAD + 64 * KPAD) * 4)

__global__ __launch_bounds__(256) void attn_kernel(
    const float* __restrict__ qkv, const int* __restrict__ lens,
    bf16* __restrict__ ctx_hi, bf16* __restrict__ ctx_lo)
{
    extern __shared__ float smem[];
    float* sS = smem;
    float* sQ = sS + AQ * SPAD;
    float* sKV = sQ + AQ * KPAD;

    const int qt = blockIdx.x;
    const int hd = blockIdx.y;
    const int b  = blockIdx.z;
    const int t  = threadIdx.x;
    const int len = lens[b];

    const float* base = qkv + (size_t)b * SMAX * (3 * DMODEL);

    {
        const int r = t >> 4;
        const int c = (t & 15) * 4;
#pragma unroll
        for (int p = 0; p < 2; p++) {
            const int q = r + p * 16;
            float4 v = *(const float4*)(base + (size_t)(qt * AQ + q) * (3 * DMODEL) + hd * DH + c);
            *(float4*)(sQ + q * KPAD + c) = v;
        }
    }

    const int wq = (t >> 5) * 4;
    const int lk = t & 31;

    for (int kt = 0; kt < 8; kt++) {
        __syncthreads();
        {
            const int r = t >> 4;
            const int c = (t & 15) * 4;
#pragma unroll
            for (int p = 0; p < 4; p++) {
                const int key = r + p * 16;
                float4 v = *(const float4*)(base + (size_t)(kt * 64 + key) * (3 * DMODEL)
                                            + DMODEL + hd * DH + c);
                sKV[(c + 0) * KPAD + key] = v.x;
                sKV[(c + 1) * KPAD + key] = v.y;
                sKV[(c + 2) * KPAD + key] = v.z;
                sKV[(c + 3) * KPAD + key] = v.w;
            }
        }
        __syncthreads();

        float acc[4][2] = {{0.f,0.f},{0.f,0.f},{0.f,0.f},{0.f,0.f}};
#pragma unroll 8
        for (int d = 0; d < 64; d++) {
            const float k0v = sKV[d * KPAD + lk * 2];
            const float k1v = sKV[d * KPAD + lk * 2 + 1];
#pragma unroll
            for (int i = 0; i < 4; i++) {
                const float qv = sQ[(wq + i) * KPAD + d];
                acc[i][0] += qv * k0v;
                acc[i][1] += qv * k1v;
            }
        }
#pragma unroll
        for (int i = 0; i < 4; i++)
#pragma unroll
            for (int j = 0; j < 2; j++) {
                const int kk = kt * 64 + lk * 2 + j;
                sS[(wq + i) * SPAD + kk] = (kk < len) ? acc[i][j] * 0.125f : -1e9f;
            }
    }
    __syncthreads();

    {
        const int w = t >> 5, lane = t & 31;
        for (int qi = w * 4; qi < w * 4 + 4; qi++) {
            float* row = sS + qi * SPAD;
            float m = -1e30f;
            for (int k = lane; k < SMAX; k += 32) m = fmaxf(m, row[k]);
#pragma unroll
            for (int o = 16; o; o >>= 1) m = fmaxf(m, __shfl_xor_sync(0xffffffffu, m, o));
            float sum = 0.0f;
            for (int k = lane; k < SMAX; k += 32) {
                float e = expf(row[k] - m);
                row[k] = e;
                sum += e;
            }
#pragma unroll
            for (int o = 16; o; o >>= 1) sum += __shfl_xor_sync(0xffffffffu, sum, o);
            const float inv = 1.0f / sum;
            for (int k = lane; k < SMAX; k += 32) row[k] *= inv;
        }
    }

    float o[4][2] = {{0.f,0.f},{0.f,0.f},{0.f,0.f},{0.f,0.f}};
    const int dv = lk * 2;
    for (int kt = 0; kt < 8; kt++) {
        __syncthreads();
        {
            const int r = t >> 4;
            const int c = (t & 15) * 4;
#pragma unroll
            for (int p = 0; p < 4; p++) {
                const int key = r + p * 16;
                float4 v = *(const float4*)(base + (size_t)(kt * 64 + key) * (3 * DMODEL)
                                            + 2 * DMODEL + hd * DH + c);
                *(float4*)(sKV + key * KPAD + c) = v;
            }
        }
        __syncthreads();
#pragma unroll 8
        for (int k = 0; k < 64; k++) {
            const float v0 = sKV[k * KPAD + dv];
            const float v1 = sKV[k * KPAD + dv + 1];
#pragma unroll
            for (int i = 0; i < 4; i++) {
                const float p = sS[(wq + i) * SPAD + kt * 64 + k];
                o[i][0] += p * v0;
                o[i][1] += p * v1;
            }
        }
    }
#pragma unroll
    for (int i = 0; i < 4; i++) {
        const int q = qt * AQ + wq + i;
        const size_t ix = ((size_t)b * SMAX + q) * DMODEL + hd * DH + dv;
        bf16 h0, l0, h1, l1;
        split1(o[i][0], h0, l0);
        split1(o[i][1], h1, l1);
        ctx_hi[ix] = h0; ctx_hi[ix + 1] = h1;
        ctx_lo[ix] = l0; ctx_lo[ix + 1] = l1;
    }
}

// ---------------- LayerNorm (in place) + split output ------------------------
__global__ __launch_bounds__(128) void ln_kernel(
    float* __restrict__ h, const float* __restrict__ g, const float* __restrict__ bta,
    bf16* __restrict__ hhi, bf16* __restrict__ hlo)
{
    __shared__ float red[8];
    const int row = blockIdx.x;
    const int t = threadIdx.x;
    float* p = h + (size_t)row * DMODEL + t * 4;
    float4 v = *(float4*)p;
    float s  = v.x + v.y + v.z + v.w;
    float ss = v.x * v.x + v.y * v.y + v.z * v.z + v.w * v.w;
#pragma unroll
    for (int o = 16; o; o >>= 1) {
        s  += __shfl_xor_sync(0xffffffffu, s, o);
        ss += __shfl_xor_sync(0xffffffffu, ss, o);
    }
    const int w = t >> 5;
    if ((t & 31) == 0) { red[w] = s; red[4 + w] = ss; }
    __syncthreads();
    s  = red[0] + red[1] + red[2] + red[3];
    ss = red[4] + red[5] + red[6] + red[7];
    const float mean = s * (1.0f / DMODEL);
    const float var  = ss * (1.0f / DMODEL) - mean * mean;
    const float rstd = rsqrtf(var + 1e-5f);
    float4 gg = *(const float4*)(g + t * 4);
    float4 bb = *(const float4*)(bta + t * 4);
    v.x = (v.x - mean) * rstd * gg.x + bb.x;
    v.y = (v.y - mean) * rstd * gg.y + bb.y;
    v.z = (v.z - mean) * rstd * gg.z + bb.z;
    v.w = (v.w - mean) * rstd * gg.w + bb.w;
    *(float4*)p = v;
    split4(v, hhi + (size_t)row * DMODEL + t * 4, hlo + (size_t)row * DMODEL + t * 4);
}

// ---------------- two-phase masked mean pooling ------------------------------
__global__ __launch_bounds__(128) void pool_part_kernel(
    const float* __restrict__ h, const int* __restrict__ lens, float* __restrict__ part)
{
    const int b = blockIdx.x;
    const int ch = blockIdx.y;
    const int d = threadIdx.x * 4;
    const int len = lens[b];
    const int t0 = ch * 64;
    int nt = len - t0;
    if (nt > 64) nt = 64;
    float4 s = {0.f, 0.f, 0.f, 0.f};
    for (int t = 0; t < nt; t++) {
        float4 v = *(const float4*)(h + ((size_t)b * SMAX + t0 + t) * DMODEL + d);
        s.x += v.x; s.y += v.y; s.z += v.z; s.w += v.w;
    }
    *(float4*)(part + (size_t)(b * 8 + ch) * DMODEL + d) = s;
}

__global__ __launch_bounds__(DMODEL) void pool_final_kernel(
    const float* __restrict__ part, const int* __restrict__ lens,
    float* __restrict__ out, int out_size)
{
    const int b = blockIdx.x;
    const int d = threadIdx.x;
    float s = 0.0f;
#pragma unroll
    for (int c = 0; c < 8; c++) s += part[(size_t)(b * 8 + c) * DMODEL + d];
    out[b * DMODEL + d] = s / (float)lens[b];
    if (d == 0 && out_size >= BATCH * DMODEL + BATCH)
        out[BATCH * DMODEL + b] = (float)lens[b];
}

// ---------------- launch ------------------------------------------------------
extern "C" void kernel_launch(void* const* d_in, const int* in_sizes, int n_in,
                              void* d_out, int out_size)
{
    (void)in_sizes; (void)n_in;
    const float* x     = (const float*)d_in[0];
    const int*   lens  = (const int*)  d_in[1];
    const float* We    = (const float*)d_in[2];
    const float* be    = (const float*)d_in[3];
    const float* Wqkv  = (const float*)d_in[4];
    const float* bqkv  = (const float*)d_in[5];
    const float* Wo    = (const float*)d_in[6];
    const float* bo    = (const float*)d_in[7];
    const float* ln1g  = (const float*)d_in[8];
    const float* ln1b  = (const float*)d_in[9];
    const float* W1    = (const float*)d_in[10];
    const float* b1    = (const float*)d_in[11];
    const float* W2    = (const float*)d_in[12];
    const float* b2    = (const float*)d_in[13];
    const float* ln2g  = (const float*)d_in[14];
    const float* ln2b  = (const float*)d_in[15];
    float* out = (float*)d_out;

    void *ph, *pqkv, *ppool;
    void *phh, *phl, *pch, *pcl, *pfh, *pfl;
    void *pwqh, *pwql, *pwoh, *pwol, *pw1h, *pw1l, *pw2h, *pw2l;
    cudaGetSymbolAddress(&ph,    g_h);
    cudaGetSymbolAddress(&pqkv,  g_qkv);
    cudaGetSymbolAddress(&ppool, g_pool);
    cudaGetSymbolAddress(&phh,   g_h_hi);   cudaGetSymbolAddress(&phl, g_h_lo);
    cudaGetSymbolAddress(&pch,   g_ctx_hi); cudaGetSymbolAddress(&pcl, g_ctx_lo);
    cudaGetSymbolAddress(&pfh,   g_ff_hi);  cudaGetSymbolAddress(&pfl, g_ff_lo);
    cudaGetSymbolAddress(&pwqh,  g_wqkv_hi); cudaGetSymbolAddress(&pwql, g_wqkv_lo);
    cudaGetSymbolAddress(&pwoh,  g_wo_hi);   cudaGetSymbolAddress(&pwol, g_wo_lo);
    cudaGetSymbolAddress(&pw1h,  g_w1_hi);   cudaGetSymbolAddress(&pw1l, g_w1_lo);
    cudaGetSymbolAddress(&pw2h,  g_w2_hi);   cudaGetSymbolAddress(&pw2l, g_w2_lo);

    float* h    = (float*)ph;
    float* qkv  = (float*)pqkv;
    float* pool = (float*)ppool;
    bf16 *h_hi = (bf16*)phh, *h_lo = (bf16*)phl;
    bf16 *c_hi = (bf16*)pch, *c_lo = (bf16*)pcl;
    bf16 *f_hi = (bf16*)pfh, *f_lo = (bf16*)pfl;
    bf16 *wq_hi = (bf16*)pwqh, *wq_lo = (bf16*)pwql;
    bf16 *wo_hi = (bf16*)pwoh, *wo_lo = (bf16*)pwol;
    bf16 *w1_hi = (bf16*)pw1h, *w1_lo = (bf16*)pw1l;
    bf16 *w2_hi = (bf16*)pw2h, *w2_lo = (bf16*)pw2l;

    cudaFuncSetAttribute(attn_kernel,
                         cudaFuncAttributeMaxDynamicSharedMemorySize, ATTN_SMEM);
    cudaFuncSetAttribute(bgemm_kernel<EPI_NONE>,
                         cudaFuncAttributeMaxDynamicSharedMemorySize, GSMEM);
    cudaFuncSetAttribute(bgemm_kernel<EPI_RELU>,
                         cudaFuncAttributeMaxDynamicSharedMemorySize, GSMEM);
    cudaFuncSetAttribute(bgemm_kernel<EPI_RES>,
                         cudaFuncAttributeMaxDynamicSharedMemorySize, GSMEM);

    // ---- weight splits (once per launch) ----
    split_kernel<<<NLAYERS * 3 * DMODEL * DMODEL / 1024, 256>>>(Wqkv, wq_hi, wq_lo);
    split_kernel<<<NLAYERS * DMODEL * DMODEL / 1024, 256>>>(Wo, wo_hi, wo_lo);
    split_kernel<<<NLAYERS * DFF * DMODEL / 1024, 256>>>(W1, w1_hi, w1_lo);
    split_kernel<<<NLAYERS * DMODEL * DFF / 1024, 256>>>(W2, w2_hi, w2_lo);

    // ---- embedding + positional encoding ----
    embed_kernel<<<dim3(DMODEL / 128, NTOK / 128), 256>>>(
        x, We, be, h, h_hi, h_lo, NTOK, DMODEL, INSZ);

    for (int l = 0; l < NLAYERS; l++) {
        const bf16* wqh = wq_hi + (size_t)l * 3 * DMODEL * DMODEL;
        const bf16* wql = wq_lo + (size_t)l * 3 * DMODEL * DMODEL;
        const bf16* woh = wo_hi + (size_t)l * DMODEL * DMODEL;
        const bf16* wol = wo_lo + (size_t)l * DMODEL * DMODEL;
        const bf16* w1h = w1_hi + (size_t)l * DFF * DMODEL;
        const bf16* w1l = w1_lo + (size_t)l * DFF * DMODEL;
        const bf16* w2h = w2_hi + (size_t)l * DMODEL * DFF;
        const bf16* w2l = w2_lo + (size_t)l * DMODEL * DFF;
        const float* bq  = bqkv + (size_t)l * 3 * DMODEL;
        const float* bO  = bo   + (size_t)l * DMODEL;
        const float* bf1 = b1   + (size_t)l * DFF;
        const float* bf2 = b2   + (size_t)l * DMODEL;

        bgemm_kernel<EPI_NONE><<<dim3(3 * DMODEL / 128, NTOK / 128), 512, GSMEM>>>(
            h_hi, h_lo, wqh, wql, bq, nullptr, qkv, nullptr, nullptr,
            NTOK, 3 * DMODEL, DMODEL);

        attn_kernel<<<dim3(SMAX / AQ, NHEAD, BATCH), 256, ATTN_SMEM>>>(
            qkv, lens, c_hi, c_lo);

        bgemm_kernel<EPI_RES><<<dim3(DMODEL / 128, NTOK / 128), 512, GSMEM>>>(
            c_hi, c_lo, woh, wol, bO, h, h, nullptr, nullptr,
            NTOK, DMODEL, DMODEL);
        ln_kernel<<<NTOK, 128>>>(h, ln1g + l * DMODEL, ln1b + l * DMODEL, h_hi, h_lo);

        bgemm_kernel<EPI_RELU><<<dim3(DFF / 128, NTOK / 128), 512, GSMEM>>>(
            h_hi, h_lo, w1h, w1l, bf1, nullptr, nullptr, f_hi, f_lo,
            NTOK, DFF, DMODEL);
        bgemm_kernel<EPI_RES><<<dim3(DMODEL / 128, NTOK / 128), 512, GSMEM>>>(
            f_hi, f_lo, w2h, w2l, bf2, h, h, nullptr, nullptr,
            NTOK, DMODEL, DFF);
        ln_kernel<<<NTOK, 128>>>(h, ln2g + l * DMODEL, ln2b + l * DMODEL, h_hi, h_lo);
    }

    pool_part_kernel<<<dim3(BATCH, 8), 128>>>(h, lens, pool);
    pool_final_kernel<<<BATCH, DMODEL>>>(pool, lens, out, out_size);
}

// round 5
// speedup vs baseline: 1.0600x; 1.0600x over previous
#include <cuda_runtime.h>
#include <cuda_bf16.h>
#include <cstdint>

// ---------------- problem constants ----------------
#define NLAYERS 4
#define INSZ    80
#define DMODEL  512
#define NHEAD   8
#define DH      64
#define DFF     2048
#define BATCH   16
#define SMAX    512
#define NTOK    (BATCH * SMAX)   // 8192

typedef __nv_bfloat16 bf16;

// ---------------- scratch (device globals; no allocs allowed) ----------------
__device__ float g_h   [NTOK * DMODEL];
__device__ float g_qkv [NTOK * 3 * DMODEL];
__device__ float g_pool[BATCH * 8 * DMODEL];

__device__ bf16 g_h_hi [NTOK * DMODEL],  g_h_lo [NTOK * DMODEL];
__device__ bf16 g_ctx_hi[NTOK * DMODEL], g_ctx_lo[NTOK * DMODEL];
__device__ bf16 g_ff_hi[NTOK * DFF],     g_ff_lo[NTOK * DFF];

__device__ bf16 g_wqkv_hi[NLAYERS * 3 * DMODEL * DMODEL], g_wqkv_lo[NLAYERS * 3 * DMODEL * DMODEL];
__device__ bf16 g_wo_hi  [NLAYERS * DMODEL * DMODEL],     g_wo_lo  [NLAYERS * DMODEL * DMODEL];
__device__ bf16 g_w1_hi  [NLAYERS * DFF * DMODEL],        g_w1_lo  [NLAYERS * DFF * DMODEL];
__device__ bf16 g_w2_hi  [NLAYERS * DMODEL * DFF],        g_w2_lo  [NLAYERS * DMODEL * DFF];

enum { EPI_NONE = 0, EPI_RELU = 2, EPI_RES = 3 };

// ---------------- helpers -----------------------------------------------------
__device__ __forceinline__ void mma16816(float* d, const uint32_t* a, const uint32_t* b) {
    asm volatile(
        "mma.sync.aligned.m16n8k16.row.col.f32.bf16.bf16.f32 "
        "{%0,%1,%2,%3},{%4,%5,%6,%7},{%8,%9},{%0,%1,%2,%3};\n"
        : "+f"(d[0]), "+f"(d[1]), "+f"(d[2]), "+f"(d[3])
        : "r"(a[0]), "r"(a[1]), "r"(a[2]), "r"(a[3]), "r"(b[0]), "r"(b[1]));
}

__device__ __forceinline__ uint32_t ld32bf(const bf16* p) {
    return *reinterpret_cast<const uint32_t*>(p);
}

__device__ __forceinline__ void split1(float v, bf16& h, bf16& l) {
    h = __float2bfloat16(v);
    l = __float2bfloat16(v - __bfloat162float(h));
}

__device__ __forceinline__ void split4(float4 v, bf16* dh, bf16* dl) {
    union { bf16 b[4]; uint2 u; } H, L;
    split1(v.x, H.b[0], L.b[0]);
    split1(v.y, H.b[1], L.b[1]);
    split1(v.z, H.b[2], L.b[2]);
    split1(v.w, H.b[3], L.b[3]);
    *reinterpret_cast<uint2*>(dh) = H.u;
    *reinterpret_cast<uint2*>(dl) = L.u;
}

// ---------------- fp32 -> hi/lo split kernel ---------------------------------
__global__ __launch_bounds__(256) void split_kernel(
    const float* __restrict__ src, bf16* __restrict__ hi, bf16* __restrict__ lo)
{
    const int i = (blockIdx.x * 256 + threadIdx.x) * 4;
    float4 v = *(const float4*)(src + i);
    split4(v, hi + i, lo + i);
}

// =============================================================================
// bf16 split-precision tensor-core GEMM (pre-split operands), R2 structure:
//   C[M,N] = (Ah+Al)[M,K] * (Bh+Bl)[N,K]^T + bias (+epilogue)
//   acc += Ah*Bh + Ah*Bl + Al*Bh  (fp32 accum)
// 256 threads, 128x128x32 tile, warp tile 64x32, register double-buffer.
// =============================================================================
#define BK    32
#define LDSK  40                   // padded k-stride: fragment loads conflict-free
#define PLE   (128 * LDSK)         // elems per plane (10 KB)
#define BUFE  (4 * PLE)            // elems per buffer (40 KB)
#define GSMEM (2 * BUFE * 2)       // 80 KB

template <int EPI>
__global__ __launch_bounds__(256) void bgemm_kernel(
    const bf16* __restrict__ Ah, const bf16* __restrict__ Al,
    const bf16* __restrict__ Bh, const bf16* __restrict__ Bl,
    const float* __restrict__ bias, const float* __restrict__ res,
    float* __restrict__ Cf, bf16* __restrict__ Chi, bf16* __restrict__ Clo,
    int M, int N, int K)
{
    extern __shared__ bf16 sm[];

    const int tid = threadIdx.x;
    const int bm = blockIdx.y * 128;
    const int bn = blockIdx.x * 128;

    const int wid  = tid >> 5;
    const int wm   = wid & 1;       // 64-row half
    const int wn   = wid >> 1;      // 32-col quarter
    const int lane = tid & 31;
    const int g    = lane >> 2;
    const int tg   = lane & 3;

    // loader mapping: per plane, thread -> (row = tid>>1, 16-elem half = tid&1)
    const int lrow = tid >> 1;
    const int lcol = (tid & 1) * 16;
    const size_t gA = (size_t)(bm + lrow) * K + lcol;
    const size_t gB = (size_t)(bn + lrow) * K + lcol;
    const int soff = lrow * LDSK + lcol;

    float acc[4][4][4];
#pragma unroll
    for (int i = 0; i < 4; i++)
#pragma unroll
        for (int j = 0; j < 4; j++)
#pragma unroll
            for (int r = 0; r < 4; r++) acc[i][j][r] = 0.0f;

    const int nt = K / BK;

    // ---- prologue: load tile 0 directly to smem ----
    {
        *(uint4*)(sm + 0 * PLE + soff)     = *(const uint4*)(Ah + gA);
        *(uint4*)(sm + 0 * PLE + soff + 8) = *(const uint4*)(Ah + gA + 8);
        *(uint4*)(sm + 1 * PLE + soff)     = *(const uint4*)(Al + gA);
        *(uint4*)(sm + 1 * PLE + soff + 8) = *(const uint4*)(Al + gA + 8);
        *(uint4*)(sm + 2 * PLE + soff)     = *(const uint4*)(Bh + gB);
        *(uint4*)(sm + 2 * PLE + soff + 8) = *(const uint4*)(Bh + gB + 8);
        *(uint4*)(sm + 3 * PLE + soff)     = *(const uint4*)(Bl + gB);
        *(uint4*)(sm + 3 * PLE + soff + 8) = *(const uint4*)(Bl + gB + 8);
    }
    __syncthreads();

    for (int t = 0; t < nt; t++) {
        const int cur = (t & 1) * BUFE;
        const int nxt = ((t + 1) & 1) * BUFE;

        // prefetch next K-tile into registers
        uint4 pf[8];
        const bool have_next = (t + 1 < nt);
        if (have_next) {
            const int k0 = (t + 1) * BK;
            pf[0] = *(const uint4*)(Ah + gA + k0);
            pf[1] = *(const uint4*)(Ah + gA + k0 + 8);
            pf[2] = *(const uint4*)(Al + gA + k0);
            pf[3] = *(const uint4*)(Al + gA + k0 + 8);
            pf[4] = *(const uint4*)(Bh + gB + k0);
            pf[5] = *(const uint4*)(Bh + gB + k0 + 8);
            pf[6] = *(const uint4*)(Bl + gB + k0);
            pf[7] = *(const uint4*)(Bl + gB + k0 + 8);
        }

        const bf16* pAh = sm + cur;
        const bf16* pAl = sm + cur + PLE;
        const bf16* pBh = sm + cur + 2 * PLE;
        const bf16* pBl = sm + cur + 3 * PLE;

#pragma unroll
        for (int ks = 0; ks < 2; ks++) {
            const int kc = ks * 16 + 2 * tg;
            uint32_t af[4][4], bh[4][2], bl[4][2];
#pragma unroll
            for (int mi = 0; mi < 4; mi++) {
                const bf16* p = pAh + (wm * 64 + mi * 16 + g) * LDSK + kc;
                af[mi][0] = ld32bf(p);
                af[mi][1] = ld32bf(p + 8 * LDSK);
                af[mi][2] = ld32bf(p + 8);
                af[mi][3] = ld32bf(p + 8 * LDSK + 8);
            }
#pragma unroll
            for (int ni = 0; ni < 4; ni++) {
                const bf16* p = pBh + (wn * 32 + ni * 8 + g) * LDSK + kc;
                bh[ni][0] = ld32bf(p);
                bh[ni][1] = ld32bf(p + 8);
            }
#pragma unroll
            for (int mi = 0; mi < 4; mi++)
#pragma unroll
                for (int ni = 0; ni < 4; ni++)
                    mma16816(acc[mi][ni], af[mi], bh[ni]);

#pragma unroll
            for (int ni = 0; ni < 4; ni++) {
                const bf16* p = pBl + (wn * 32 + ni * 8 + g) * LDSK + kc;
                bl[ni][0] = ld32bf(p);
                bl[ni][1] = ld32bf(p + 8);
            }
#pragma unroll
            for (int mi = 0; mi < 4; mi++)
#pragma unroll
                for (int ni = 0; ni < 4; ni++)
                    mma16816(acc[mi][ni], af[mi], bl[ni]);

#pragma unroll
            for (int mi = 0; mi < 4; mi++) {
                const bf16* p = pAl + (wm * 64 + mi * 16 + g) * LDSK + kc;
                af[mi][0] = ld32bf(p);
                af[mi][1] = ld32bf(p + 8 * LDSK);
                af[mi][2] = ld32bf(p + 8);
                af[mi][3] = ld32bf(p + 8 * LDSK + 8);
            }
#pragma unroll
            for (int mi = 0; mi < 4; mi++)
#pragma unroll
                for (int ni = 0; ni < 4; ni++)
                    mma16816(acc[mi][ni], af[mi], bh[ni]);
        }

        if (have_next) {
            *(uint4*)(sm + nxt + 0 * PLE + soff)     = pf[0];
            *(uint4*)(sm + nxt + 0 * PLE + soff + 8) = pf[1];
            *(uint4*)(sm + nxt + 1 * PLE + soff)     = pf[2];
            *(uint4*)(sm + nxt + 1 * PLE + soff + 8) = pf[3];
            *(uint4*)(sm + nxt + 2 * PLE + soff)     = pf[4];
            *(uint4*)(sm + nxt + 2 * PLE + soff + 8) = pf[5];
            *(uint4*)(sm + nxt + 3 * PLE + soff)     = pf[6];
            *(uint4*)(sm + nxt + 3 * PLE + soff + 8) = pf[7];
        }
        __syncthreads();
    }

    // ---- epilogue ----
#pragma unroll
    for (int mi = 0; mi < 4; mi++) {
#pragma unroll
        for (int ni = 0; ni < 4; ni++) {
            const int m = bm + wm * 64 + mi * 16 + g;
            const int n = bn + wn * 32 + ni * 8 + tg * 2;
            const float b0 = bias[n], b1 = bias[n + 1];
#pragma unroll
            for (int h = 0; h < 2; h++) {
                const int mm = m + h * 8;
                float v0 = acc[mi][ni][h * 2 + 0] + b0;
                float v1 = acc[mi][ni][h * 2 + 1] + b1;
                const size_t ix = (size_t)mm * N + n;
                if (EPI == EPI_RELU) {
                    v0 = fmaxf(v0, 0.0f); v1 = fmaxf(v1, 0.0f);
                    bf16 h0, l0, h1, l1;
                    split1(v0, h0, l0); split1(v1, h1, l1);
                    Chi[ix] = h0; Chi[ix + 1] = h1;
                    Clo[ix] = l0; Clo[ix + 1] = l1;
                } else {
                    if (EPI == EPI_RES) { v0 += res[ix]; v1 += res[ix + 1]; }
                    Cf[ix] = v0; Cf[ix + 1] = v1;
                }
            }
        }
    }
}

// ---------------- fp32 SGEMM for embed (K=80) + PE + split output ------------
__global__ __launch_bounds__(256) void embed_kernel(
    const float* __restrict__ A, const float* __restrict__ B,
    const float* __restrict__ bias,
    float* __restrict__ C, bf16* __restrict__ Chi, bf16* __restrict__ Clo,
    int M, int N, int K)
{
    __shared__ float As[16][132];
    __shared__ float Bs[16][132];

    const int tid = threadIdx.x;
    const int bm = blockIdx.y * 128;
    const int bn = blockIdx.x * 128;

    const int lr = tid >> 2;
    const int lc = (tid & 3) * 4;
    const int ty = tid >> 4;
    const int tx = tid & 15;

    float acc[8][8];
#pragma unroll
    for (int i = 0; i < 8; i++)
#pragma unroll
        for (int j = 0; j < 8; j++) acc[i][j] = 0.0f;

    for (int k0 = 0; k0 < K; k0 += 16) {
#pragma unroll
        for (int p = 0; p < 2; p++) {
            const int row = lr + p * 64;
            float4 a = *(const float4*)(A + (size_t)(bm + row) * K + k0 + lc);
            float4 b = *(const float4*)(B + (size_t)(bn + row) * K + k0 + lc);
            As[lc + 0][row] = a.x; As[lc + 1][row] = a.y;
            As[lc + 2][row] = a.z; As[lc + 3][row] = a.w;
            Bs[lc + 0][row] = b.x; Bs[lc + 1][row] = b.y;
            Bs[lc + 2][row] = b.z; Bs[lc + 3][row] = b.w;
        }
        __syncthreads();
#pragma unroll
        for (int kk = 0; kk < 16; kk++) {
            float a[8], b[8];
            *(float4*)(a)     = *(const float4*)&As[kk][ty * 8];
            *(float4*)(a + 4) = *(const float4*)&As[kk][ty * 8 + 4];
            *(float4*)(b)     = *(const float4*)&Bs[kk][tx * 8];
            *(float4*)(b + 4) = *(const float4*)&Bs[kk][tx * 8 + 4];
#pragma unroll
            for (int i = 0; i < 8; i++)
#pragma unroll
                for (int j = 0; j < 8; j++)
                    acc[i][j] += a[i] * b[j];
        }
        __syncthreads();
    }

    const int m0 = bm + ty * 8;
    const int n0 = bn + tx * 8;
    float bv[8];
#pragma unroll
    for (int j = 0; j < 8; j++) bv[j] = bias[n0 + j];

#pragma unroll
    for (int i = 0; i < 8; i++) {
        const int m = m0 + i;
        const int s = m & (SMAX - 1);
#pragma unroll
        for (int j = 0; j < 8; j++) {
            const int n = n0 + j;
            float v = acc[i][j] + bv[j];
            const int de = n & ~1;
            float ang = (float)s * expf((float)de * (-9.210340371976184f / 512.0f));
            v += (n & 1) ? cosf(ang) : sinf(ang);
            const size_t ix = (size_t)m * N + n;
            C[ix] = v;
            bf16 hh, ll; split1(v, hh, ll);
            Chi[ix] = hh; Clo[ix] = ll;
        }
    }
}

// ---------------- fused attention (fp32), epilogue writes ctx splits ---------
#define AQ   32
#define SPAD 516
#define KPAD 68
#define ATTN_SMEM ((AQ * SPAD + AQ * KPAD + 64 * KPAD) * 4)

__global__ __launch_bounds__(256) void attn_kernel(
    const float* __restrict__ qkv, const int* __restrict__ lens,
    bf16* __restrict__ ctx_hi, bf16* __restrict__ ctx_lo)
{
    extern __shared__ float smem[];
    float* sS = smem;
    float* sQ = sS + AQ * SPAD;
    float* sKV = sQ + AQ * KPAD;

    const int qt = blockIdx.x;
    const int hd = blockIdx.y;
    const int b  = blockIdx.z;
    const int t  = threadIdx.x;
    const int len = lens[b];

    const float* base = qkv + (size_t)b * SMAX * (3 * DMODEL);

    {
        const int r = t >> 4;
        const int c = (t & 15) * 4;
#pragma unroll
        for (int p = 0; p < 2; p++) {
            const int q = r + p * 16;
            float4 v = *(const float4*)(base + (size_t)(qt * AQ + q) * (3 * DMODEL) + hd * DH + c);
            *(float4*)(sQ + q * KPAD + c) = v;
        }
    }

    const int wq = (t >> 5) * 4;
    const int lk = t & 31;

    for (int kt = 0; kt < 8; kt++) {
        __syncthreads();
        {
            const int r = t >> 4;
            const int c = (t & 15) * 4;
#pragma unroll
            for (int p = 0; p < 4; p++) {
                const int key = r + p * 16;
                float4 v = *(const float4*)(base + (size_t)(kt * 64 + key) * (3 * DMODEL)
                                            + DMODEL + hd * DH + c);
                sKV[(c + 0) * KPAD + key] = v.x;
                sKV[(c + 1) * KPAD + key] = v.y;
                sKV[(c + 2) * KPAD + key] = v.z;
                sKV[(c + 3) * KPAD + key] = v.w;
            }
        }
        __syncthreads();

        float acc[4][2] = {{0.f,0.f},{0.f,0.f},{0.f,0.f},{0.f,0.f}};
#pragma unroll 8
        for (int d = 0; d < 64; d++) {
            const float k0v = sKV[d * KPAD + lk * 2];
            const float k1v = sKV[d * KPAD + lk * 2 + 1];
#pragma unroll
            for (int i = 0; i < 4; i++) {
                const float qv = sQ[(wq + i) * KPAD + d];
                acc[i][0] += qv * k0v;
                acc[i][1] += qv * k1v;
            }
        }
#pragma unroll
        for (int i = 0; i < 4; i++)
#pragma unroll
            for (int j = 0; j < 2; j++) {
                const int kk = kt * 64 + lk * 2 + j;
                sS[(wq + i) * SPAD + kk] = (kk < len) ? acc[i][j] * 0.125f : -1e9f;
            }
    }
    __syncthreads();

    {
        const int w = t >> 5, lane = t & 31;
        for (int qi = w * 4; qi < w * 4 + 4; qi++) {
            float* row = sS + qi * SPAD;
            float m = -1e30f;
            for (int k = lane; k < SMAX; k += 32) m = fmaxf(m, row[k]);
#pragma unroll
            for (int o = 16; o; o >>= 1) m = fmaxf(m, __shfl_xor_sync(0xffffffffu, m, o));
            float sum = 0.0f;
            for (int k = lane; k < SMAX; k += 32) {
                float e = expf(row[k] - m);
                row[k] = e;
                sum += e;
            }
#pragma unroll
            for (int o = 16; o; o >>= 1) sum += __shfl_xor_sync(0xffffffffu, sum, o);
            const float inv = 1.0f / sum;
            for (int k = lane; k < SMAX; k += 32) row[k] *= inv;
        }
    }

    float o[4][2] = {{0.f,0.f},{0.f,0.f},{0.f,0.f},{0.f,0.f}};
    const int dv = lk * 2;
    for (int kt = 0; kt < 8; kt++) {
        __syncthreads();
        {
            const int r = t >> 4;
            const int c = (t & 15) * 4;
#pragma unroll
            for (int p = 0; p < 4; p++) {
                const int key = r + p * 16;
                float4 v = *(const float4*)(base + (size_t)(kt * 64 + key) * (3 * DMODEL)
                                            + 2 * DMODEL + hd * DH + c);
                *(float4*)(sKV + key * KPAD + c) = v;
            }
        }
        __syncthreads();
#pragma unroll 8
        for (int k = 0; k < 64; k++) {
            const float v0 = sKV[k * KPAD + dv];
            const float v1 = sKV[k * KPAD + dv + 1];
#pragma unroll
            for (int i = 0; i < 4; i++) {
                const float p = sS[(wq + i) * SPAD + kt * 64 + k];
                o[i][0] += p * v0;
                o[i][1] += p * v1;
            }
        }
    }
#pragma unroll
    for (int i = 0; i < 4; i++) {
        const int q = qt * AQ + wq + i;
        const size_t ix = ((size_t)b * SMAX + q) * DMODEL + hd * DH + dv;
        bf16 h0, l0, h1, l1;
        split1(o[i][0], h0, l0);
        split1(o[i][1], h1, l1);
        ctx_hi[ix] = h0; ctx_hi[ix + 1] = h1;
        ctx_lo[ix] = l0; ctx_lo[ix + 1] = l1;
    }
}

// ---------------- LayerNorm (in place) + split output ------------------------
__global__ __launch_bounds__(128) void ln_kernel(
    float* __restrict__ h, const float* __restrict__ g, const float* __restrict__ bta,
    bf16* __restrict__ hhi, bf16* __restrict__ hlo)
{
    __shared__ float red[8];
    const int row = blockIdx.x;
    const int t = threadIdx.x;
    float* p = h + (size_t)row * DMODEL + t * 4;
    float4 v = *(float4*)p;
    float s  = v.x + v.y + v.z + v.w;
    float ss = v.x * v.x + v.y * v.y + v.z * v.z + v.w * v.w;
#pragma unroll
    for (int o = 16; o; o >>= 1) {
        s  += __shfl_xor_sync(0xffffffffu, s, o);
        ss += __shfl_xor_sync(0xffffffffu, ss, o);
    }
    const int w = t >> 5;
    if ((t & 31) == 0) { red[w] = s; red[4 + w] = ss; }
    __syncthreads();
    s  = red[0] + red[1] + red[2] + red[3];
    ss = red[4] + red[5] + red[6] + red[7];
    const float mean = s * (1.0f / DMODEL);
    const float var  = ss * (1.0f / DMODEL) - mean * mean;
    const float rstd = rsqrtf(var + 1e-5f);
    float4 gg = *(const float4*)(g + t * 4);
    float4 bb = *(const float4*)(bta + t * 4);
    v.x = (v.x - mean) * rstd * gg.x + bb.x;
    v.y = (v.y - mean) * rstd * gg.y + bb.y;
    v.z = (v.z - mean) * rstd * gg.z + bb.z;
    v.w = (v.w - mean) * rstd * gg.w + bb.w;
    *(float4*)p = v;
    split4(v, hhi + (size_t)row * DMODEL + t * 4, hlo + (size_t)row * DMODEL + t * 4);
}

// ---------------- two-phase masked mean pooling ------------------------------
__global__ __launch_bounds__(128) void pool_part_kernel(
    const float* __restrict__ h, const int* __restrict__ lens, float* __restrict__ part)
{
    const int b = blockIdx.x;
    const int ch = blockIdx.y;
    const int d = threadIdx.x * 4;
    const int len = lens[b];
    const int t0 = ch * 64;
    int nt = len - t0;
    if (nt > 64) nt = 64;
    float4 s = {0.f, 0.f, 0.f, 0.f};
    for (int t = 0; t < nt; t++) {
        float4 v = *(const float4*)(h + ((size_t)b * SMAX + t0 + t) * DMODEL + d);
        s.x += v.x; s.y += v.y; s.z += v.z; s.w += v.w;
    }
    *(float4*)(part + (size_t)(b * 8 + ch) * DMODEL + d) = s;
}

__global__ __launch_bounds__(DMODEL) void pool_final_kernel(
    const float* __restrict__ part, const int* __restrict__ lens,
    float* __restrict__ out, int out_size)
{
    const int b = blockIdx.x;
    const int d = threadIdx.x;
    float s = 0.0f;
#pragma unroll
    for (int c = 0; c < 8; c++) s += part[(size_t)(b * 8 + c) * DMODEL + d];
    out[b * DMODEL + d] = s / (float)lens[b];
    if (d == 0 && out_size >= BATCH * DMODEL + BATCH)
        out[BATCH * DMODEL + b] = (float)lens[b];
}

// ---------------- launch ------------------------------------------------------
extern "C" void kernel_launch(void* const* d_in, const int* in_sizes, int n_in,
                              void* d_out, int out_size)
{
    (void)in_sizes; (void)n_in;
    const float* x     = (const float*)d_in[0];
    const int*   lens  = (const int*)  d_in[1];
    const float* We    = (const float*)d_in[2];
    const float* be    = (const float*)d_in[3];
    const float* Wqkv  = (const float*)d_in[4];
    const float* bqkv  = (const float*)d_in[5];
    const float* Wo    = (const float*)d_in[6];
    const float* bo    = (const float*)d_in[7];
    const float* ln1g  = (const float*)d_in[8];
    const float* ln1b  = (const float*)d_in[9];
    const float* W1    = (const float*)d_in[10];
    const float* b1    = (const float*)d_in[11];
    const float* W2    = (const float*)d_in[12];
    const float* b2    = (const float*)d_in[13];
    const float* ln2g  = (const float*)d_in[14];
    const float* ln2b  = (const float*)d_in[15];
    float* out = (float*)d_out;

    void *ph, *pqkv, *ppool;
    void *phh, *phl, *pch, *pcl, *pfh, *pfl;
    void *pwqh, *pwql, *pwoh, *pwol, *pw1h, *pw1l, *pw2h, *pw2l;
    cudaGetSymbolAddress(&ph,    g_h);
    cudaGetSymbolAddress(&pqkv,  g_qkv);
    cudaGetSymbolAddress(&ppool, g_pool);
    cudaGetSymbolAddress(&phh,   g_h_hi);   cudaGetSymbolAddress(&phl, g_h_lo);
    cudaGetSymbolAddress(&pch,   g_ctx_hi); cudaGetSymbolAddress(&pcl, g_ctx_lo);
    cudaGetSymbolAddress(&pfh,   g_ff_hi);  cudaGetSymbolAddress(&pfl, g_ff_lo);
    cudaGetSymbolAddress(&pwqh,  g_wqkv_hi); cudaGetSymbolAddress(&pwql, g_wqkv_lo);
    cudaGetSymbolAddress(&pwoh,  g_wo_hi);   cudaGetSymbolAddress(&pwol, g_wo_lo);
    cudaGetSymbolAddress(&pw1h,  g_w1_hi);   cudaGetSymbolAddress(&pw1l, g_w1_lo);
    cudaGetSymbolAddress(&pw2h,  g_w2_hi);   cudaGetSymbolAddress(&pw2l, g_w2_lo);

    float* h    = (float*)ph;
    float* qkv  = (float*)pqkv;
    float* pool = (float*)ppool;
    bf16 *h_hi = (bf16*)phh, *h_lo = (bf16*)phl;
    bf16 *c_hi = (bf16*)pch, *c_lo = (bf16*)pcl;
    bf16 *f_hi = (bf16*)pfh, *f_lo = (bf16*)pfl;
    bf16 *wq_hi = (bf16*)pwqh, *wq_lo = (bf16*)pwql;
    bf16 *wo_hi = (bf16*)pwoh, *wo_lo = (bf16*)pwol;
    bf16 *w1_hi = (bf16*)pw1h, *w1_lo = (bf16*)pw1l;
    bf16 *w2_hi = (bf16*)pw2h, *w2_lo = (bf16*)pw2l;

    cudaFuncSetAttribute(attn_kernel,
                         cudaFuncAttributeMaxDynamicSharedMemorySize, ATTN_SMEM);
    cudaFuncSetAttribute(bgemm_kernel<EPI_NONE>,
                         cudaFuncAttributeMaxDynamicSharedMemorySize, GSMEM);
    cudaFuncSetAttribute(bgemm_kernel<EPI_RELU>,
                         cudaFuncAttributeMaxDynamicSharedMemorySize, GSMEM);
    cudaFuncSetAttribute(bgemm_kernel<EPI_RES>,
                         cudaFuncAttributeMaxDynamicSharedMemorySize, GSMEM);

    // ---- weight splits (once per launch) ----
    split_kernel<<<NLAYERS * 3 * DMODEL * DMODEL / 1024, 256>>>(Wqkv, wq_hi, wq_lo);
    split_kernel<<<NLAYERS * DMODEL * DMODEL / 1024, 256>>>(Wo, wo_hi, wo_lo);
    split_kernel<<<NLAYERS * DFF * DMODEL / 1024, 256>>>(W1, w1_hi, w1_lo);
    split_kernel<<<NLAYERS * DMODEL * DFF / 1024, 256>>>(W2, w2_hi, w2_lo);

    // ---- embedding + positional encoding ----
    embed_kernel<<<dim3(DMODEL / 128, NTOK / 128), 256>>>(
        x, We, be, h, h_hi, h_lo, NTOK, DMODEL, INSZ);

    for (int l = 0; l < NLAYERS; l++) {
        const bf16* wqh = wq_hi + (size_t)l * 3 * DMODEL * DMODEL;
        const bf16* wql = wq_lo + (size_t)l * 3 * DMODEL * DMODEL;
        const bf16* woh = wo_hi + (size_t)l * DMODEL * DMODEL;
        const bf16* wol = wo_lo + (size_t)l * DMODEL * DMODEL;
        const bf16* w1h = w1_hi + (size_t)l * DFF * DMODEL;
        const bf16* w1l = w1_lo + (size_t)l * DFF * DMODEL;
        const bf16* w2h = w2_hi + (size_t)l * DMODEL * DFF;
        const bf16* w2l = w2_lo + (size_t)l * DMODEL * DFF;
        const float* bq  = bqkv + (size_t)l * 3 * DMODEL;
        const float* bO  = bo   + (size_t)l * DMODEL;
        const float* bf1 = b1   + (size_t)l * DFF;
        const float* bf2 = b2   + (size_t)l * DMODEL;

        bgemm_kernel<EPI_NONE><<<dim3(3 * DMODEL / 128, NTOK / 128), 256, GSMEM>>>(
            h_hi, h_lo, wqh, wql, bq, nullptr, qkv, nullptr, nullptr,
            NTOK, 3 * DMODEL, DMODEL);

        attn_kernel<<<dim3(SMAX / AQ, NHEAD, BATCH), 256, ATTN_SMEM>>>(
            qkv, lens, c_hi, c_lo);

        bgemm_kernel<EPI_RES><<<dim3(DMODEL / 128, NTOK / 128), 256, GSMEM>>>(
            c_hi, c_lo, woh, wol, bO, h, h, nullptr, nullptr,
            NTOK, DMODEL, DMODEL);
        ln_kernel<<<NTOK, 128>>>(h, ln1g + l * DMODEL, ln1b + l * DMODEL, h_hi, h_lo);

        bgemm_kernel<EPI_RELU><<<dim3(DFF / 128, NTOK / 128), 256, GSMEM>>>(
            h_hi, h_lo, w1h, w1l, bf1, nullptr, nullptr, f_hi, f_lo,
            NTOK, DFF, DMODEL);
        bgemm_kernel<EPI_RES><<<dim3(DMODEL / 128, NTOK / 128), 256, GSMEM>>>(
            f_hi, f_lo, w2h, w2l, bf2, h, h, nullptr, nullptr,
            NTOK, DMODEL, DFF);
        ln_kernel<<<NTOK, 128>>>(h, ln2g + l * DMODEL, ln2b + l * DMODEL, h_hi, h_lo);
    }

    pool_part_kernel<<<dim3(BATCH, 8), 128>>>(h, lens, pool);
    pool_final_kernel<<<BATCH, DMODEL>>>(pool, lens, out, out_size);
}

// round 6
// speedup vs baseline: 1.5817x; 1.4921x over previous
#include <cuda_runtime.h>
#include <cuda_bf16.h>
#include <cstdint>

// ---------------- problem constants ----------------
#define NLAYERS 4
#define INSZ    80
#define DMODEL  512
#define NHEAD   8
#define DH      64
#define DFF     2048
#define BATCH   16
#define SMAX    512
#define NTOK    (BATCH * SMAX)   // 8192

typedef __nv_bfloat16 bf16;

// ---------------- scratch (device globals; no allocs allowed) ----------------
__device__ float g_h  [NTOK * DMODEL];       // hidden state
__device__ float g_qkv[NTOK * 3 * DMODEL];   // qkv projections
__device__ float g_ctx[NTOK * DMODEL];       // attention context
__device__ float g_ff [NTOK * DFF];          // ff intermediate
__device__ float g_pool[BATCH * 8 * DMODEL]; // pooling partials

enum { EPI_NONE = 0, EPI_PE = 1, EPI_RELU = 2, EPI_RES = 3 };

// ---------------- helpers -----------------------------------------------------
__device__ __forceinline__ void mma16816(float* d, const uint32_t* a, const uint32_t* b) {
    asm volatile(
        "mma.sync.aligned.m16n8k16.row.col.f32.bf16.bf16.f32 "
        "{%0,%1,%2,%3},{%4,%5,%6,%7},{%8,%9},{%0,%1,%2,%3};\n"
        : "+f"(d[0]), "+f"(d[1]), "+f"(d[2]), "+f"(d[3])
        : "r"(a[0]), "r"(a[1]), "r"(a[2]), "r"(a[3]), "r"(b[0]), "r"(b[1]));
}

__device__ __forceinline__ uint32_t ld32(const bf16* p) {
    return *reinterpret_cast<const uint32_t*>(p);
}

__device__ __forceinline__ void split1(float v, bf16& h, bf16& l) {
    h = __float2bfloat16(v);
    l = __float2bfloat16(v - __bfloat162float(h));
}

__device__ __forceinline__ void cvt_store4(bf16* dh, bf16* dl, float4 v) {
    union { bf16 b[4]; uint2 u; } H, L;
    split1(v.x, H.b[0], L.b[0]);
    split1(v.y, H.b[1], L.b[1]);
    split1(v.z, H.b[2], L.b[2]);
    split1(v.w, H.b[3], L.b[3]);
    *reinterpret_cast<uint2*>(dh) = H.u;
    *reinterpret_cast<uint2*>(dl) = L.u;
}

__device__ __forceinline__ void packsplit2(float x, float y, uint32_t& hi, uint32_t& lo) {
    bf16 hx, lx, hy, ly;
    split1(x, hx, lx);
    split1(y, hy, ly);
    union { bf16 b[2]; uint32_t u; } H, L;
    H.b[0] = hx; H.b[1] = hy;
    L.b[0] = lx; L.b[1] = ly;
    hi = H.u; lo = L.u;
}

// =============================================================================
// bf16 split-precision tensor-core GEMM (EXACT R2 version — proven fastest):
//   C[M,N] = A[M,K] * B[N,K]^T + bias (+epilogue), fp32 in/out,
//   in-kernel hi/lo split, acc += Ah*Bh + Ah*Bl + Al*Bh.
// =============================================================================
#define BK    32
#define LDS40 40
#define PLANE (128 * LDS40)
#define GSMEM (4 * 2 * PLANE * 2)   // 81920 B

template <int EPI>
__global__ __launch_bounds__(256) void bgemm_kernel(
    const float* __restrict__ A, const float* __restrict__ B,
    const float* __restrict__ bias, const float* __restrict__ res,
    float* __restrict__ C, int M, int N, int K)
{
    extern __shared__ bf16 sm[];
    bf16* sAh = sm;
    bf16* sAl = sm + 2 * PLANE;
    bf16* sBh = sm + 4 * PLANE;
    bf16* sBl = sm + 6 * PLANE;

    const int tid = threadIdx.x;
    const int bm = blockIdx.y * 128;
    const int bn = blockIdx.x * 128;

    const int wid  = tid >> 5;
    const int wm   = wid & 1;
    const int wn   = wid >> 1;
    const int lane = tid & 31;
    const int g    = lane >> 2;
    const int tg   = lane & 3;

    float acc[4][4][4];
#pragma unroll
    for (int i = 0; i < 4; i++)
#pragma unroll
        for (int j = 0; j < 4; j++)
#pragma unroll
            for (int r = 0; r < 4; r++) acc[i][j][r] = 0.0f;

    const int ntile = K / BK;

    {
#pragma unroll
        for (int p = 0; p < 4; p++) {
            const int idx = tid + p * 256;
            const int row = idx >> 3;
            const int c4  = (idx & 7) * 4;
            float4 va = *(const float4*)(A + (size_t)(bm + row) * K + c4);
            float4 vb = *(const float4*)(B + (size_t)(bn + row) * K + c4);
            cvt_store4(sAh + row * LDS40 + c4, sAl + row * LDS40 + c4, va);
            cvt_store4(sBh + row * LDS40 + c4, sBl + row * LDS40 + c4, vb);
        }
    }
    __syncthreads();

    for (int t = 0; t < ntile; t++) {
        const int cur = (t & 1) * PLANE;
        const int nxt = ((t + 1) & 1) * PLANE;

        float4 ra[4], rb[4];
        const bool have_next = (t + 1 < ntile);
        if (have_next) {
            const int k0 = (t + 1) * BK;
#pragma unroll
            for (int p = 0; p < 4; p++) {
                const int idx = tid + p * 256;
                const int row = idx >> 3;
                const int c4  = (idx & 7) * 4;
                ra[p] = *(const float4*)(A + (size_t)(bm + row) * K + k0 + c4);
                rb[p] = *(const float4*)(B + (size_t)(bn + row) * K + k0 + c4);
            }
        }

#pragma unroll
        for (int ks = 0; ks < 2; ks++) {
            const int kc = ks * 16 + 2 * tg;
            uint32_t ah[4][4], al[4][4], bh[4][2], bl[4][2];
#pragma unroll
            for (int mi = 0; mi < 4; mi++) {
                const int r = wm * 64 + mi * 16 + g;
                const bf16* pH = sAh + cur + r * LDS40 + kc;
                const bf16* pL = sAl + cur + r * LDS40 + kc;
                ah[mi][0] = ld32(pH);
                ah[mi][1] = ld32(pH + 8 * LDS40);
                ah[mi][2] = ld32(pH + 8);
                ah[mi][3] = ld32(pH + 8 * LDS40 + 8);
                al[mi][0] = ld32(pL);
                al[mi][1] = ld32(pL + 8 * LDS40);
                al[mi][2] = ld32(pL + 8);
                al[mi][3] = ld32(pL + 8 * LDS40 + 8);
            }
#pragma unroll
            for (int ni = 0; ni < 4; ni++) {
                const int r = wn * 32 + ni * 8 + g;
                const bf16* pH = sBh + cur + r * LDS40 + kc;
                const bf16* pL = sBl + cur + r * LDS40 + kc;
                bh[ni][0] = ld32(pH);
                bh[ni][1] = ld32(pH + 8);
                bl[ni][0] = ld32(pL);
                bl[ni][1] = ld32(pL + 8);
            }
#pragma unroll
            for (int mi = 0; mi < 4; mi++)
#pragma unroll
                for (int ni = 0; ni < 4; ni++) {
                    mma16816(acc[mi][ni], ah[mi], bh[ni]);
                    mma16816(acc[mi][ni], ah[mi], bl[ni]);
                    mma16816(acc[mi][ni], al[mi], bh[ni]);
                }
        }

        if (have_next) {
#pragma unroll
            for (int p = 0; p < 4; p++) {
                const int idx = tid + p * 256;
                const int row = idx >> 3;
                const int c4  = (idx & 7) * 4;
                cvt_store4(sAh + nxt + row * LDS40 + c4, sAl + nxt + row * LDS40 + c4, ra[p]);
                cvt_store4(sBh + nxt + row * LDS40 + c4, sBl + nxt + row * LDS40 + c4, rb[p]);
            }
        }
        __syncthreads();
    }

#pragma unroll
    for (int mi = 0; mi < 4; mi++) {
#pragma unroll
        for (int ni = 0; ni < 4; ni++) {
            const int m = bm + wm * 64 + mi * 16 + g;
            const int n = bn + wn * 32 + ni * 8 + tg * 2;
            const float b0 = bias[n], b1 = bias[n + 1];
#pragma unroll
            for (int h = 0; h < 2; h++) {
                const int mm = m + h * 8;
                float v0 = acc[mi][ni][h * 2 + 0] + b0;
                float v1 = acc[mi][ni][h * 2 + 1] + b1;
                if (EPI == EPI_RELU) { v0 = fmaxf(v0, 0.0f); v1 = fmaxf(v1, 0.0f); }
                if (EPI == EPI_RES) {
                    const float* rp = res + (size_t)mm * N + n;
                    v0 += rp[0]; v1 += rp[1];
                }
                float* cp = C + (size_t)mm * N + n;
                cp[0] = v0; cp[1] = v1;
            }
        }
    }
}

// ---------------- fp32 SGEMM (embed, K=80) — EXACT R2 version ----------------
template <int EPI>
__global__ __launch_bounds__(256) void sgemm_kernel(
    const float* __restrict__ A, const float* __restrict__ B,
    const float* __restrict__ bias, const float* __restrict__ res,
    float* __restrict__ C, int M, int N, int K)
{
    __shared__ float As[16][132];
    __shared__ float Bs[16][132];

    const int tid = threadIdx.x;
    const int bm = blockIdx.y * 128;
    const int bn = blockIdx.x * 128;

    const int lr = tid >> 2;
    const int lc = (tid & 3) * 4;
    const int ty = tid >> 4;
    const int tx = tid & 15;

    float acc[8][8];
#pragma unroll
    for (int i = 0; i < 8; i++)
#pragma unroll
        for (int j = 0; j < 8; j++) acc[i][j] = 0.0f;

    for (int k0 = 0; k0 < K; k0 += 16) {
#pragma unroll
        for (int p = 0; p < 2; p++) {
            const int row = lr + p * 64;
            float4 a = *(const float4*)(A + (size_t)(bm + row) * K + k0 + lc);
            float4 b = *(const float4*)(B + (size_t)(bn + row) * K + k0 + lc);
            As[lc + 0][row] = a.x; As[lc + 1][row] = a.y;
            As[lc + 2][row] = a.z; As[lc + 3][row] = a.w;
            Bs[lc + 0][row] = b.x; Bs[lc + 1][row] = b.y;
            Bs[lc + 2][row] = b.z; Bs[lc + 3][row] = b.w;
        }
        __syncthreads();
#pragma unroll
        for (int kk = 0; kk < 16; kk++) {
            float a[8], b[8];
            *(float4*)(a)     = *(const float4*)&As[kk][ty * 8];
            *(float4*)(a + 4) = *(const float4*)&As[kk][ty * 8 + 4];
            *(float4*)(b)     = *(const float4*)&Bs[kk][tx * 8];
            *(float4*)(b + 4) = *(const float4*)&Bs[kk][tx * 8 + 4];
#pragma unroll
            for (int i = 0; i < 8; i++)
#pragma unroll
                for (int j = 0; j < 8; j++)
                    acc[i][j] += a[i] * b[j];
        }
        __syncthreads();
    }

    const int m0 = bm + ty * 8;
    const int n0 = bn + tx * 8;
    float bv[8];
#pragma unroll
    for (int j = 0; j < 8; j++) bv[j] = bias[n0 + j];

#pragma unroll
    for (int i = 0; i < 8; i++) {
        const int m = m0 + i;
        const int s = m & (SMAX - 1);
#pragma unroll
        for (int j = 0; j < 8; j++) {
            const int n = n0 + j;
            float v = acc[i][j] + bv[j];
            if (EPI == EPI_RELU) v = fmaxf(v, 0.0f);
            if (EPI == EPI_RES)  v += res[(size_t)m * N + n];
            if (EPI == EPI_PE) {
                const int de = n & ~1;
                float ang = (float)s * expf((float)de * (-9.210340371976184f / 512.0f));
                v += (n & 1) ? cosf(ang) : sinf(ang);
            }
            C[(size_t)m * N + n] = v;
        }
    }
}

// =============================================================================
// Flash-style tensor-core attention.
// CTA = (64 queries, head, batch), 128 threads (4 warps, 16 query rows each).
// QK^T and P·V via split-bf16 3-pass m16n8k16 (same scheme as GEMM, ~1e-6 err).
// Online softmax in registers; key-padding mask (col >= len -> -1e9).
// =============================================================================
#define ATQ   64
#define APAD  72
#define APLE  (64 * APAD)
#define ATTN_SMEM (6 * APLE * 2)   // 55296 B

__global__ __launch_bounds__(128) void fattn_kernel(
    const float* __restrict__ qkv, const int* __restrict__ lens,
    float* __restrict__ ctx)
{
    extern __shared__ bf16 sa[];
    bf16* sQh = sa;
    bf16* sQl = sa + APLE;
    bf16* sKh = sa + 2 * APLE;
    bf16* sKl = sa + 3 * APLE;
    bf16* sVh = sa + 4 * APLE;   // transposed: [dh][key]
    bf16* sVl = sa + 5 * APLE;

    const int qt = blockIdx.x;
    const int hd = blockIdx.y;
    const int b  = blockIdx.z;
    const int tid  = threadIdx.x;
    const int w    = tid >> 5;
    const int lane = tid & 31;
    const int g    = lane >> 2;
    const int tg   = lane & 3;
    const int len  = lens[b];

    const float* base = qkv + (size_t)b * SMAX * (3 * DMODEL);

    // ---- load Q tile [64 x 64], split into hi/lo ----
#pragma unroll
    for (int p = 0; p < 8; p++) {
        const int cid = p * 128 + tid;
        const int r  = cid >> 4;
        const int c4 = (cid & 15) * 4;
        float4 v = *(const float4*)(base + (size_t)(qt * ATQ + r) * (3 * DMODEL) + hd * DH + c4);
        cvt_store4(sQh + r * APAD + c4, sQl + r * APAD + c4, v);
    }

    float sfr[8][4];
    float ofr[8][4];
#pragma unroll
    for (int j = 0; j < 8; j++)
#pragma unroll
        for (int c = 0; c < 4; c++) ofr[j][c] = 0.0f;
    float m0 = -1e30f, m1 = -1e30f, l0 = 0.0f, l1 = 0.0f;

    const int qrow = w * 16;

    for (int kt = 0; kt < 8; kt++) {
        __syncthreads();
        // ---- load K tile (split) + V tile (split + transpose) ----
#pragma unroll
        for (int p = 0; p < 8; p++) {
            const int cid = p * 128 + tid;
            const int r  = cid >> 4;
            const int c4 = (cid & 15) * 4;
            const float* rowp = base + (size_t)(kt * 64 + r) * (3 * DMODEL) + hd * DH;
            float4 kv = *(const float4*)(rowp + DMODEL + c4);
            cvt_store4(sKh + r * APAD + c4, sKl + r * APAD + c4, kv);
            float4 vv = *(const float4*)(rowp + 2 * DMODEL + c4);
            float vf[4] = {vv.x, vv.y, vv.z, vv.w};
#pragma unroll
            for (int i = 0; i < 4; i++) {
                bf16 hh, ll;
                split1(vf[i], hh, ll);
                sVh[(c4 + i) * APAD + r] = hh;
                sVl[(c4 + i) * APAD + r] = ll;
            }
        }
        __syncthreads();

        // ---- S = Q K^T (split, 3 passes) ----
#pragma unroll
        for (int j = 0; j < 8; j++)
#pragma unroll
            for (int c = 0; c < 4; c++) sfr[j][c] = 0.0f;

#pragma unroll
        for (int kc = 0; kc < 4; kc++) {
            const int kcol = kc * 16 + 2 * tg;
            uint32_t aQh[4], aQl[4];
            const bf16* q0 = sQh + (qrow + g) * APAD + kcol;
            aQh[0] = ld32(q0);
            aQh[1] = ld32(q0 + 8 * APAD);
            aQh[2] = ld32(q0 + 8);
            aQh[3] = ld32(q0 + 8 * APAD + 8);
            const bf16* q1 = sQl + (qrow + g) * APAD + kcol;
            aQl[0] = ld32(q1);
            aQl[1] = ld32(q1 + 8 * APAD);
            aQl[2] = ld32(q1 + 8);
            aQl[3] = ld32(q1 + 8 * APAD + 8);
#pragma unroll
            for (int j = 0; j < 8; j++) {
                uint32_t bh[2], bl[2];
                const bf16* k0 = sKh + (j * 8 + g) * APAD + kcol;
                bh[0] = ld32(k0); bh[1] = ld32(k0 + 8);
                const bf16* k1 = sKl + (j * 8 + g) * APAD + kcol;
                bl[0] = ld32(k1); bl[1] = ld32(k1 + 8);
                mma16816(sfr[j], aQh, bh);
                mma16816(sfr[j], aQh, bl);
                mma16816(sfr[j], aQl, bh);
            }
        }

        // ---- scale + mask + online softmax update ----
        float tmax0 = -1e30f, tmax1 = -1e30f;
#pragma unroll
        for (int j = 0; j < 8; j++) {
            const int col = kt * 64 + j * 8 + 2 * tg;
            const bool v0 = col < len, v1 = (col + 1) < len;
            sfr[j][0] = v0 ? sfr[j][0] * 0.125f : -1e9f;
            sfr[j][1] = v1 ? sfr[j][1] * 0.125f : -1e9f;
            sfr[j][2] = v0 ? sfr[j][2] * 0.125f : -1e9f;
            sfr[j][3] = v1 ? sfr[j][3] * 0.125f : -1e9f;
            tmax0 = fmaxf(tmax0, fmaxf(sfr[j][0], sfr[j][1]));
            tmax1 = fmaxf(tmax1, fmaxf(sfr[j][2], sfr[j][3]));
        }
        tmax0 = fmaxf(tmax0, __shfl_xor_sync(0xffffffffu, tmax0, 1));
        tmax0 = fmaxf(tmax0, __shfl_xor_sync(0xffffffffu, tmax0, 2));
        tmax1 = fmaxf(tmax1, __shfl_xor_sync(0xffffffffu, tmax1, 1));
        tmax1 = fmaxf(tmax1, __shfl_xor_sync(0xffffffffu, tmax1, 2));

        const float nm0 = fmaxf(m0, tmax0), nm1 = fmaxf(m1, tmax1);
        const float al0 = expf(m0 - nm0), al1 = expf(m1 - nm1);
        m0 = nm0; m1 = nm1;

        float rs0 = 0.0f, rs1 = 0.0f;
#pragma unroll
        for (int j = 0; j < 8; j++) {
            sfr[j][0] = expf(sfr[j][0] - nm0);
            sfr[j][1] = expf(sfr[j][1] - nm0);
            sfr[j][2] = expf(sfr[j][2] - nm1);
            sfr[j][3] = expf(sfr[j][3] - nm1);
            rs0 += sfr[j][0] + sfr[j][1];
            rs1 += sfr[j][2] + sfr[j][3];
        }
        rs0 += __shfl_xor_sync(0xffffffffu, rs0, 1);
        rs0 += __shfl_xor_sync(0xffffffffu, rs0, 2);
        rs1 += __shfl_xor_sync(0xffffffffu, rs1, 1);
        rs1 += __shfl_xor_sync(0xffffffffu, rs1, 2);
        l0 = l0 * al0 + rs0;
        l1 = l1 * al1 + rs1;

#pragma unroll
        for (int j = 0; j < 8; j++) {
            ofr[j][0] *= al0; ofr[j][1] *= al0;
            ofr[j][2] *= al1; ofr[j][3] *= al1;
        }

        // ---- O += P V (split P and V, 3 passes) ----
#pragma unroll
        for (int kc = 0; kc < 4; kc++) {
            uint32_t aPh[4], aPl[4];
            packsplit2(sfr[2 * kc][0],     sfr[2 * kc][1],     aPh[0], aPl[0]);
            packsplit2(sfr[2 * kc][2],     sfr[2 * kc][3],     aPh[1], aPl[1]);
            packsplit2(sfr[2 * kc + 1][0], sfr[2 * kc + 1][1], aPh[2], aPl[2]);
            packsplit2(sfr[2 * kc + 1][2], sfr[2 * kc + 1][3], aPh[3], aPl[3]);
            const int kcol = kc * 16 + 2 * tg;
#pragma unroll
            for (int j = 0; j < 8; j++) {
                uint32_t bh[2], bl[2];
                const bf16* v0 = sVh + (j * 8 + g) * APAD + kcol;
                bh[0] = ld32(v0); bh[1] = ld32(v0 + 8);
                const bf16* v1 = sVl + (j * 8 + g) * APAD + kcol;
                bl[0] = ld32(v1); bl[1] = ld32(v1 + 8);
                mma16816(ofr[j], aPh, bh);
                mma16816(ofr[j], aPh, bl);
                mma16816(ofr[j], aPl, bh);
            }
        }
    }

    // ---- finalize: O /= l, write ctx fp32 ----
    const float inv0 = 1.0f / l0, inv1 = 1.0f / l1;
    const int q0 = qt * ATQ + qrow + g;
#pragma unroll
    for (int j = 0; j < 8; j++) {
        const int col = hd * DH + j * 8 + 2 * tg;
        float* p0 = ctx + ((size_t)b * SMAX + q0) * DMODEL + col;
        p0[0] = ofr[j][0] * inv0;
        p0[1] = ofr[j][1] * inv0;
        float* p1 = ctx + ((size_t)b * SMAX + q0 + 8) * DMODEL + col;
        p1[0] = ofr[j][2] * inv1;
        p1[1] = ofr[j][3] * inv1;
    }
}

// ---------------- LayerNorm (in place, per token row of 512) ----------------
__global__ __launch_bounds__(128) void ln_kernel(
    float* __restrict__ h, const float* __restrict__ g, const float* __restrict__ bta)
{
    __shared__ float red[8];
    const int row = blockIdx.x;
    const int t = threadIdx.x;
    float* p = h + (size_t)row * DMODEL + t * 4;
    float4 v = *(float4*)p;
    float s  = v.x + v.y + v.z + v.w;
    float ss = v.x * v.x + v.y * v.y + v.z * v.z + v.w * v.w;
#pragma unroll
    for (int o = 16; o; o >>= 1) {
        s  += __shfl_xor_sync(0xffffffffu, s, o);
        ss += __shfl_xor_sync(0xffffffffu, ss, o);
    }
    const int w = t >> 5;
    if ((t & 31) == 0) { red[w] = s; red[4 + w] = ss; }
    __syncthreads();
    s  = red[0] + red[1] + red[2] + red[3];
    ss = red[4] + red[5] + red[6] + red[7];
    const float mean = s * (1.0f / DMODEL);
    const float var  = ss * (1.0f / DMODEL) - mean * mean;
    const float rstd = rsqrtf(var + 1e-5f);
    float4 gg = *(const float4*)(g + t * 4);
    float4 bb = *(const float4*)(bta + t * 4);
    v.x = (v.x - mean) * rstd * gg.x + bb.x;
    v.y = (v.y - mean) * rstd * gg.y + bb.y;
    v.z = (v.z - mean) * rstd * gg.z + bb.z;
    v.w = (v.w - mean) * rstd * gg.w + bb.w;
    *(float4*)p = v;
}

// ---------------- two-phase masked mean pooling ------------------------------
__global__ __launch_bounds__(128) void pool_part_kernel(
    const float* __restrict__ h, const int* __restrict__ lens, float* __restrict__ part)
{
    const int b = blockIdx.x;
    const int ch = blockIdx.y;
    const int d = threadIdx.x * 4;
    const int len = lens[b];
    const int t0 = ch * 64;
    int nt = len - t0;
    if (nt > 64) nt = 64;
    float4 s = {0.f, 0.f, 0.f, 0.f};
    for (int t = 0; t < nt; t++) {
        float4 v = *(const float4*)(h + ((size_t)b * SMAX + t0 + t) * DMODEL + d);
        s.x += v.x; s.y += v.y; s.z += v.z; s.w += v.w;
    }
    *(float4*)(part + (size_t)(b * 8 + ch) * DMODEL + d) = s;
}

__global__ __launch_bounds__(DMODEL) void pool_final_kernel(
    const float* __restrict__ part, const int* __restrict__ lens,
    float* __restrict__ out, int out_size)
{
    const int b = blockIdx.x;
    const int d = threadIdx.x;
    float s = 0.0f;
#pragma unroll
    for (int c = 0; c < 8; c++) s += part[(size_t)(b * 8 + c) * DMODEL + d];
    out[b * DMODEL + d] = s / (float)lens[b];
    if (d == 0 && out_size >= BATCH * DMODEL + BATCH)
        out[BATCH * DMODEL + b] = (float)lens[b];
}

// ---------------- launch ------------------------------------------------------
extern "C" void kernel_launch(void* const* d_in, const int* in_sizes, int n_in,
                              void* d_out, int out_size)
{
    (void)in_sizes; (void)n_in;
    const float* x     = (const float*)d_in[0];
    const int*   lens  = (const int*)  d_in[1];
    const float* We    = (const float*)d_in[2];
    const float* be    = (const float*)d_in[3];
    const float* Wqkv  = (const float*)d_in[4];
    const float* bqkv  = (const float*)d_in[5];
    const float* Wo    = (const float*)d_in[6];
    const float* bo    = (const float*)d_in[7];
    const float* ln1g  = (const float*)d_in[8];
    const float* ln1b  = (const float*)d_in[9];
    const float* W1    = (const float*)d_in[10];
    const float* b1    = (const float*)d_in[11];
    const float* W2    = (const float*)d_in[12];
    const float* b2    = (const float*)d_in[13];
    const float* ln2g  = (const float*)d_in[14];
    const float* ln2b  = (const float*)d_in[15];
    float* out = (float*)d_out;

    void *ph, *pqkv, *pctx, *pff, *ppool;
    cudaGetSymbolAddress(&ph,    g_h);
    cudaGetSymbolAddress(&pqkv,  g_qkv);
    cudaGetSymbolAddress(&pctx,  g_ctx);
    cudaGetSymbolAddress(&pff,   g_ff);
    cudaGetSymbolAddress(&ppool, g_pool);
    float* h    = (float*)ph;
    float* qkv  = (float*)pqkv;
    float* ctx  = (float*)pctx;
    float* ff   = (float*)pff;
    float* pool = (float*)ppool;

    cudaFuncSetAttribute(fattn_kernel,
                         cudaFuncAttributeMaxDynamicSharedMemorySize, ATTN_SMEM);
    cudaFuncSetAttribute(bgemm_kernel<EPI_NONE>,
                         cudaFuncAttributeMaxDynamicSharedMemorySize, GSMEM);
    cudaFuncSetAttribute(bgemm_kernel<EPI_RELU>,
                         cudaFuncAttributeMaxDynamicSharedMemorySize, GSMEM);
    cudaFuncSetAttribute(bgemm_kernel<EPI_RES>,
                         cudaFuncAttributeMaxDynamicSharedMemorySize, GSMEM);

    // embedding + positional encoding (fp32 path): h = x @ We^T + be + PE
    sgemm_kernel<EPI_PE><<<dim3(DMODEL / 128, NTOK / 128), 256>>>(
        x, We, be, nullptr, h, NTOK, DMODEL, INSZ);

    for (int l = 0; l < NLAYERS; l++) {
        const float* wq  = Wqkv + (size_t)l * 3 * DMODEL * DMODEL;
        const float* bq  = bqkv + (size_t)l * 3 * DMODEL;
        const float* wo  = Wo   + (size_t)l * DMODEL * DMODEL;
        const float* bO  = bo   + (size_t)l * DMODEL;
        const float* w1  = W1   + (size_t)l * DFF * DMODEL;
        const float* bf1 = b1   + (size_t)l * DFF;
        const float* w2  = W2   + (size_t)l * DMODEL * DFF;
        const float* bf2 = b2   + (size_t)l * DMODEL;

        // qkv = h @ Wqkv^T + bqkv
        bgemm_kernel<EPI_NONE><<<dim3(3 * DMODEL / 128, NTOK / 128), 256, GSMEM>>>(
            h, wq, bq, nullptr, qkv, NTOK, 3 * DMODEL, DMODEL);

        // attention -> ctx (fp32)
        fattn_kernel<<<dim3(SMAX / ATQ, NHEAD, BATCH), 128, ATTN_SMEM>>>(qkv, lens, ctx);

        // h = h + ctx @ Wo^T + bo
        bgemm_kernel<EPI_RES><<<dim3(DMODEL / 128, NTOK / 128), 256, GSMEM>>>(
            ctx, wo, bO, h, h, NTOK, DMODEL, DMODEL);
        ln_kernel<<<NTOK, 128>>>(h, ln1g + l * DMODEL, ln1b + l * DMODEL);

        // ff = relu(h @ W1^T + b1)
        bgemm_kernel<EPI_RELU><<<dim3(DFF / 128, NTOK / 128), 256, GSMEM>>>(
            h, w1, bf1, nullptr, ff, NTOK, DFF, DMODEL);
        // h = h + ff @ W2^T + b2
        bgemm_kernel<EPI_RES><<<dim3(DMODEL / 128, NTOK / 128), 256, GSMEM>>>(
            ff, w2, bf2, h, h, NTOK, DMODEL, DFF);
        ln_kernel<<<NTOK, 128>>>(h, ln2g + l * DMODEL, ln2b + l * DMODEL);
    }

    pool_part_kernel<<<dim3(BATCH, 8), 128>>>(h, lens, pool);
    pool_final_kernel<<<BATCH, DMODEL>>>(pool, lens, out, out_size);
}

// round 8
// speedup vs baseline: 1.6289x; 1.0299x over previous
#include <cuda_runtime.h>
#include <cuda_bf16.h>
#include <cstdint>

// ---------------- problem constants ----------------
#define NLAYERS 4
#define INSZ    80
#define DMODEL  512
#define NHEAD   8
#define DH      64
#define DFF     2048
#define BATCH   16
#define SMAX    512
#define NTOK    (BATCH * SMAX)   // 8192

typedef __nv_bfloat16 bf16;

// ---------------- scratch (device globals; no allocs allowed) ----------------
__device__ float g_h  [NTOK * DMODEL];       // hidden state
__device__ float g_qkv[NTOK * 3 * DMODEL];   // qkv projections
__device__ float g_ctx[NTOK * DMODEL];       // attention context
__device__ float g_ff [NTOK * DFF];          // ff intermediate
__device__ float g_pool[BATCH * 8 * DMODEL]; // pooling partials

enum { EPI_NONE = 0, EPI_PE = 1, EPI_RELU = 2, EPI_RES = 3 };

// ---------------- helpers -----------------------------------------------------
__device__ __forceinline__ void mma16816(float* d, const uint32_t* a, const uint32_t* b) {
    asm volatile(
        "mma.sync.aligned.m16n8k16.row.col.f32.bf16.bf16.f32 "
        "{%0,%1,%2,%3},{%4,%5,%6,%7},{%8,%9},{%0,%1,%2,%3};\n"
        : "+f"(d[0]), "+f"(d[1]), "+f"(d[2]), "+f"(d[3])
        : "r"(a[0]), "r"(a[1]), "r"(a[2]), "r"(a[3]), "r"(b[0]), "r"(b[1]));
}

__device__ __forceinline__ uint32_t ld32(const bf16* p) {
    return *reinterpret_cast<const uint32_t*>(p);
}

__device__ __forceinline__ void split1(float v, bf16& h, bf16& l) {
    h = __float2bfloat16(v);
    l = __float2bfloat16(v - __bfloat162float(h));
}

__device__ __forceinline__ void cvt_store4(bf16* dh, bf16* dl, float4 v) {
    union { bf16 b[4]; uint2 u; } H, L;
    split1(v.x, H.b[0], L.b[0]);
    split1(v.y, H.b[1], L.b[1]);
    split1(v.z, H.b[2], L.b[2]);
    split1(v.w, H.b[3], L.b[3]);
    *reinterpret_cast<uint2*>(dh) = H.u;
    *reinterpret_cast<uint2*>(dl) = L.u;
}

__device__ __forceinline__ void packsplit2(float x, float y, uint32_t& hi, uint32_t& lo) {
    bf16 hx, lx, hy, ly;
    split1(x, hx, lx);
    split1(y, hy, ly);
    union { bf16 b[2]; uint32_t u; } H, L;
    H.b[0] = hx; H.b[1] = hy;
    L.b[0] = lx; L.b[1] = ly;
    hi = H.u; lo = L.u;
}

// =============================================================================
// bf16 split-precision tensor-core GEMM (R2 scheme, 128x64 CTA tile):
//   C[M,N] = A[M,K] * B[N,K]^T + bias (+epilogue), fp32 in/out,
//   in-kernel hi/lo split, acc += Ah*Bh + Ah*Bl + Al*Bh.
// 256 threads, warp tile 32x32 (warp grid 4m x 2n), register double-buffer.
// Target: ~110 regs -> 2 CTAs/SM.
// =============================================================================
#define BK    32
#define LDS40 40
#define APLN  (128 * LDS40)            // A plane elems (10240)
#define BPLN  (64 * LDS40)             // B plane elems (5120)
#define BUFE  (2 * APLN + 2 * BPLN)    // elems per buffer (30720)
#define GSMEM (2 * BUFE * 2)           // bytes: 61440

template <int EPI>
__global__ __launch_bounds__(256) void bgemm_kernel(
    const float* __restrict__ A, const float* __restrict__ B,
    const float* __restrict__ bias, const float* __restrict__ res,
    float* __restrict__ C, int M, int N, int K)
{
    extern __shared__ bf16 sm[];

    const int tid = threadIdx.x;
    const int bm = blockIdx.y * 128;
    const int bn = blockIdx.x * 64;

    const int wid  = tid >> 5;
    const int wm   = wid & 3;       // 32-row quarter
    const int wn   = wid >> 2;      // 32-col half
    const int lane = tid & 31;
    const int g    = lane >> 2;
    const int tg   = lane & 3;

    float acc[2][4][4];
#pragma unroll
    for (int i = 0; i < 2; i++)
#pragma unroll
        for (int j = 0; j < 4; j++)
#pragma unroll
            for (int r = 0; r < 4; r++) acc[i][j][r] = 0.0f;

    const int ntile = K / BK;

    // ---- prologue: load tile 0, split into smem ----
    {
#pragma unroll
        for (int p = 0; p < 4; p++) {
            const int idx = tid + p * 256;
            const int row = idx >> 3;
            const int c4  = (idx & 7) * 4;
            float4 va = *(const float4*)(A + (size_t)(bm + row) * K + c4);
            cvt_store4(sm + row * LDS40 + c4, sm + APLN + row * LDS40 + c4, va);
        }
#pragma unroll
        for (int p = 0; p < 2; p++) {
            const int idx = tid + p * 256;
            const int row = idx >> 3;
            const int c4  = (idx & 7) * 4;
            float4 vb = *(const float4*)(B + (size_t)(bn + row) * K + c4);
            cvt_store4(sm + 2 * APLN + row * LDS40 + c4,
                       sm + 2 * APLN + BPLN + row * LDS40 + c4, vb);
        }
    }
    __syncthreads();

    for (int t = 0; t < ntile; t++) {
        const int cur = (t & 1) * BUFE;
        const int nxt = ((t + 1) & 1) * BUFE;

        // prefetch next K-tile into registers
        float4 ra[4], rb[2];
        const bool have_next = (t + 1 < ntile);
        if (have_next) {
            const int k0 = (t + 1) * BK;
#pragma unroll
            for (int p = 0; p < 4; p++) {
                const int idx = tid + p * 256;
                const int row = idx >> 3;
                const int c4  = (idx & 7) * 4;
                ra[p] = *(const float4*)(A + (size_t)(bm + row) * K + k0 + c4);
            }
#pragma unroll
            for (int p = 0; p < 2; p++) {
                const int idx = tid + p * 256;
                const int row = idx >> 3;
                const int c4  = (idx & 7) * 4;
                rb[p] = *(const float4*)(B + (size_t)(bn + row) * K + k0 + c4);
            }
        }

        const bf16* sAh = sm + cur;
        const bf16* sAl = sm + cur + APLN;
        const bf16* sBh = sm + cur + 2 * APLN;
        const bf16* sBl = sm + cur + 2 * APLN + BPLN;

#pragma unroll
        for (int ks = 0; ks < 2; ks++) {
            const int kc = ks * 16 + 2 * tg;
            uint32_t ah[2][4], al[2][4], bh[4][2], bl[4][2];
#pragma unroll
            for (int mi = 0; mi < 2; mi++) {
                const int r = wm * 32 + mi * 16 + g;
                const bf16* pH = sAh + r * LDS40 + kc;
                const bf16* pL = sAl + r * LDS40 + kc;
                ah[mi][0] = ld32(pH);
                ah[mi][1] = ld32(pH + 8 * LDS40);
                ah[mi][2] = ld32(pH + 8);
                ah[mi][3] = ld32(pH + 8 * LDS40 + 8);
                al[mi][0] = ld32(pL);
                al[mi][1] = ld32(pL + 8 * LDS40);
                al[mi][2] = ld32(pL + 8);
                al[mi][3] = ld32(pL + 8 * LDS40 + 8);
            }
#pragma unroll
            for (int ni = 0; ni < 4; ni++) {
                const int r = wn * 32 + ni * 8 + g;
                const bf16* pH = sBh + r * LDS40 + kc;
                const bf16* pL = sBl + r * LDS40 + kc;
                bh[ni][0] = ld32(pH);
                bh[ni][1] = ld32(pH + 8);
                bl[ni][0] = ld32(pL);
                bl[ni][1] = ld32(pL + 8);
            }
#pragma unroll
            for (int mi = 0; mi < 2; mi++)
#pragma unroll
                for (int ni = 0; ni < 4; ni++) {
                    mma16816(acc[mi][ni], ah[mi], bh[ni]);
                    mma16816(acc[mi][ni], ah[mi], bl[ni]);
                    mma16816(acc[mi][ni], al[mi], bh[ni]);
                }
        }

        if (have_next) {
#pragma unroll
            for (int p = 0; p < 4; p++) {
                const int idx = tid + p * 256;
                const int row = idx >> 3;
                const int c4  = (idx & 7) * 4;
                cvt_store4(sm + nxt + row * LDS40 + c4,
                           sm + nxt + APLN + row * LDS40 + c4, ra[p]);
            }
#pragma unroll
            for (int p = 0; p < 2; p++) {
                const int idx = tid + p * 256;
                const int row = idx >> 3;
                const int c4  = (idx & 7) * 4;
                cvt_store4(sm + nxt + 2 * APLN + row * LDS40 + c4,
                           sm + nxt + 2 * APLN + BPLN + row * LDS40 + c4, rb[p]);
            }
        }
        __syncthreads();
    }

    // ---- epilogue ----
#pragma unroll
    for (int mi = 0; mi < 2; mi++) {
#pragma unroll
        for (int ni = 0; ni < 4; ni++) {
            const int m = bm + wm * 32 + mi * 16 + g;
            const int n = bn + wn * 32 + ni * 8 + tg * 2;
            const float b0 = bias[n], b1 = bias[n + 1];
#pragma unroll
            for (int h = 0; h < 2; h++) {
                const int mm = m + h * 8;
                float v0 = acc[mi][ni][h * 2 + 0] + b0;
                float v1 = acc[mi][ni][h * 2 + 1] + b1;
                if (EPI == EPI_RELU) { v0 = fmaxf(v0, 0.0f); v1 = fmaxf(v1, 0.0f); }
                if (EPI == EPI_RES) {
                    const float* rp = res + (size_t)mm * N + n;
                    v0 += rp[0]; v1 += rp[1];
                }
                float* cp = C + (size_t)mm * N + n;
                cp[0] = v0; cp[1] = v1;
            }
        }
    }
}

// ---------------- fp32 SGEMM (embed, K=80) — R2 version ----------------------
template <int EPI>
__global__ __launch_bounds__(256) void sgemm_kernel(
    const float* __restrict__ A, const float* __restrict__ B,
    const float* __restrict__ bias, const float* __restrict__ res,
    float* __restrict__ C, int M, int N, int K)
{
    __shared__ float As[16][132];
    __shared__ float Bs[16][132];

    const int tid = threadIdx.x;
    const int bm = blockIdx.y * 128;
    const int bn = blockIdx.x * 128;

    const int lr = tid >> 2;
    const int lc = (tid & 3) * 4;
    const int ty = tid >> 4;
    const int tx = tid & 15;

    float acc[8][8];
#pragma unroll
    for (int i = 0; i < 8; i++)
#pragma unroll
        for (int j = 0; j < 8; j++) acc[i][j] = 0.0f;

    for (int k0 = 0; k0 < K; k0 += 16) {
#pragma unroll
        for (int p = 0; p < 2; p++) {
            const int row = lr + p * 64;
            float4 a = *(const float4*)(A + (size_t)(bm + row) * K + k0 + lc);
            float4 b = *(const float4*)(B + (size_t)(bn + row) * K + k0 + lc);
            As[lc + 0][row] = a.x; As[lc + 1][row] = a.y;
            As[lc + 2][row] = a.z; As[lc + 3][row] = a.w;
            Bs[lc + 0][row] = b.x; Bs[lc + 1][row] = b.y;
            Bs[lc + 2][row] = b.z; Bs[lc + 3][row] = b.w;
        }
        __syncthreads();
#pragma unroll
        for (int kk = 0; kk < 16; kk++) {
            float a[8], b[8];
            *(float4*)(a)     = *(const float4*)&As[kk][ty * 8];
            *(float4*)(a + 4) = *(const float4*)&As[kk][ty * 8 + 4];
            *(float4*)(b)     = *(const float4*)&Bs[kk][tx * 8];
            *(float4*)(b + 4) = *(const float4*)&Bs[kk][tx * 8 + 4];
#pragma unroll
            for (int i = 0; i < 8; i++)
#pragma unroll
                for (int j = 0; j < 8; j++)
                    acc[i][j] += a[i] * b[j];
        }
        __syncthreads();
    }

    const int m0 = bm + ty * 8;
    const int n0 = bn + tx * 8;
    float bv[8];
#pragma unroll
    for (int j = 0; j < 8; j++) bv[j] = bias[n0 + j];

#pragma unroll
    for (int i = 0; i < 8; i++) {
        const int m = m0 + i;
        const int s = m & (SMAX - 1);
#pragma unroll
        for (int j = 0; j < 8; j++) {
            const int n = n0 + j;
            float v = acc[i][j] + bv[j];
            if (EPI == EPI_RELU) v = fmaxf(v, 0.0f);
            if (EPI == EPI_RES)  v += res[(size_t)m * N + n];
            if (EPI == EPI_PE) {
                const int de = n & ~1;
                float ang = (float)s * expf((float)de * (-9.210340371976184f / 512.0f));
                v += (n & 1) ? cosf(ang) : sinf(ang);
            }
            C[(size_t)m * N + n] = v;
        }
    }
}

// =============================================================================
// Flash-style tensor-core attention (R6, unchanged).
// =============================================================================
#define ATQ   64
#define APAD  72
#define APLE  (64 * APAD)
#define ATTN_SMEM (6 * APLE * 2)   // 55296 B

__global__ __launch_bounds__(128) void fattn_kernel(
    const float* __restrict__ qkv, const int* __restrict__ lens,
    float* __restrict__ ctx)
{
    extern __shared__ bf16 sa[];
    bf16* sQh = sa;
    bf16* sQl = sa + APLE;
    bf16* sKh = sa + 2 * APLE;
    bf16* sKl = sa + 3 * APLE;
    bf16* sVh = sa + 4 * APLE;   // transposed: [dh][key]
    bf16* sVl = sa + 5 * APLE;

    const int qt = blockIdx.x;
    const int hd = blockIdx.y;
    const int b  = blockIdx.z;
    const int tid  = threadIdx.x;
    const int w    = tid >> 5;
    const int lane = tid & 31;
    const int g    = lane >> 2;
    const int tg   = lane & 3;
    const int len  = lens[b];

    const float* base = qkv + (size_t)b * SMAX * (3 * DMODEL);

#pragma unroll
    for (int p = 0; p < 8; p++) {
        const int cid = p * 128 + tid;
        const int r  = cid >> 4;
        const int c4 = (cid & 15) * 4;
        float4 v = *(const float4*)(base + (size_t)(qt * ATQ + r) * (3 * DMODEL) + hd * DH + c4);
        cvt_store4(sQh + r * APAD + c4, sQl + r * APAD + c4, v);
    }

    float sfr[8][4];
    float ofr[8][4];
#pragma unroll
    for (int j = 0; j < 8; j++)
#pragma unroll
        for (int c = 0; c < 4; c++) ofr[j][c] = 0.0f;
    float m0 = -1e30f, m1 = -1e30f, l0 = 0.0f, l1 = 0.0f;

    const int qrow = w * 16;

    for (int kt = 0; kt < 8; kt++) {
        __syncthreads();
#pragma unroll
        for (int p = 0; p < 8; p++) {
            const int cid = p * 128 + tid;
            const int r  = cid >> 4;
            const int c4 = (cid & 15) * 4;
            const float* rowp = base + (size_t)(kt * 64 + r) * (3 * DMODEL) + hd * DH;
            float4 kv = *(const float4*)(rowp + DMODEL + c4);
            cvt_store4(sKh + r * APAD + c4, sKl + r * APAD + c4, kv);
            float4 vv = *(const float4*)(rowp + 2 * DMODEL + c4);
            float vf[4] = {vv.x, vv.y, vv.z, vv.w};
#pragma unroll
            for (int i = 0; i < 4; i++) {
                bf16 hh, ll;
                split1(vf[i], hh, ll);
                sVh[(c4 + i) * APAD + r] = hh;
                sVl[(c4 + i) * APAD + r] = ll;
            }
        }
        __syncthreads();

#pragma unroll
        for (int j = 0; j < 8; j++)
#pragma unroll
            for (int c = 0; c < 4; c++) sfr[j][c] = 0.0f;

#pragma unroll
        for (int kc = 0; kc < 4; kc++) {
            const int kcol = kc * 16 + 2 * tg;
            uint32_t aQh[4], aQl[4];
            const bf16* q0 = sQh + (qrow + g) * APAD + kcol;
            aQh[0] = ld32(q0);
            aQh[1] = ld32(q0 + 8 * APAD);
            aQh[2] = ld32(q0 + 8);
            aQh[3] = ld32(q0 + 8 * APAD + 8);
            const bf16* q1 = sQl + (qrow + g) * APAD + kcol;
            aQl[0] = ld32(q1);
            aQl[1] = ld32(q1 + 8 * APAD);
            aQl[2] = ld32(q1 + 8);
            aQl[3] = ld32(q1 + 8 * APAD + 8);
#pragma unroll
            for (int j = 0; j < 8; j++) {
                uint32_t bh[2], bl[2];
                const bf16* k0 = sKh + (j * 8 + g) * APAD + kcol;
                bh[0] = ld32(k0); bh[1] = ld32(k0 + 8);
                const bf16* k1 = sKl + (j * 8 + g) * APAD + kcol;
                bl[0] = ld32(k1); bl[1] = ld32(k1 + 8);
                mma16816(sfr[j], aQh, bh);
                mma16816(sfr[j], aQh, bl);
                mma16816(sfr[j], aQl, bh);
            }
        }

        float tmax0 = -1e30f, tmax1 = -1e30f;
#pragma unroll
        for (int j = 0; j < 8; j++) {
            const int col = kt * 64 + j * 8 + 2 * tg;
            const bool v0 = col < len, v1 = (col + 1) < len;
            sfr[j][0] = v0 ? sfr[j][0] * 0.125f : -1e9f;
            sfr[j][1] = v1 ? sfr[j][1] * 0.125f : -1e9f;
            sfr[j][2] = v0 ? sfr[j][2] * 0.125f : -1e9f;
            sfr[j][3] = v1 ? sfr[j][3] * 0.125f : -1e9f;
            tmax0 = fmaxf(tmax0, fmaxf(sfr[j][0], sfr[j][1]));
            tmax1 = fmaxf(tmax1, fmaxf(sfr[j][2], sfr[j][3]));
        }
        tmax0 = fmaxf(tmax0, __shfl_xor_sync(0xffffffffu, tmax0, 1));
        tmax0 = fmaxf(tmax0, __shfl_xor_sync(0xffffffffu, tmax0, 2));
        tmax1 = fmaxf(tmax1, __shfl_xor_sync(0xffffffffu, tmax1, 1));
        tmax1 = fmaxf(tmax1, __shfl_xor_sync(0xffffffffu, tmax1, 2));

        const float nm0 = fmaxf(m0, tmax0), nm1 = fmaxf(m1, tmax1);
        const float al0 = expf(m0 - nm0), al1 = expf(m1 - nm1);
        m0 = nm0; m1 = nm1;

        float rs0 = 0.0f, rs1 = 0.0f;
#pragma unroll
        for (int j = 0; j < 8; j++) {
            sfr[j][0] = expf(sfr[j][0] - nm0);
            sfr[j][1] = expf(sfr[j][1] - nm0);
            sfr[j][2] = expf(sfr[j][2] - nm1);
            sfr[j][3] = expf(sfr[j][3] - nm1);
            rs0 += sfr[j][0] + sfr[j][1];
            rs1 += sfr[j][2] + sfr[j][3];
        }
        rs0 += __shfl_xor_sync(0xffffffffu, rs0, 1);
        rs0 += __shfl_xor_sync(0xffffffffu, rs0, 2);
        rs1 += __shfl_xor_sync(0xffffffffu, rs1, 1);
        rs1 += __shfl_xor_sync(0xffffffffu, rs1, 2);
        l0 = l0 * al0 + rs0;
        l1 = l1 * al1 + rs1;

#pragma unroll
        for (int j = 0; j < 8; j++) {
            ofr[j][0] *= al0; ofr[j][1] *= al0;
            ofr[j][2] *= al1; ofr[j][3] *= al1;
        }

#pragma unroll
        for (int kc = 0; kc < 4; kc++) {
            uint32_t aPh[4], aPl[4];
            packsplit2(sfr[2 * kc][0],     sfr[2 * kc][1],     aPh[0], aPl[0]);
            packsplit2(sfr[2 * kc][2],     sfr[2 * kc][3],     aPh[1], aPl[1]);
            packsplit2(sfr[2 * kc + 1][0], sfr[2 * kc + 1][1], aPh[2], aPl[2]);
            packsplit2(sfr[2 * kc + 1][2], sfr[2 * kc + 1][3], aPh[3], aPl[3]);
            const int kcol = kc * 16 + 2 * tg;
#pragma unroll
            for (int j = 0; j < 8; j++) {
                uint32_t bh[2], bl[2];
                const bf16* v0 = sVh + (j * 8 + g) * APAD + kcol;
                bh[0] = ld32(v0); bh[1] = ld32(v0 + 8);
                const bf16* v1 = sVl + (j * 8 + g) * APAD + kcol;
                bl[0] = ld32(v1); bl[1] = ld32(v1 + 8);
                mma16816(ofr[j], aPh, bh);
                mma16816(ofr[j], aPh, bl);
                mma16816(ofr[j], aPl, bh);
            }
        }
    }

    const float inv0 = 1.0f / l0, inv1 = 1.0f / l1;
    const int q0 = qt * ATQ + qrow + g;
#pragma unroll
    for (int j = 0; j < 8; j++) {
        const int col = hd * DH + j * 8 + 2 * tg;
        float* p0 = ctx + ((size_t)b * SMAX + q0) * DMODEL + col;
        p0[0] = ofr[j][0] * inv0;
        p0[1] = ofr[j][1] * inv0;
        float* p1 = ctx + ((size_t)b * SMAX + q0 + 8) * DMODEL + col;
        p1[0] = ofr[j][2] * inv1;
        p1[1] = ofr[j][3] * inv1;
    }
}

// ---------------- LayerNorm (in place, per token row of 512) ----------------
__global__ __launch_bounds__(128) void ln_kernel(
    float* __restrict__ h, const float* __restrict__ g, const float* __restrict__ bta)
{
    __shared__ float red[8];
    const int row = blockIdx.x;
    const int t = threadIdx.x;
    float* p = h + (size_t)row * DMODEL + t * 4;
    float4 v = *(float4*)p;
    float s  = v.x + v.y + v.z + v.w;
    float ss = v.x * v.x + v.y * v.y + v.z * v.z + v.w * v.w;
#pragma unroll
    for (int o = 16; o; o >>= 1) {
        s  += __shfl_xor_sync(0xffffffffu, s, o);
        ss += __shfl_xor_sync(0xffffffffu, ss, o);
    }
    const int w = t >> 5;
    if ((t & 31) == 0) { red[w] = s; red[4 + w] = ss; }
    __syncthreads();
    s  = red[0] + red[1] + red[2] + red[3];
    ss = red[4] + red[5] + red[6] + red[7];
    const float mean = s * (1.0f / DMODEL);
    const float var  = ss * (1.0f / DMODEL) - mean * mean;
    const float rstd = rsqrtf(var + 1e-5f);
    float4 gg = *(const float4*)(g + t * 4);
    float4 bb = *(const float4*)(bta + t * 4);
    v.x = (v.x - mean) * rstd * gg.x + bb.x;
    v.y = (v.y - mean) * rstd * gg.y + bb.y;
    v.z = (v.z - mean) * rstd * gg.z + bb.z;
    v.w = (v.w - mean) * rstd * gg.w + bb.w;
    *(float4*)p = v;
}

// ---------------- two-phase masked mean pooling ------------------------------
__global__ __launch_bounds__(128) void pool_part_kernel(
    const float* __restrict__ h, const int* __restrict__ lens, float* __restrict__ part)
{
    const int b = blockIdx.x;
    const int ch = blockIdx.y;
    const int d = threadIdx.x * 4;
    const int len = lens[b];
    const int t0 = ch * 64;
    int nt = len - t0;
    if (nt > 64) nt = 64;
    float4 s = {0.f, 0.f, 0.f, 0.f};
    for (int t = 0; t < nt; t++) {
        float4 v = *(const float4*)(h + ((size_t)b * SMAX + t0 + t) * DMODEL + d);
        s.x += v.x; s.y += v.y; s.z += v.z; s.w += v.w;
    }
    *(float4*)(part + (size_t)(b * 8 + ch) * DMODEL + d) = s;
}

__global__ __launch_bounds__(DMODEL) void pool_final_kernel(
    const float* __restrict__ part, const int* __restrict__ lens,
    float* __restrict__ out, int out_size)
{
    const int b = blockIdx.x;
    const int d = threadIdx.x;
    float s = 0.0f;
#pragma unroll
    for (int c = 0; c < 8; c++) s += part[(size_t)(b * 8 + c) * DMODEL + d];
    out[b * DMODEL + d] = s / (float)lens[b];
    if (d == 0 && out_size >= BATCH * DMODEL + BATCH)
        out[BATCH * DMODEL + b] = (float)lens[b];
}

// ---------------- launch ------------------------------------------------------
extern "C" void kernel_launch(void* const* d_in, const int* in_sizes, int n_in,
                              void* d_out, int out_size)
{
    (void)in_sizes; (void)n_in;
    const float* x     = (const float*)d_in[0];
    const int*   lens  = (const int*)  d_in[1];
    const float* We    = (const float*)d_in[2];
    const float* be    = (const float*)d_in[3];
    const float* Wqkv  = (const float*)d_in[4];
    const float* bqkv  = (const float*)d_in[5];
    const float* Wo    = (const float*)d_in[6];
    const float* bo    = (const float*)d_in[7];
    const float* ln1g  = (const float*)d_in[8];
    const float* ln1b  = (const float*)d_in[9];
    const float* W1    = (const float*)d_in[10];
    const float* b1    = (const float*)d_in[11];
    const float* W2    = (const float*)d_in[12];
    const float* b2    = (const float*)d_in[13];
    const float* ln2g  = (const float*)d_in[14];
    const float* ln2b  = (const float*)d_in[15];
    float* out = (float*)d_out;

    void *ph, *pqkv, *pctx, *pff, *ppool;
    cudaGetSymbolAddress(&ph,    g_h);
    cudaGetSymbolAddress(&pqkv,  g_qkv);
    cudaGetSymbolAddress(&pctx,  g_ctx);
    cudaGetSymbolAddress(&pff,   g_ff);
    cudaGetSymbolAddress(&ppool, g_pool);
    float* h    = (float*)ph;
    float* qkv  = (float*)pqkv;
    float* ctx  = (float*)pctx;
    float* ff   = (float*)pff;
    float* pool = (float*)ppool;

    cudaFuncSetAttribute(fattn_kernel,
                         cudaFuncAttributeMaxDynamicSharedMemorySize, ATTN_SMEM);
    cudaFuncSetAttribute(bgemm_kernel<EPI_NONE>,
                         cudaFuncAttributeMaxDynamicSharedMemorySize, GSMEM);
    cudaFuncSetAttribute(bgemm_kernel<EPI_RELU>,
                         cudaFuncAttributeMaxDynamicSharedMemorySize, GSMEM);
    cudaFuncSetAttribute(bgemm_kernel<EPI_RES>,
                         cudaFuncAttributeMaxDynamicSharedMemorySize, GSMEM);

    // embedding + positional encoding (fp32 path): h = x @ We^T + be + PE
    sgemm_kernel<EPI_PE><<<dim3(DMODEL / 128, NTOK / 128), 256>>>(
        x, We, be, nullptr, h, NTOK, DMODEL, INSZ);

    for (int l = 0; l < NLAYERS; l++) {
        const float* wq  = Wqkv + (size_t)l * 3 * DMODEL * DMODEL;
        const float* bq  = bqkv + (size_t)l * 3 * DMODEL;
        const float* wo  = Wo   + (size_t)l * DMODEL * DMODEL;
        const float* bO  = bo   + (size_t)l * DMODEL;
        const float* w1  = W1   + (size_t)l * DFF * DMODEL;
        const float* bf1 = b1   + (size_t)l * DFF;
        const float* w2  = W2   + (size_t)l * DMODEL * DFF;
        const float* bf2 = b2   + (size_t)l * DMODEL;

        // qkv = h @ Wqkv^T + bqkv
        bgemm_kernel<EPI_NONE><<<dim3(3 * DMODEL / 64, NTOK / 128), 256, GSMEM>>>(
            h, wq, bq, nullptr, qkv, NTOK, 3 * DMODEL, DMODEL);

        // attention -> ctx (fp32)
        fattn_kernel<<<dim3(SMAX / ATQ, NHEAD, BATCH), 128, ATTN_SMEM>>>(qkv, lens, ctx);

        // h = h + ctx @ Wo^T + bo
        bgemm_kernel<EPI_RES><<<dim3(DMODEL / 64, NTOK / 128), 256, GSMEM>>>(
            ctx, wo, bO, h, h, NTOK, DMODEL, DMODEL);
        ln_kernel<<<NTOK, 128>>>(h, ln1g + l * DMODEL, ln1b + l * DMODEL);

        // ff = relu(h @ W1^T + b1)
        bgemm_kernel<EPI_RELU><<<dim3(DFF / 64, NTOK / 128), 256, GSMEM>>>(
            h, w1, bf1, nullptr, ff, NTOK, DFF, DMODEL);
        // h = h + ff @ W2^T + b2
        bgemm_kernel<EPI_RES><<<dim3(DMODEL / 64, NTOK / 128), 256, GSMEM>>>(
            ff, w2, bf2, h, h, NTOK, DMODEL, DFF);
        ln_kernel<<<NTOK, 128>>>(h, ln2g + l * DMODEL, ln2b + l * DMODEL);
    }

    pool_part_kernel<<<dim3(BATCH, 8), 128>>>(h, lens, pool);
    pool_final_kernel<<<BATCH, DMODEL>>>(pool, lens, out, out_size);
}

// round 9
// speedup vs baseline: 1.7465x; 1.0722x over previous
#include <cuda_runtime.h>
#include <cuda_bf16.h>
#include <cstdint>

// ---------------- problem constants ----------------
#define NLAYERS 4
#define INSZ    80
#define DMODEL  512
#define NHEAD   8
#define DH      64
#define DFF     2048
#define BATCH   16
#define SMAX    512
#define NTOK    (BATCH * SMAX)   // 8192

typedef __nv_bfloat16 bf16;

// ---------------- scratch (device globals; no allocs allowed) ----------------
__device__ float g_h  [NTOK * DMODEL];       // hidden state
__device__ float g_qkv[NTOK * 3 * DMODEL];   // qkv projections
__device__ float g_ctx[NTOK * DMODEL];       // attention context
__device__ float g_ff [NTOK * DFF];          // ff intermediate
__device__ float g_pool[BATCH * 8 * DMODEL]; // pooling partials

enum { EPI_NONE = 0, EPI_PE = 1, EPI_RELU = 2, EPI_RES = 3 };

// ---------------- helpers -----------------------------------------------------
__device__ __forceinline__ void mma16816(float* d, const uint32_t* a, const uint32_t* b) {
    asm volatile(
        "mma.sync.aligned.m16n8k16.row.col.f32.bf16.bf16.f32 "
        "{%0,%1,%2,%3},{%4,%5,%6,%7},{%8,%9},{%0,%1,%2,%3};\n"
        : "+f"(d[0]), "+f"(d[1]), "+f"(d[2]), "+f"(d[3])
        : "r"(a[0]), "r"(a[1]), "r"(a[2]), "r"(a[3]), "r"(b[0]), "r"(b[1]));
}

// tf32 m16n8k8 MMA (fp32 accum)
__device__ __forceinline__ void mma1688(float* d, const uint32_t* a, const uint32_t* b) {
    asm volatile(
        "mma.sync.aligned.m16n8k8.row.col.f32.tf32.tf32.f32 "
        "{%0,%1,%2,%3},{%4,%5,%6,%7},{%8,%9},{%0,%1,%2,%3};\n"
        : "+f"(d[0]), "+f"(d[1]), "+f"(d[2]), "+f"(d[3])
        : "r"(a[0]), "r"(a[1]), "r"(a[2]), "r"(a[3]), "r"(b[0]), "r"(b[1]));
}

__device__ __forceinline__ uint32_t f2tf32(float f) {
    uint32_t u;
    asm("cvt.rna.tf32.f32 %0, %1;" : "=r"(u) : "f"(f));
    return u;
}

__device__ __forceinline__ uint4 tf32x4(float4 v) {
    uint4 u;
    u.x = f2tf32(v.x); u.y = f2tf32(v.y);
    u.z = f2tf32(v.z); u.w = f2tf32(v.w);
    return u;
}

__device__ __forceinline__ uint32_t ld32(const bf16* p) {
    return *reinterpret_cast<const uint32_t*>(p);
}

__device__ __forceinline__ void split1(float v, bf16& h, bf16& l) {
    h = __float2bfloat16(v);
    l = __float2bfloat16(v - __bfloat162float(h));
}

__device__ __forceinline__ void cvt_store4(bf16* dh, bf16* dl, float4 v) {
    union { bf16 b[4]; uint2 u; } H, L;
    split1(v.x, H.b[0], L.b[0]);
    split1(v.y, H.b[1], L.b[1]);
    split1(v.z, H.b[2], L.b[2]);
    split1(v.w, H.b[3], L.b[3]);
    *reinterpret_cast<uint2*>(dh) = H.u;
    *reinterpret_cast<uint2*>(dl) = L.u;
}

__device__ __forceinline__ void packsplit2(float x, float y, uint32_t& hi, uint32_t& lo) {
    bf16 hx, lx, hy, ly;
    split1(x, hx, lx);
    split1(y, hy, ly);
    union { bf16 b[2]; uint32_t u; } H, L;
    H.b[0] = hx; H.b[1] = hy;
    L.b[0] = lx; L.b[1] = ly;
    hi = H.u; lo = L.u;
}

// =============================================================================
// TF32 single-pass tensor-core GEMM:
//   C[M,N] = A[M,K] * B[N,K]^T + bias (+epilogue), fp32 in/out.
// 128x64 CTA tile, 256 threads, warp tile 32x32 (4m x 2n), reg double-buffer.
// smem holds tf32 operands (stride-36 fp32 rows, conflict-free frag loads).
// =============================================================================
#define BK    32
#define LDS36 36
#define APLNW (128 * LDS36)            // A plane u32 words
#define BPLNW (64 * LDS36)             // B plane u32 words
#define BUFW  (APLNW + BPLNW)          // words per buffer
#define GSMEM (2 * BUFW * 4)           // bytes: 55296

template <int EPI>
__global__ __launch_bounds__(256) void bgemm_kernel(
    const float* __restrict__ A, const float* __restrict__ B,
    const float* __restrict__ bias, const float* __restrict__ res,
    float* __restrict__ C, int M, int N, int K)
{
    extern __shared__ uint32_t smu[];

    const int tid = threadIdx.x;
    const int bm = blockIdx.y * 128;
    const int bn = blockIdx.x * 64;

    const int wid  = tid >> 5;
    const int wm   = wid & 3;       // 32-row quarter
    const int wn   = wid >> 2;      // 32-col half
    const int lane = tid & 31;
    const int g    = lane >> 2;
    const int tg   = lane & 3;

    float acc[2][4][4];
#pragma unroll
    for (int i = 0; i < 2; i++)
#pragma unroll
        for (int j = 0; j < 4; j++)
#pragma unroll
            for (int r = 0; r < 4; r++) acc[i][j][r] = 0.0f;

    const int ntile = K / BK;

    // ---- prologue: load tile 0, convert to tf32, store to smem ----
    {
#pragma unroll
        for (int p = 0; p < 4; p++) {
            const int idx = tid + p * 256;
            const int row = idx >> 3;
            const int c4  = (idx & 7) * 4;
            float4 va = *(const float4*)(A + (size_t)(bm + row) * K + c4);
            *(uint4*)(smu + row * LDS36 + c4) = tf32x4(va);
        }
#pragma unroll
        for (int p = 0; p < 2; p++) {
            const int idx = tid + p * 256;
            const int row = idx >> 3;
            const int c4  = (idx & 7) * 4;
            float4 vb = *(const float4*)(B + (size_t)(bn + row) * K + c4);
            *(uint4*)(smu + APLNW + row * LDS36 + c4) = tf32x4(vb);
        }
    }
    __syncthreads();

    for (int t = 0; t < ntile; t++) {
        const int cur = (t & 1) * BUFW;
        const int nxt = ((t + 1) & 1) * BUFW;

        // prefetch next K-tile into registers
        float4 ra[4], rb[2];
        const bool have_next = (t + 1 < ntile);
        if (have_next) {
            const int k0 = (t + 1) * BK;
#pragma unroll
            for (int p = 0; p < 4; p++) {
                const int idx = tid + p * 256;
                const int row = idx >> 3;
                const int c4  = (idx & 7) * 4;
                ra[p] = *(const float4*)(A + (size_t)(bm + row) * K + k0 + c4);
            }
#pragma unroll
            for (int p = 0; p < 2; p++) {
                const int idx = tid + p * 256;
                const int row = idx >> 3;
                const int c4  = (idx & 7) * 4;
                rb[p] = *(const float4*)(B + (size_t)(bn + row) * K + k0 + c4);
            }
        }

        const uint32_t* pA = smu + cur;
        const uint32_t* pB = smu + cur + APLNW;

#pragma unroll
        for (int kk = 0; kk < 4; kk++) {        // 4 x k8 steps
            const int kc = kk * 8 + tg;
            uint32_t a[2][4], b[4][2];
#pragma unroll
            for (int mi = 0; mi < 2; mi++) {
                const int r = wm * 32 + mi * 16 + g;
                a[mi][0] = pA[r * LDS36 + kc];
                a[mi][1] = pA[(r + 8) * LDS36 + kc];
                a[mi][2] = pA[r * LDS36 + kc + 4];
                a[mi][3] = pA[(r + 8) * LDS36 + kc + 4];
            }
#pragma unroll
            for (int ni = 0; ni < 4; ni++) {
                const int r = wn * 32 + ni * 8 + g;
                b[ni][0] = pB[r * LDS36 + kc];
                b[ni][1] = pB[r * LDS36 + kc + 4];
            }
#pragma unroll
            for (int mi = 0; mi < 2; mi++)
#pragma unroll
                for (int ni = 0; ni < 4; ni++)
                    mma1688(acc[mi][ni], a[mi], b[ni]);
        }

        if (have_next) {
#pragma unroll
            for (int p = 0; p < 4; p++) {
                const int idx = tid + p * 256;
                const int row = idx >> 3;
                const int c4  = (idx & 7) * 4;
                *(uint4*)(smu + nxt + row * LDS36 + c4) = tf32x4(ra[p]);
            }
#pragma unroll
            for (int p = 0; p < 2; p++) {
                const int idx = tid + p * 256;
                const int row = idx >> 3;
                const int c4  = (idx & 7) * 4;
                *(uint4*)(smu + nxt + APLNW + row * LDS36 + c4) = tf32x4(rb[p]);
            }
        }
        __syncthreads();
    }

    // ---- epilogue ----
#pragma unroll
    for (int mi = 0; mi < 2; mi++) {
#pragma unroll
        for (int ni = 0; ni < 4; ni++) {
            const int m = bm + wm * 32 + mi * 16 + g;
            const int n = bn + wn * 32 + ni * 8 + tg * 2;
            const float b0 = bias[n], b1 = bias[n + 1];
#pragma unroll
            for (int h = 0; h < 2; h++) {
                const int mm = m + h * 8;
                float v0 = acc[mi][ni][h * 2 + 0] + b0;
                float v1 = acc[mi][ni][h * 2 + 1] + b1;
                if (EPI == EPI_RELU) { v0 = fmaxf(v0, 0.0f); v1 = fmaxf(v1, 0.0f); }
                if (EPI == EPI_RES) {
                    const float* rp = res + (size_t)mm * N + n;
                    v0 += rp[0]; v1 += rp[1];
                }
                float* cp = C + (size_t)mm * N + n;
                cp[0] = v0; cp[1] = v1;
            }
        }
    }
}

// ---------------- fp32 SGEMM (embed, K=80) — R2 version ----------------------
template <int EPI>
__global__ __launch_bounds__(256) void sgemm_kernel(
    const float* __restrict__ A, const float* __restrict__ B,
    const float* __restrict__ bias, const float* __restrict__ res,
    float* __restrict__ C, int M, int N, int K)
{
    __shared__ float As[16][132];
    __shared__ float Bs[16][132];

    const int tid = threadIdx.x;
    const int bm = blockIdx.y * 128;
    const int bn = blockIdx.x * 128;

    const int lr = tid >> 2;
    const int lc = (tid & 3) * 4;
    const int ty = tid >> 4;
    const int tx = tid & 15;

    float acc[8][8];
#pragma unroll
    for (int i = 0; i < 8; i++)
#pragma unroll
        for (int j = 0; j < 8; j++) acc[i][j] = 0.0f;

    for (int k0 = 0; k0 < K; k0 += 16) {
#pragma unroll
        for (int p = 0; p < 2; p++) {
            const int row = lr + p * 64;
            float4 a = *(const float4*)(A + (size_t)(bm + row) * K + k0 + lc);
            float4 b = *(const float4*)(B + (size_t)(bn + row) * K + k0 + lc);
            As[lc + 0][row] = a.x; As[lc + 1][row] = a.y;
            As[lc + 2][row] = a.z; As[lc + 3][row] = a.w;
            Bs[lc + 0][row] = b.x; Bs[lc + 1][row] = b.y;
            Bs[lc + 2][row] = b.z; Bs[lc + 3][row] = b.w;
        }
        __syncthreads();
#pragma unroll
        for (int kk = 0; kk < 16; kk++) {
            float a[8], b[8];
            *(float4*)(a)     = *(const float4*)&As[kk][ty * 8];
            *(float4*)(a + 4) = *(const float4*)&As[kk][ty * 8 + 4];
            *(float4*)(b)     = *(const float4*)&Bs[kk][tx * 8];
            *(float4*)(b + 4) = *(const float4*)&Bs[kk][tx * 8 + 4];
#pragma unroll
            for (int i = 0; i < 8; i++)
#pragma unroll
                for (int j = 0; j < 8; j++)
                    acc[i][j] += a[i] * b[j];
        }
        __syncthreads();
    }

    const int m0 = bm + ty * 8;
    const int n0 = bn + tx * 8;
    float bv[8];
#pragma unroll
    for (int j = 0; j < 8; j++) bv[j] = bias[n0 + j];

#pragma unroll
    for (int i = 0; i < 8; i++) {
        const int m = m0 + i;
        const int s = m & (SMAX - 1);
#pragma unroll
        for (int j = 0; j < 8; j++) {
            const int n = n0 + j;
            float v = acc[i][j] + bv[j];
            if (EPI == EPI_RELU) v = fmaxf(v, 0.0f);
            if (EPI == EPI_RES)  v += res[(size_t)m * N + n];
            if (EPI == EPI_PE) {
                const int de = n & ~1;
                float ang = (float)s * expf((float)de * (-9.210340371976184f / 512.0f));
                v += (n & 1) ? cosf(ang) : sinf(ang);
            }
            C[(size_t)m * N + n] = v;
        }
    }
}

// =============================================================================
// Flash-style tensor-core attention (R6, unchanged).
// =============================================================================
#define ATQ   64
#define APAD  72
#define APLE  (64 * APAD)
#define ATTN_SMEM (6 * APLE * 2)   // 55296 B

__global__ __launch_bounds__(128) void fattn_kernel(
    const float* __restrict__ qkv, const int* __restrict__ lens,
    float* __restrict__ ctx)
{
    extern __shared__ bf16 sa[];
    bf16* sQh = sa;
    bf16* sQl = sa + APLE;
    bf16* sKh = sa + 2 * APLE;
    bf16* sKl = sa + 3 * APLE;
    bf16* sVh = sa + 4 * APLE;   // transposed: [dh][key]
    bf16* sVl = sa + 5 * APLE;

    const int qt = blockIdx.x;
    const int hd = blockIdx.y;
    const int b  = blockIdx.z;
    const int tid  = threadIdx.x;
    const int w    = tid >> 5;
    const int lane = tid & 31;
    const int g    = lane >> 2;
    const int tg   = lane & 3;
    const int len  = lens[b];

    const float* base = qkv + (size_t)b * SMAX * (3 * DMODEL);

#pragma unroll
    for (int p = 0; p < 8; p++) {
        const int cid = p * 128 + tid;
        const int r  = cid >> 4;
        const int c4 = (cid & 15) * 4;
        float4 v = *(const float4*)(base + (size_t)(qt * ATQ + r) * (3 * DMODEL) + hd * DH + c4);
        cvt_store4(sQh + r * APAD + c4, sQl + r * APAD + c4, v);
    }

    float sfr[8][4];
    float ofr[8][4];
#pragma unroll
    for (int j = 0; j < 8; j++)
#pragma unroll
        for (int c = 0; c < 4; c++) ofr[j][c] = 0.0f;
    float m0 = -1e30f, m1 = -1e30f, l0 = 0.0f, l1 = 0.0f;

    const int qrow = w * 16;

    for (int kt = 0; kt < 8; kt++) {
        __syncthreads();
#pragma unroll
        for (int p = 0; p < 8; p++) {
            const int cid = p * 128 + tid;
            const int r  = cid >> 4;
            const int c4 = (cid & 15) * 4;
            const float* rowp = base + (size_t)(kt * 64 + r) * (3 * DMODEL) + hd * DH;
            float4 kv = *(const float4*)(rowp + DMODEL + c4);
            cvt_store4(sKh + r * APAD + c4, sKl + r * APAD + c4, kv);
            float4 vv = *(const float4*)(rowp + 2 * DMODEL + c4);
            float vf[4] = {vv.x, vv.y, vv.z, vv.w};
#pragma unroll
            for (int i = 0; i < 4; i++) {
                bf16 hh, ll;
                split1(vf[i], hh, ll);
                sVh[(c4 + i) * APAD + r] = hh;
                sVl[(c4 + i) * APAD + r] = ll;
            }
        }
        __syncthreads();

#pragma unroll
        for (int j = 0; j < 8; j++)
#pragma unroll
            for (int c = 0; c < 4; c++) sfr[j][c] = 0.0f;

#pragma unroll
        for (int kc = 0; kc < 4; kc++) {
            const int kcol = kc * 16 + 2 * tg;
            uint32_t aQh[4], aQl[4];
            const bf16* q0 = sQh + (qrow + g) * APAD + kcol;
            aQh[0] = ld32(q0);
            aQh[1] = ld32(q0 + 8 * APAD);
            aQh[2] = ld32(q0 + 8);
            aQh[3] = ld32(q0 + 8 * APAD + 8);
            const bf16* q1 = sQl + (qrow + g) * APAD + kcol;
            aQl[0] = ld32(q1);
            aQl[1] = ld32(q1 + 8 * APAD);
            aQl[2] = ld32(q1 + 8);
            aQl[3] = ld32(q1 + 8 * APAD + 8);
#pragma unroll
            for (int j = 0; j < 8; j++) {
                uint32_t bh[2], bl[2];
                const bf16* k0 = sKh + (j * 8 + g) * APAD + kcol;
                bh[0] = ld32(k0); bh[1] = ld32(k0 + 8);
                const bf16* k1 = sKl + (j * 8 + g) * APAD + kcol;
                bl[0] = ld32(k1); bl[1] = ld32(k1 + 8);
                mma16816(sfr[j], aQh, bh);
                mma16816(sfr[j], aQh, bl);
                mma16816(sfr[j], aQl, bh);
            }
        }

        float tmax0 = -1e30f, tmax1 = -1e30f;
#pragma unroll
        for (int j = 0; j < 8; j++) {
            const int col = kt * 64 + j * 8 + 2 * tg;
            const bool v0 = col < len, v1 = (col + 1) < len;
            sfr[j][0] = v0 ? sfr[j][0] * 0.125f : -1e9f;
            sfr[j][1] = v1 ? sfr[j][1] * 0.125f : -1e9f;
            sfr[j][2] = v0 ? sfr[j][2] * 0.125f : -1e9f;
            sfr[j][3] = v1 ? sfr[j][3] * 0.125f : -1e9f;
            tmax0 = fmaxf(tmax0, fmaxf(sfr[j][0], sfr[j][1]));
            tmax1 = fmaxf(tmax1, fmaxf(sfr[j][2], sfr[j][3]));
        }
        tmax0 = fmaxf(tmax0, __shfl_xor_sync(0xffffffffu, tmax0, 1));
        tmax0 = fmaxf(tmax0, __shfl_xor_sync(0xffffffffu, tmax0, 2));
        tmax1 = fmaxf(tmax1, __shfl_xor_sync(0xffffffffu, tmax1, 1));
        tmax1 = fmaxf(tmax1, __shfl_xor_sync(0xffffffffu, tmax1, 2));

        const float nm0 = fmaxf(m0, tmax0), nm1 = fmaxf(m1, tmax1);
        const float al0 = expf(m0 - nm0), al1 = expf(m1 - nm1);
        m0 = nm0; m1 = nm1;

        float rs0 = 0.0f, rs1 = 0.0f;
#pragma unroll
        for (int j = 0; j < 8; j++) {
            sfr[j][0] = expf(sfr[j][0] - nm0);
            sfr[j][1] = expf(sfr[j][1] - nm0);
            sfr[j][2] = expf(sfr[j][2] - nm1);
            sfr[j][3] = expf(sfr[j][3] - nm1);
            rs0 += sfr[j][0] + sfr[j][1];
            rs1 += sfr[j][2] + sfr[j][3];
        }
        rs0 += __shfl_xor_sync(0xffffffffu, rs0, 1);
        rs0 += __shfl_xor_sync(0xffffffffu, rs0, 2);
        rs1 += __shfl_xor_sync(0xffffffffu, rs1, 1);
        rs1 += __shfl_xor_sync(0xffffffffu, rs1, 2);
        l0 = l0 * al0 + rs0;
        l1 = l1 * al1 + rs1;

#pragma unroll
        for (int j = 0; j < 8; j++) {
            ofr[j][0] *= al0; ofr[j][1] *= al0;
            ofr[j][2] *= al1; ofr[j][3] *= al1;
        }

#pragma unroll
        for (int kc = 0; kc < 4; kc++) {
            uint32_t aPh[4], aPl[4];
            packsplit2(sfr[2 * kc][0],     sfr[2 * kc][1],     aPh[0], aPl[0]);
            packsplit2(sfr[2 * kc][2],     sfr[2 * kc][3],     aPh[1], aPl[1]);
            packsplit2(sfr[2 * kc + 1][0], sfr[2 * kc + 1][1], aPh[2], aPl[2]);
            packsplit2(sfr[2 * kc + 1][2], sfr[2 * kc + 1][3], aPh[3], aPl[3]);
            const int kcol = kc * 16 + 2 * tg;
#pragma unroll
            for (int j = 0; j < 8; j++) {
                uint32_t bh[2], bl[2];
                const bf16* v0 = sVh + (j * 8 + g) * APAD + kcol;
                bh[0] = ld32(v0); bh[1] = ld32(v0 + 8);
                const bf16* v1 = sVl + (j * 8 + g) * APAD + kcol;
                bl[0] = ld32(v1); bl[1] = ld32(v1 + 8);
                mma16816(ofr[j], aPh, bh);
                mma16816(ofr[j], aPh, bl);
                mma16816(ofr[j], aPl, bh);
            }
        }
    }

    const float inv0 = 1.0f / l0, inv1 = 1.0f / l1;
    const int q0 = qt * ATQ + qrow + g;
#pragma unroll
    for (int j = 0; j < 8; j++) {
        const int col = hd * DH + j * 8 + 2 * tg;
        float* p0 = ctx + ((size_t)b * SMAX + q0) * DMODEL + col;
        p0[0] = ofr[j][0] * inv0;
        p0[1] = ofr[j][1] * inv0;
        float* p1 = ctx + ((size_t)b * SMAX + q0 + 8) * DMODEL + col;
        p1[0] = ofr[j][2] * inv1;
        p1[1] = ofr[j][3] * inv1;
    }
}

// ---------------- LayerNorm (in place, per token row of 512) ----------------
__global__ __launch_bounds__(128) void ln_kernel(
    float* __restrict__ h, const float* __restrict__ g, const float* __restrict__ bta)
{
    __shared__ float red[8];
    const int row = blockIdx.x;
    const int t = threadIdx.x;
    float* p = h + (size_t)row * DMODEL + t * 4;
    float4 v = *(float4*)p;
    float s  = v.x + v.y + v.z + v.w;
    float ss = v.x * v.x + v.y * v.y + v.z * v.z + v.w * v.w;
#pragma unroll
    for (int o = 16; o; o >>= 1) {
        s  += __shfl_xor_sync(0xffffffffu, s, o);
        ss += __shfl_xor_sync(0xffffffffu, ss, o);
    }
    const int w = t >> 5;
    if ((t & 31) == 0) { red[w] = s; red[4 + w] = ss; }
    __syncthreads();
    s  = red[0] + red[1] + red[2] + red[3];
    ss = red[4] + red[5] + red[6] + red[7];
    const float mean = s * (1.0f / DMODEL);
    const float var  = ss * (1.0f / DMODEL) - mean * mean;
    const float rstd = rsqrtf(var + 1e-5f);
    float4 gg = *(const float4*)(g + t * 4);
    float4 bb = *(const float4*)(bta + t * 4);
    v.x = (v.x - mean) * rstd * gg.x + bb.x;
    v.y = (v.y - mean) * rstd * gg.y + bb.y;
    v.z = (v.z - mean) * rstd * gg.z + bb.z;
    v.w = (v.w - mean) * rstd * gg.w + bb.w;
    *(float4*)p = v;
}

// ---------------- two-phase masked mean pooling ------------------------------
__global__ __launch_bounds__(128) void pool_part_kernel(
    const float* __restrict__ h, const int* __restrict__ lens, float* __restrict__ part)
{
    const int b = blockIdx.x;
    const int ch = blockIdx.y;
    const int d = threadIdx.x * 4;
    const int len = lens[b];
    const int t0 = ch * 64;
    int nt = len - t0;
    if (nt > 64) nt = 64;
    float4 s = {0.f, 0.f, 0.f, 0.f};
    for (int t = 0; t < nt; t++) {
        float4 v = *(const float4*)(h + ((size_t)b * SMAX + t0 + t) * DMODEL + d);
        s.x += v.x; s.y += v.y; s.z += v.z; s.w += v.w;
    }
    *(float4*)(part + (size_t)(b * 8 + ch) * DMODEL + d) = s;
}

__global__ __launch_bounds__(DMODEL) void pool_final_kernel(
    const float* __restrict__ part, const int* __restrict__ lens,
    float* __restrict__ out, int out_size)
{
    const int b = blockIdx.x;
    const int d = threadIdx.x;
    float s = 0.0f;
#pragma unroll
    for (int c = 0; c < 8; c++) s += part[(size_t)(b * 8 + c) * DMODEL + d];
    out[b * DMODEL + d] = s / (float)lens[b];
    if (d == 0 && out_size >= BATCH * DMODEL + BATCH)
        out[BATCH * DMODEL + b] = (float)lens[b];
}

// ---------------- launch ------------------------------------------------------
extern "C" void kernel_launch(void* const* d_in, const int* in_sizes, int n_in,
                              void* d_out, int out_size)
{
    (void)in_sizes; (void)n_in;
    const float* x     = (const float*)d_in[0];
    const int*   lens  = (const int*)  d_in[1];
    const float* We    = (const float*)d_in[2];
    const float* be    = (const float*)d_in[3];
    const float* Wqkv  = (const float*)d_in[4];
    const float* bqkv  = (const float*)d_in[5];
    const float* Wo    = (const float*)d_in[6];
    const float* bo    = (const float*)d_in[7];
    const float* ln1g  = (const float*)d_in[8];
    const float* ln1b  = (const float*)d_in[9];
    const float* W1    = (const float*)d_in[10];
    const float* b1    = (const float*)d_in[11];
    const float* W2    = (const float*)d_in[12];
    const float* b2    = (const float*)d_in[13];
    const float* ln2g  = (const float*)d_in[14];
    const float* ln2b  = (const float*)d_in[15];
    float* out = (float*)d_out;

    void *ph, *pqkv, *pctx, *pff, *ppool;
    cudaGetSymbolAddress(&ph,    g_h);
    cudaGetSymbolAddress(&pqkv,  g_qkv);
    cudaGetSymbolAddress(&pctx,  g_ctx);
    cudaGetSymbolAddress(&pff,   g_ff);
    cudaGetSymbolAddress(&ppool, g_pool);
    float* h    = (float*)ph;
    float* qkv  = (float*)pqkv;
    float* ctx  = (float*)pctx;
    float* ff   = (float*)pff;
    float* pool = (float*)ppool;

    cudaFuncSetAttribute(fattn_kernel,
                         cudaFuncAttributeMaxDynamicSharedMemorySize, ATTN_SMEM);
    cudaFuncSetAttribute(bgemm_kernel<EPI_NONE>,
                         cudaFuncAttributeMaxDynamicSharedMemorySize, GSMEM);
    cudaFuncSetAttribute(bgemm_kernel<EPI_RELU>,
                         cudaFuncAttributeMaxDynamicSharedMemorySize, GSMEM);
    cudaFuncSetAttribute(bgemm_kernel<EPI_RES>,
                         cudaFuncAttributeMaxDynamicSharedMemorySize, GSMEM);

    // embedding + positional encoding (fp32 path): h = x @ We^T + be + PE
    sgemm_kernel<EPI_PE><<<dim3(DMODEL / 128, NTOK / 128), 256>>>(
        x, We, be, nullptr, h, NTOK, DMODEL, INSZ);

    for (int l = 0; l < NLAYERS; l++) {
        const float* wq  = Wqkv + (size_t)l * 3 * DMODEL * DMODEL;
        const float* bq  = bqkv + (size_t)l * 3 * DMODEL;
        const float* wo  = Wo   + (size_t)l * DMODEL * DMODEL;
        const float* bO  = bo   + (size_t)l * DMODEL;
        const float* w1  = W1   + (size_t)l * DFF * DMODEL;
        const float* bf1 = b1   + (size_t)l * DFF;
        const float* w2  = W2   + (size_t)l * DMODEL * DFF;
        const float* bf2 = b2   + (size_t)l * DMODEL;

        // qkv = h @ Wqkv^T + bqkv
        bgemm_kernel<EPI_NONE><<<dim3(3 * DMODEL / 64, NTOK / 128), 256, GSMEM>>>(
            h, wq, bq, nullptr, qkv, NTOK, 3 * DMODEL, DMODEL);

        // attention -> ctx (fp32)
        fattn_kernel<<<dim3(SMAX / ATQ, NHEAD, BATCH), 128, ATTN_SMEM>>>(qkv, lens, ctx);

        // h = h + ctx @ Wo^T + bo
        bgemm_kernel<EPI_RES><<<dim3(DMODEL / 64, NTOK / 128), 256, GSMEM>>>(
            ctx, wo, bO, h, h, NTOK, DMODEL, DMODEL);
        ln_kernel<<<NTOK, 128>>>(h, ln1g + l * DMODEL, ln1b + l * DMODEL);

        // ff = relu(h @ W1^T + b1)
        bgemm_kernel<EPI_RELU><<<dim3(DFF / 64, NTOK / 128), 256, GSMEM>>>(
            h, w1, bf1, nullptr, ff, NTOK, DFF, DMODEL);
        // h = h + ff @ W2^T + b2
        bgemm_kernel<EPI_RES><<<dim3(DMODEL / 64, NTOK / 128), 256, GSMEM>>>(
            ff, w2, bf2, h, h, NTOK, DMODEL, DFF);
        ln_kernel<<<NTOK, 128>>>(h, ln2g + l * DMODEL, ln2b + l * DMODEL);
    }

    pool_part_kernel<<<dim3(BATCH, 8), 128>>>(h, lens, pool);
    pool_final_kernel<<<BATCH, DMODEL>>>(pool, lens, out, out_size);
}

// round 11
// speedup vs baseline: 1.9795x; 1.1334x over previous
#include <cuda_runtime.h>
#include <cuda_bf16.h>
#include <cstdint>

// ---------------- problem constants ----------------
#define NLAYERS 4
#define INSZ    80
#define DMODEL  512
#define NHEAD   8
#define DH      64
#define DFF     2048
#define BATCH   16
#define SMAX    512
#define NTOK    (BATCH * SMAX)   // 8192

typedef __nv_bfloat16 bf16;

// ---------------- scratch (device globals; no allocs allowed) ----------------
__device__ float g_h  [NTOK * DMODEL];       // hidden state (exact fp32)
__device__ float g_ht [NTOK * DMODEL];       // tf32-rounded copy of h (GEMM A input)
__device__ float g_qkv[NTOK * 3 * DMODEL];   // qkv projections (fp32, attention input)
__device__ float g_ctx[NTOK * DMODEL];       // attention context (tf32-rounded)
__device__ float g_ff [NTOK * DFF];          // ff intermediate (tf32-rounded)
__device__ float g_pool[BATCH * 8 * DMODEL]; // pooling partials

// tf32-rounded weight copies
__device__ float g_wq_r[NLAYERS * 3 * DMODEL * DMODEL];
__device__ float g_wo_r[NLAYERS * DMODEL * DMODEL];
__device__ float g_w1_r[NLAYERS * DFF * DMODEL];
__device__ float g_w2_r[NLAYERS * DMODEL * DFF];

enum { EPI_NONE = 0, EPI_PE = 1, EPI_RELU = 2, EPI_RES = 3 };

// ---------------- helpers -----------------------------------------------------
__device__ __forceinline__ void mma16816(float* d, const uint32_t* a, const uint32_t* b) {
    asm volatile(
        "mma.sync.aligned.m16n8k16.row.col.f32.bf16.bf16.f32 "
        "{%0,%1,%2,%3},{%4,%5,%6,%7},{%8,%9},{%0,%1,%2,%3};\n"
        : "+f"(d[0]), "+f"(d[1]), "+f"(d[2]), "+f"(d[3])
        : "r"(a[0]), "r"(a[1]), "r"(a[2]), "r"(a[3]), "r"(b[0]), "r"(b[1]));
}

// tf32 m16n8k8 MMA (fp32 accum); operands pre-rounded fp32 bit-patterns
__device__ __forceinline__ void mma1688(float* d, const uint32_t* a, const uint32_t* b) {
    asm volatile(
        "mma.sync.aligned.m16n8k8.row.col.f32.tf32.tf32.f32 "
        "{%0,%1,%2,%3},{%4,%5,%6,%7},{%8,%9},{%0,%1,%2,%3};\n"
        : "+f"(d[0]), "+f"(d[1]), "+f"(d[2]), "+f"(d[3])
        : "r"(a[0]), "r"(a[1]), "r"(a[2]), "r"(a[3]), "r"(b[0]), "r"(b[1]));
}

__device__ __forceinline__ float roundtf(float f) {
    uint32_t u;
    asm("cvt.rna.tf32.f32 %0, %1;" : "=r"(u) : "f"(f));
    return __uint_as_float(u);
}

__device__ __forceinline__ float4 roundtf4(float4 v) {
    v.x = roundtf(v.x); v.y = roundtf(v.y);
    v.z = roundtf(v.z); v.w = roundtf(v.w);
    return v;
}

__device__ __forceinline__ uint32_t ld32(const bf16* p) {
    return *reinterpret_cast<const uint32_t*>(p);
}

__device__ __forceinline__ void split1(float v, bf16& h, bf16& l) {
    h = __float2bfloat16(v);
    l = __float2bfloat16(v - __bfloat162float(h));
}

__device__ __forceinline__ void cvt_store4(bf16* dh, bf16* dl, float4 v) {
    union { bf16 b[4]; uint2 u; } H, L;
    split1(v.x, H.b[0], L.b[0]);
    split1(v.y, H.b[1], L.b[1]);
    split1(v.z, H.b[2], L.b[2]);
    split1(v.w, H.b[3], L.b[3]);
    *reinterpret_cast<uint2*>(dh) = H.u;
    *reinterpret_cast<uint2*>(dl) = L.u;
}

__device__ __forceinline__ void packsplit2(float x, float y, uint32_t& hi, uint32_t& lo) {
    bf16 hx, lx, hy, ly;
    split1(x, hx, lx);
    split1(y, hy, ly);
    union { bf16 b[2]; uint32_t u; } H, L;
    H.b[0] = hx; H.b[1] = hy;
    L.b[0] = lx; L.b[1] = ly;
    hi = H.u; lo = L.u;
}

__device__ __forceinline__ void cp16(uint32_t saddr, const void* g) {
    asm volatile("cp.async.cg.shared.global [%0], [%1], 16;\n" :: "r"(saddr), "l"(g));
}
__device__ __forceinline__ void cp_commit() { asm volatile("cp.async.commit_group;\n"); }
template <int N>
__device__ __forceinline__ void cp_wait() {
    asm volatile("cp.async.wait_group %0;\n" :: "n"(N));
}

// ---------------- fp32 -> tf32-rounded copy kernel ---------------------------
__global__ __launch_bounds__(256) void round_kernel(
    const float* __restrict__ src, float* __restrict__ dst)
{
    const int i = (blockIdx.x * 256 + threadIdx.x) * 4;
    *(float4*)(dst + i) = roundtf4(*(const float4*)(src + i));
}

// =============================================================================
// TF32 single-pass tensor-core GEMM, cp.async feed, pre-rounded operands:
//   C[M,N] = A[M,K] * B[N,K]^T + bias (+epilogue), fp32 in/out.
// 128x64 CTA tile, 256 threads, warp tile 32x32 (4m x 2n), 2-stage cp.async.
// =============================================================================
#define BK    32
#define LDS36 36
#define APLNW (128 * LDS36)
#define BPLNW (64 * LDS36)
#define BUFW  (APLNW + BPLNW)
#define GSMEM (2 * BUFW * 4)           // 55296 B

template <int EPI>
__global__ __launch_bounds__(256) void bgemm_kernel(
    const float* __restrict__ A, const float* __restrict__ B,
    const float* __restrict__ bias, const float* __restrict__ res,
    float* __restrict__ C, int M, int N, int K)
{
    extern __shared__ uint32_t smu[];
    const uint32_t smbase = (uint32_t)__cvta_generic_to_shared(smu);

    const int tid = threadIdx.x;
    const int bm = blockIdx.y * 128;
    const int bn = blockIdx.x * 64;

    const int wid  = tid >> 5;
    const int wm   = wid & 3;
    const int wn   = wid >> 2;
    const int lane = tid & 31;
    const int g    = lane >> 2;
    const int tg   = lane & 3;

    const int lrow = tid >> 3;
    const int lc4  = (tid & 7) * 4;

    float acc[2][4][4];
#pragma unroll
    for (int i = 0; i < 2; i++)
#pragma unroll
        for (int j = 0; j < 4; j++)
#pragma unroll
            for (int r = 0; r < 4; r++) acc[i][j][r] = 0.0f;

    const int ntile = K / BK;

#define LOAD_TILE(T, BUF)                                                         \
    {                                                                             \
        const int k0 = (T) * BK;                                                  \
        const uint32_t sb = smbase + (BUF) * (BUFW * 4);                          \
        _Pragma("unroll")                                                         \
        for (int p = 0; p < 4; p++) {                                             \
            const int row = lrow + p * 32;                                        \
            cp16(sb + (row * LDS36 + lc4) * 4,                                    \
                 A + (size_t)(bm + row) * K + k0 + lc4);                          \
        }                                                                         \
        _Pragma("unroll")                                                         \
        for (int p = 0; p < 2; p++) {                                             \
            const int row = lrow + p * 32;                                        \
            cp16(sb + (APLNW + row * LDS36 + lc4) * 4,                            \
                 B + (size_t)(bn + row) * K + k0 + lc4);                          \
        }                                                                         \
    }

    LOAD_TILE(0, 0);
    cp_commit();

    for (int t = 0; t < ntile; t++) {
        if (t + 1 < ntile) {
            LOAD_TILE(t + 1, (t + 1) & 1);
            cp_commit();
            cp_wait<1>();
        } else {
            cp_wait<0>();
        }
        __syncthreads();

        const uint32_t* pA = smu + (t & 1) * BUFW;
        const uint32_t* pB = pA + APLNW;

#pragma unroll
        for (int kk = 0; kk < 4; kk++) {
            const int kc = kk * 8 + tg;
            uint32_t a[2][4], b[4][2];
#pragma unroll
            for (int mi = 0; mi < 2; mi++) {
                const int r = wm * 32 + mi * 16 + g;
                a[mi][0] = pA[r * LDS36 + kc];
                a[mi][1] = pA[(r + 8) * LDS36 + kc];
                a[mi][2] = pA[r * LDS36 + kc + 4];
                a[mi][3] = pA[(r + 8) * LDS36 + kc + 4];
            }
#pragma unroll
            for (int ni = 0; ni < 4; ni++) {
                const int r = wn * 32 + ni * 8 + g;
                b[ni][0] = pB[r * LDS36 + kc];
                b[ni][1] = pB[r * LDS36 + kc + 4];
            }
#pragma unroll
            for (int mi = 0; mi < 2; mi++)
#pragma unroll
                for (int ni = 0; ni < 4; ni++)
                    mma1688(acc[mi][ni], a[mi], b[ni]);
        }
        __syncthreads();
    }
#undef LOAD_TILE

    // ---- epilogue ----
#pragma unroll
    for (int mi = 0; mi < 2; mi++) {
#pragma unroll
        for (int ni = 0; ni < 4; ni++) {
            const int m = bm + wm * 32 + mi * 16 + g;
            const int n = bn + wn * 32 + ni * 8 + tg * 2;
            const float b0 = bias[n], b1 = bias[n + 1];
#pragma unroll
            for (int h = 0; h < 2; h++) {
                const int mm = m + h * 8;
                float v0 = acc[mi][ni][h * 2 + 0] + b0;
                float v1 = acc[mi][ni][h * 2 + 1] + b1;
                if (EPI == EPI_RELU) {
                    // output feeds next tf32 GEMM only -> store rounded
                    v0 = roundtf(fmaxf(v0, 0.0f));
                    v1 = roundtf(fmaxf(v1, 0.0f));
                }
                if (EPI == EPI_RES) {
                    const float* rp = res + (size_t)mm * N + n;
                    v0 += rp[0]; v1 += rp[1];
                }
                float* cp = C + (size_t)mm * N + n;
                cp[0] = v0; cp[1] = v1;
            }
        }
    }
}

// ---------------- fp32 SGEMM (embed, K=80), writes h exact + h_t rounded -----
__global__ __launch_bounds__(256) void embed_kernel(
    const float* __restrict__ A, const float* __restrict__ B,
    const float* __restrict__ bias,
    float* __restrict__ C, float* __restrict__ Ct, int M, int N, int K)
{
    __shared__ float As[16][132];
    __shared__ float Bs[16][132];

    const int tid = threadIdx.x;
    const int bm = blockIdx.y * 128;
    const int bn = blockIdx.x * 128;

    const int lr = tid >> 2;
    const int lc = (tid & 3) * 4;
    const int ty = tid >> 4;
    const int tx = tid & 15;

    float acc[8][8];
#pragma unroll
    for (int i = 0; i < 8; i++)
#pragma unroll
        for (int j = 0; j < 8; j++) acc[i][j] = 0.0f;

    for (int k0 = 0; k0 < K; k0 += 16) {
#pragma unroll
        for (int p = 0; p < 2; p++) {
            const int row = lr + p * 64;
            float4 a = *(const float4*)(A + (size_t)(bm + row) * K + k0 + lc);
            float4 b = *(const float4*)(B + (size_t)(bn + row) * K + k0 + lc);
            As[lc + 0][row] = a.x; As[lc + 1][row] = a.y;
            As[lc + 2][row] = a.z; As[lc + 3][row] = a.w;
            Bs[lc + 0][row] = b.x; Bs[lc + 1][row] = b.y;
            Bs[lc + 2][row] = b.z; Bs[lc + 3][row] = b.w;
        }
        __syncthreads();
#pragma unroll
        for (int kk = 0; kk < 16; kk++) {
            float a[8], b[8];
            *(float4*)(a)     = *(const float4*)&As[kk][ty * 8];
            *(float4*)(a + 4) = *(const float4*)&As[kk][ty * 8 + 4];
            *(float4*)(b)     = *(const float4*)&Bs[kk][tx * 8];
            *(float4*)(b + 4) = *(const float4*)&Bs[kk][tx * 8 + 4];
#pragma unroll
            for (int i = 0; i < 8; i++)
#pragma unroll
                for (int j = 0; j < 8; j++)
                    acc[i][j] += a[i] * b[j];
        }
        __syncthreads();
    }

    const int m0 = bm + ty * 8;
    const int n0 = bn + tx * 8;
    float bv[8];
#pragma unroll
    for (int j = 0; j < 8; j++) bv[j] = bias[n0 + j];

#pragma unroll
    for (int i = 0; i < 8; i++) {
        const int m = m0 + i;
        const int s = m & (SMAX - 1);
#pragma unroll
        for (int j = 0; j < 8; j++) {
            const int n = n0 + j;
            float v = acc[i][j] + bv[j];
            const int de = n & ~1;
            float ang = (float)s * expf((float)de * (-9.210340371976184f / 512.0f));
            v += (n & 1) ? cosf(ang) : sinf(ang);
            const size_t ix = (size_t)m * N + n;
            C[ix]  = v;
            Ct[ix] = roundtf(v);
        }
    }
}

// =============================================================================
// Flash-style tensor-core attention (R6 core); writes ctx tf32-rounded.
// =============================================================================
#define ATQ   64
#define APAD  72
#define APLE  (64 * APAD)
#define ATTN_SMEM (6 * APLE * 2)   // 55296 B

__global__ __launch_bounds__(128) void fattn_kernel(
    const float* __restrict__ qkv, const int* __restrict__ lens,
    float* __restrict__ ctx)
{
    extern __shared__ bf16 sa[];
    bf16* sQh = sa;
    bf16* sQl = sa + APLE;
    bf16* sKh = sa + 2 * APLE;
    bf16* sKl = sa + 3 * APLE;
    bf16* sVh = sa + 4 * APLE;   // transposed: [dh][key]
    bf16* sVl = sa + 5 * APLE;

    const int qt = blockIdx.x;
    const int hd = blockIdx.y;
    const int b  = blockIdx.z;
    const int tid  = threadIdx.x;
    const int w    = tid >> 5;
    const int lane = tid & 31;
    const int g    = lane >> 2;
    const int tg   = lane & 3;
    const int len  = lens[b];

    const float* base = qkv + (size_t)b * SMAX * (3 * DMODEL);

#pragma unroll
    for (int p = 0; p < 8; p++) {
        const int cid = p * 128 + tid;
        const int r  = cid >> 4;
        const int c4 = (cid & 15) * 4;
        float4 v = *(const float4*)(base + (size_t)(qt * ATQ + r) * (3 * DMODEL) + hd * DH + c4);
        cvt_store4(sQh + r * APAD + c4, sQl + r * APAD + c4, v);
    }

    float sfr[8][4];
    float ofr[8][4];
#pragma unroll
    for (int j = 0; j < 8; j++)
#pragma unroll
        for (int c = 0; c < 4; c++) ofr[j][c] = 0.0f;
    float m0 = -1e30f, m1 = -1e30f, l0 = 0.0f, l1 = 0.0f;

    const int qrow = w * 16;

    for (int kt = 0; kt < 8; kt++) {
        __syncthreads();
#pragma unroll
        for (int p = 0; p < 8; p++) {
            const int cid = p * 128 + tid;
            const int r  = cid >> 4;
            const int c4 = (cid & 15) * 4;
            const float* rowp = base + (size_t)(kt * 64 + r) * (3 * DMODEL) + hd * DH;
            float4 kv = *(const float4*)(rowp + DMODEL + c4);
            cvt_store4(sKh + r * APAD + c4, sKl + r * APAD + c4, kv);
            float4 vv = *(const float4*)(rowp + 2 * DMODEL + c4);
            float vf[4] = {vv.x, vv.y, vv.z, vv.w};
#pragma unroll
            for (int i = 0; i < 4; i++) {
                bf16 hh, ll;
                split1(vf[i], hh, ll);
                sVh[(c4 + i) * APAD + r] = hh;
                sVl[(c4 + i) * APAD + r] = ll;
            }
        }
        __syncthreads();

#pragma unroll
        for (int j = 0; j < 8; j++)
#pragma unroll
            for (int c = 0; c < 4; c++) sfr[j][c] = 0.0f;

#pragma unroll
        for (int kc = 0; kc < 4; kc++) {
            const int kcol = kc * 16 + 2 * tg;
            uint32_t aQh[4], aQl[4];
            const bf16* q0 = sQh + (qrow + g) * APAD + kcol;
            aQh[0] = ld32(q0);
            aQh[1] = ld32(q0 + 8 * APAD);
            aQh[2] = ld32(q0 + 8);
            aQh[3] = ld32(q0 + 8 * APAD + 8);
            const bf16* q1 = sQl + (qrow + g) * APAD + kcol;
            aQl[0] = ld32(q1);
            aQl[1] = ld32(q1 + 8 * APAD);
            aQl[2] = ld32(q1 + 8);
            aQl[3] = ld32(q1 + 8 * APAD + 8);
#pragma unroll
            for (int j = 0; j < 8; j++) {
                uint32_t bh[2], bl[2];
                const bf16* k0 = sKh + (j * 8 + g) * APAD + kcol;
                bh[0] = ld32(k0); bh[1] = ld32(k0 + 8);
                const bf16* k1 = sKl + (j * 8 + g) * APAD + kcol;
                bl[0] = ld32(k1); bl[1] = ld32(k1 + 8);
                mma16816(sfr[j], aQh, bh);
                mma16816(sfr[j], aQh, bl);
                mma16816(sfr[j], aQl, bh);
            }
        }

        float tmax0 = -1e30f, tmax1 = -1e30f;
#pragma unroll
        for (int j = 0; j < 8; j++) {
            const int col = kt * 64 + j * 8 + 2 * tg;
            const bool v0 = col < len, v1 = (col + 1) < len;
            sfr[j][0] = v0 ? sfr[j][0] * 0.125f : -1e9f;
            sfr[j][1] = v1 ? sfr[j][1] * 0.125f : -1e9f;
            sfr[j][2] = v0 ? sfr[j][2] * 0.125f : -1e9f;
            sfr[j][3] = v1 ? sfr[j][3] * 0.125f : -1e9f;
            tmax0 = fmaxf(tmax0, fmaxf(sfr[j][0], sfr[j][1]));
            tmax1 = fmaxf(tmax1, fmaxf(sfr[j][2], sfr[j][3]));
        }
        tmax0 = fmaxf(tmax0, __shfl_xor_sync(0xffffffffu, tmax0, 1));
        tmax0 = fmaxf(tmax0, __shfl_xor_sync(0xffffffffu, tmax0, 2));
        tmax1 = fmaxf(tmax1, __shfl_xor_sync(0xffffffffu, tmax1, 1));
        tmax1 = fmaxf(tmax1, __shfl_xor_sync(0xffffffffu, tmax1, 2));

        const float nm0 = fmaxf(m0, tmax0), nm1 = fmaxf(m1, tmax1);
        const float al0 = expf(m0 - nm0), al1 = expf(m1 - nm1);
        m0 = nm0; m1 = nm1;

        float rs0 = 0.0f, rs1 = 0.0f;
#pragma unroll
        for (int j = 0; j < 8; j++) {
            sfr[j][0] = expf(sfr[j][0] - nm0);
            sfr[j][1] = expf(sfr[j][1] - nm0);
            sfr[j][2] = expf(sfr[j][2] - nm1);
            sfr[j][3] = expf(sfr[j][3] - nm1);
            rs0 += sfr[j][0] + sfr[j][1];
            rs1 += sfr[j][2] + sfr[j][3];
        }
        rs0 += __shfl_xor_sync(0xffffffffu, rs0, 1);
        rs0 += __shfl_xor_sync(0xffffffffu, rs0, 2);
        rs1 += __shfl_xor_sync(0xffffffffu, rs1, 1);
        rs1 += __shfl_xor_sync(0xffffffffu, rs1, 2);
        l0 = l0 * al0 + rs0;
        l1 = l1 * al1 + rs1;

#pragma unroll
        for (int j = 0; j < 8; j++) {
            ofr[j][0] *= al0; ofr[j][1] *= al0;
            ofr[j][2] *= al1; ofr[j][3] *= al1;
        }

#pragma unroll
        for (int kc = 0; kc < 4; kc++) {
            uint32_t aPh[4], aPl[4];
            packsplit2(sfr[2 * kc][0],     sfr[2 * kc][1],     aPh[0], aPl[0]);
            packsplit2(sfr[2 * kc][2],     sfr[2 * kc][3],     aPh[1], aPl[1]);
            packsplit2(sfr[2 * kc + 1][0], sfr[2 * kc + 1][1], aPh[2], aPl[2]);
            packsplit2(sfr[2 * kc + 1][2], sfr[2 * kc + 1][3], aPh[3], aPl[3]);
            const int kcol = kc * 16 + 2 * tg;
#pragma unroll
            for (int j = 0; j < 8; j++) {
                uint32_t bh[2], bl[2];
                const bf16* v0 = sVh + (j * 8 + g) * APAD + kcol;
                bh[0] = ld32(v0); bh[1] = ld32(v0 + 8);
                const bf16* v1 = sVl + (j * 8 + g) * APAD + kcol;
                bl[0] = ld32(v1); bl[1] = ld32(v1 + 8);
                mma16816(ofr[j], aPh, bh);
                mma16816(ofr[j], aPh, bl);
                mma16816(ofr[j], aPl, bh);
            }
        }
    }

    const float inv0 = 1.0f / l0, inv1 = 1.0f / l1;
    const int q0 = qt * ATQ + qrow + g;
#pragma unroll
    for (int j = 0; j < 8; j++) {
        const int col = hd * DH + j * 8 + 2 * tg;
        float* p0 = ctx + ((size_t)b * SMAX + q0) * DMODEL + col;
        p0[0] = roundtf(ofr[j][0] * inv0);
        p0[1] = roundtf(ofr[j][1] * inv0);
        float* p1 = ctx + ((size_t)b * SMAX + q0 + 8) * DMODEL + col;
        p1[0] = roundtf(ofr[j][2] * inv1);
        p1[1] = roundtf(ofr[j][3] * inv1);
    }
}

// ---------------- LayerNorm (in place) + rounded copy -------------------------
__global__ __launch_bounds__(128) void ln_kernel(
    float* __restrict__ h, const float* __restrict__ g, const float* __restrict__ bta,
    float* __restrict__ ht)
{
    __shared__ float red[8];
    const int row = blockIdx.x;
    const int t = threadIdx.x;
    float* p = h + (size_t)row * DMODEL + t * 4;
    float4 v = *(float4*)p;
    float s  = v.x + v.y + v.z + v.w;
    float ss = v.x * v.x + v.y * v.y + v.z * v.z + v.w * v.w;
#pragma unroll
    for (int o = 16; o; o >>= 1) {
        s  += __shfl_xor_sync(0xffffffffu, s, o);
        ss += __shfl_xor_sync(0xffffffffu, ss, o);
    }
    const int w = t >> 5;
    if ((t & 31) == 0) { red[w] = s; red[4 + w] = ss; }
    __syncthreads();
    s  = red[0] + red[1] + red[2] + red[3];
    ss = red[4] + red[5] + red[6] + red[7];
    const float mean = s * (1.0f / DMODEL);
    const float var  = ss * (1.0f / DMODEL) - mean * mean;
    const float rstd = rsqrtf(var + 1e-5f);
    float4 gg = *(const float4*)(g + t * 4);
    float4 bb = *(const float4*)(bta + t * 4);
    v.x = (v.x - mean) * rstd * gg.x + bb.x;
    v.y = (v.y - mean) * rstd * gg.y + bb.y;
    v.z = (v.z - mean) * rstd * gg.z + bb.z;
    v.w = (v.w - mean) * rstd * gg.w + bb.w;
    *(float4*)p = v;
    *(float4*)(ht + (size_t)row * DMODEL + t * 4) = roundtf4(v);
}

// ---------------- two-phase masked mean pooling ------------------------------
__global__ __launch_bounds__(128) void pool_part_kernel(
    const float* __restrict__ h, const int* __restrict__ lens, float* __restrict__ part)
{
    const int b = blockIdx.x;
    const int ch = blockIdx.y;
    const int d = threadIdx.x * 4;
    const int len = lens[b];
    const int t0 = ch * 64;
    int nt = len - t0;
    if (nt > 64) nt = 64;
    float4 s = {0.f, 0.f, 0.f, 0.f};
    for (int t = 0; t < nt; t++) {
        float4 v = *(const float4*)(h + ((size_t)b * SMAX + t0 + t) * DMODEL + d);
        s.x += v.x; s.y += v.y; s.z += v.z; s.w += v.w;
    }
    *(float4*)(part + (size_t)(b * 8 + ch) * DMODEL + d) = s;
}

__global__ __launch_bounds__(DMODEL) void pool_final_kernel(
    const float* __restrict__ part, const int* __restrict__ lens,
    float* __restrict__ out, int out_size)
{
    const int b = blockIdx.x;
    const int d = threadIdx.x;
    float s = 0.0f;
#pragma unroll
    for (int c = 0; c < 8; c++) s += part[(size_t)(b * 8 + c) * DMODEL + d];
    out[b * DMODEL + d] = s / (float)lens[b];
    if (d == 0 && out_size >= BATCH * DMODEL + BATCH)
        out[BATCH * DMODEL + b] = (float)lens[b];
}

// ---------------- launch ------------------------------------------------------
extern "C" void kernel_launch(void* const* d_in, const int* in_sizes, int n_in,
                              void* d_out, int out_size)
{
    (void)in_sizes; (void)n_in;
    const float* x     = (const float*)d_in[0];
    const int*   lens  = (const int*)  d_in[1];
    const float* We    = (const float*)d_in[2];
    const float* be    = (const float*)d_in[3];
    const float* Wqkv  = (const float*)d_in[4];
    const float* bqkv  = (const float*)d_in[5];
    const float* Wo    = (const float*)d_in[6];
    const float* bo    = (const float*)d_in[7];
    const float* ln1g  = (const float*)d_in[8];
    const float* ln1b  = (const float*)d_in[9];
    const float* W1    = (const float*)d_in[10];
    const float* b1    = (const float*)d_in[11];
    const float* W2    = (const float*)d_in[12];
    const float* b2    = (const float*)d_in[13];
    const float* ln2g  = (const float*)d_in[14];
    const float* ln2b  = (const float*)d_in[15];
    float* out = (float*)d_out;

    void *ph, *pht, *pqkv, *pctx, *pff, *ppool;
    void *pwq, *pwo, *pw1, *pw2;
    cudaGetSymbolAddress(&ph,    g_h);
    cudaGetSymbolAddress(&pht,   g_ht);
    cudaGetSymbolAddress(&pqkv,  g_qkv);
    cudaGetSymbolAddress(&pctx,  g_ctx);
    cudaGetSymbolAddress(&pff,   g_ff);
    cudaGetSymbolAddress(&ppool, g_pool);
    cudaGetSymbolAddress(&pwq,   g_wq_r);
    cudaGetSymbolAddress(&pwo,   g_wo_r);
    cudaGetSymbolAddress(&pw1,   g_w1_r);
    cudaGetSymbolAddress(&pw2,   g_w2_r);
    float* h    = (float*)ph;
    float* ht   = (float*)pht;
    float* qkv  = (float*)pqkv;
    float* ctx  = (float*)pctx;
    float* ff   = (float*)pff;
    float* pool = (float*)ppool;
    float* wq_r = (float*)pwq;
    float* wo_r = (float*)pwo;
    float* w1_r = (float*)pw1;
    float* w2_r = (float*)pw2;

    cudaFuncSetAttribute(fattn_kernel,
                         cudaFuncAttributeMaxDynamicSharedMemorySize, ATTN_SMEM);
    cudaFuncSetAttribute(bgemm_kernel<EPI_NONE>,
                         cudaFuncAttributeMaxDynamicSharedMemorySize, GSMEM);
    cudaFuncSetAttribute(bgemm_kernel<EPI_RELU>,
                         cudaFuncAttributeMaxDynamicSharedMemorySize, GSMEM);
    cudaFuncSetAttribute(bgemm_kernel<EPI_RES>,
                         cudaFuncAttributeMaxDynamicSharedMemorySize, GSMEM);

    // ---- round weights to tf32 (once per launch) ----
    round_kernel<<<NLAYERS * 3 * DMODEL * DMODEL / 1024, 256>>>(Wqkv, wq_r);
    round_kernel<<<NLAYERS * DMODEL * DMODEL / 1024, 256>>>(Wo, wo_r);
    round_kernel<<<NLAYERS * DFF * DMODEL / 1024, 256>>>(W1, w1_r);
    round_kernel<<<NLAYERS * DMODEL * DFF / 1024, 256>>>(W2, w2_r);

    // embedding + positional encoding: h (exact) + ht (rounded)
    embed_kernel<<<dim3(DMODEL / 128, NTOK / 128), 256>>>(
        x, We, be, h, ht, NTOK, DMODEL, INSZ);

    for (int l = 0; l < NLAYERS; l++) {
        const float* wq  = wq_r + (size_t)l * 3 * DMODEL * DMODEL;
        const float* bq  = bqkv + (size_t)l * 3 * DMODEL;
        const float* wo  = wo_r + (size_t)l * DMODEL * DMODEL;
        const float* bO  = bo   + (size_t)l * DMODEL;
        const float* w1  = w1_r + (size_t)l * DFF * DMODEL;
        const float* bf1 = b1   + (size_t)l * DFF;
        const float* w2  = w2_r + (size_t)l * DMODEL * DFF;
        const float* bf2 = b2   + (size_t)l * DMODEL;

        // qkv = ht @ wq^T + bq  (fp32 out, feeds attention)
        bgemm_kernel<EPI_NONE><<<dim3(3 * DMODEL / 64, NTOK / 128), 256, GSMEM>>>(
            ht, wq, bq, nullptr, qkv, NTOK, 3 * DMODEL, DMODEL);

        // attention -> ctx (tf32-rounded)
        fattn_kernel<<<dim3(SMAX / ATQ, NHEAD, BATCH), 128, ATTN_SMEM>>>(qkv, lens, ctx);

        // h = h + ctx @ wo^T + bo
        bgemm_kernel<EPI_RES><<<dim3(DMODEL / 64, NTOK / 128), 256, GSMEM>>>(
            ctx, wo, bO, h, h, NTOK, DMODEL, DMODEL);
        ln_kernel<<<NTOK, 128>>>(h, ln1g + l * DMODEL, ln1b + l * DMODEL, ht);

        // ff = round(relu(ht @ w1^T + b1))
        bgemm_kernel<EPI_RELU><<<dim3(DFF / 64, NTOK / 128), 256, GSMEM>>>(
            ht, w1, bf1, nullptr, ff, NTOK, DFF, DMODEL);
        // h = h + ff @ w2^T + b2
        bgemm_kernel<EPI_RES><<<dim3(DMODEL / 64, NTOK / 128), 256, GSMEM>>>(
            ff, w2, bf2, h, h, NTOK, DMODEL, DFF);
        ln_kernel<<<NTOK, 128>>>(h, ln2g + l * DMODEL, ln2b + l * DMODEL, ht);
    }

    pool_part_kernel<<<dim3(BATCH, 8), 128>>>(h, lens, pool);
    pool_final_kernel<<<BATCH, DMODEL>>>(pool, lens, out, out_size);
}

// round 12
// speedup vs baseline: 2.1728x; 1.0977x over previous
#include <cuda_runtime.h>
#include <cuda_bf16.h>
#include <cstdint>

// ---------------- problem constants ----------------
#define NLAYERS 4
#define INSZ    80
#define DMODEL  512
#define NHEAD   8
#define DH      64
#define DFF     2048
#define BATCH   16
#define SMAX    512
#define NTOK    (BATCH * SMAX)   // 8192

typedef __nv_bfloat16 bf16;

// ---------------- scratch (device globals; no allocs allowed) ----------------
__device__ float g_h  [NTOK * DMODEL];       // hidden state (exact fp32)
__device__ float g_ht [NTOK * DMODEL];       // tf32-rounded copy of h (GEMM A input)
__device__ float g_qkv[NTOK * 3 * DMODEL];   // qkv projections (fp32, attention input)
__device__ float g_ctx[NTOK * DMODEL];       // attention context (tf32-rounded)
__device__ float g_ff [NTOK * DFF];          // ff intermediate (tf32-rounded)
__device__ float g_pool[BATCH * 8 * DMODEL]; // pooling partials

// tf32-rounded weight copies
__device__ float g_wq_r[NLAYERS * 3 * DMODEL * DMODEL];
__device__ float g_wo_r[NLAYERS * DMODEL * DMODEL];
__device__ float g_w1_r[NLAYERS * DFF * DMODEL];
__device__ float g_w2_r[NLAYERS * DMODEL * DFF];

enum { EPI_NONE = 0, EPI_PE = 1, EPI_RELU = 2, EPI_RES = 3 };

// ---------------- helpers -----------------------------------------------------
__device__ __forceinline__ void mma16816(float* d, const uint32_t* a, const uint32_t* b) {
    asm volatile(
        "mma.sync.aligned.m16n8k16.row.col.f32.bf16.bf16.f32 "
        "{%0,%1,%2,%3},{%4,%5,%6,%7},{%8,%9},{%0,%1,%2,%3};\n"
        : "+f"(d[0]), "+f"(d[1]), "+f"(d[2]), "+f"(d[3])
        : "r"(a[0]), "r"(a[1]), "r"(a[2]), "r"(a[3]), "r"(b[0]), "r"(b[1]));
}

// tf32 m16n8k8 MMA (fp32 accum); operands pre-rounded fp32 bit-patterns
__device__ __forceinline__ void mma1688(float* d, const uint32_t* a, const uint32_t* b) {
    asm volatile(
        "mma.sync.aligned.m16n8k8.row.col.f32.tf32.tf32.f32 "
        "{%0,%1,%2,%3},{%4,%5,%6,%7},{%8,%9},{%0,%1,%2,%3};\n"
        : "+f"(d[0]), "+f"(d[1]), "+f"(d[2]), "+f"(d[3])
        : "r"(a[0]), "r"(a[1]), "r"(a[2]), "r"(a[3]), "r"(b[0]), "r"(b[1]));
}

__device__ __forceinline__ float roundtf(float f) {
    uint32_t u;
    asm("cvt.rna.tf32.f32 %0, %1;" : "=r"(u) : "f"(f));
    return __uint_as_float(u);
}

__device__ __forceinline__ float4 roundtf4(float4 v) {
    v.x = roundtf(v.x); v.y = roundtf(v.y);
    v.z = roundtf(v.z); v.w = roundtf(v.w);
    return v;
}

__device__ __forceinline__ uint32_t ld32(const bf16* p) {
    return *reinterpret_cast<const uint32_t*>(p);
}

__device__ __forceinline__ void split1(float v, bf16& h, bf16& l) {
    h = __float2bfloat16(v);
    l = __float2bfloat16(v - __bfloat162float(h));
}

__device__ __forceinline__ void cvt_store4(bf16* dh, bf16* dl, float4 v) {
    union { bf16 b[4]; uint2 u; } H, L;
    split1(v.x, H.b[0], L.b[0]);
    split1(v.y, H.b[1], L.b[1]);
    split1(v.z, H.b[2], L.b[2]);
    split1(v.w, H.b[3], L.b[3]);
    *reinterpret_cast<uint2*>(dh) = H.u;
    *reinterpret_cast<uint2*>(dl) = L.u;
}

__device__ __forceinline__ void packsplit2(float x, float y, uint32_t& hi, uint32_t& lo) {
    bf16 hx, lx, hy, ly;
    split1(x, hx, lx);
    split1(y, hy, ly);
    union { bf16 b[2]; uint32_t u; } H, L;
    H.b[0] = hx; H.b[1] = hy;
    L.b[0] = lx; L.b[1] = ly;
    hi = H.u; lo = L.u;
}

__device__ __forceinline__ void cp16(uint32_t saddr, const void* g) {
    asm volatile("cp.async.cg.shared.global [%0], [%1], 16;\n" :: "r"(saddr), "l"(g));
}
__device__ __forceinline__ void cp_commit() { asm volatile("cp.async.commit_group;\n"); }
template <int N>
__device__ __forceinline__ void cp_wait() {
    asm volatile("cp.async.wait_group %0;\n" :: "n"(N));
}

// ---------------- fp32 -> tf32-rounded copy kernel ---------------------------
__global__ __launch_bounds__(256) void round_kernel(
    const float* __restrict__ src, float* __restrict__ dst)
{
    const int i = (blockIdx.x * 256 + threadIdx.x) * 4;
    *(float4*)(dst + i) = roundtf4(*(const float4*)(src + i));
}

// =============================================================================
// TF32 single-pass tensor-core GEMM, cp.async feed, pre-rounded operands:
//   C[M,N] = A[M,K] * B[N,K]^T + bias (+epilogue), fp32 in/out.
// 128x128 CTA tile, 256 threads, warp tile 32x64 (4m x 2n), 2-stage cp.async.
// =============================================================================
#define BK    32
#define LDS36 36
#define APLNW (128 * LDS36)
#define BPLNW (128 * LDS36)
#define BUFW  (APLNW + BPLNW)
#define GSMEM (2 * BUFW * 4)           // 73728 B

template <int EPI>
__global__ __launch_bounds__(256, 2) void bgemm_kernel(
    const float* __restrict__ A, const float* __restrict__ B,
    const float* __restrict__ bias, const float* __restrict__ res,
    float* __restrict__ C, int M, int N, int K)
{
    extern __shared__ uint32_t smu[];
    const uint32_t smbase = (uint32_t)__cvta_generic_to_shared(smu);

    const int tid = threadIdx.x;
    const int bm = blockIdx.y * 128;
    const int bn = blockIdx.x * 128;

    const int wid  = tid >> 5;
    const int wm   = wid & 3;       // 32-row quarter
    const int wn   = wid >> 2;      // 64-col half
    const int lane = tid & 31;
    const int g    = lane >> 2;
    const int tg   = lane & 3;

    const int lrow = tid >> 3;           // 0..31 (+32 per p)
    const int lc4  = (tid & 7) * 4;      // word col

    float acc[2][8][4];
#pragma unroll
    for (int i = 0; i < 2; i++)
#pragma unroll
        for (int j = 0; j < 8; j++)
#pragma unroll
            for (int r = 0; r < 4; r++) acc[i][j][r] = 0.0f;

    const int ntile = K / BK;

#define LOAD_TILE(T, BUF)                                                         \
    {                                                                             \
        const int k0 = (T) * BK;                                                  \
        const uint32_t sb = smbase + (BUF) * (BUFW * 4);                          \
        _Pragma("unroll")                                                         \
        for (int p = 0; p < 4; p++) {                                             \
            const int row = lrow + p * 32;                                        \
            cp16(sb + (row * LDS36 + lc4) * 4,                                    \
                 A + (size_t)(bm + row) * K + k0 + lc4);                          \
            cp16(sb + (APLNW + row * LDS36 + lc4) * 4,                            \
                 B + (size_t)(bn + row) * K + k0 + lc4);                          \
        }                                                                         \
    }

    LOAD_TILE(0, 0);
    cp_commit();

    for (int t = 0; t < ntile; t++) {
        if (t + 1 < ntile) {
            LOAD_TILE(t + 1, (t + 1) & 1);
            cp_commit();
            cp_wait<1>();
        } else {
            cp_wait<0>();
        }
        __syncthreads();

        const uint32_t* pA = smu + (t & 1) * BUFW;
        const uint32_t* pB = pA + APLNW;

#pragma unroll
        for (int kk = 0; kk < 4; kk++) {
            const int kc = kk * 8 + tg;
            uint32_t a[2][4], b[8][2];
#pragma unroll
            for (int mi = 0; mi < 2; mi++) {
                const int r = wm * 32 + mi * 16 + g;
                a[mi][0] = pA[r * LDS36 + kc];
                a[mi][1] = pA[(r + 8) * LDS36 + kc];
                a[mi][2] = pA[r * LDS36 + kc + 4];
                a[mi][3] = pA[(r + 8) * LDS36 + kc + 4];
            }
#pragma unroll
            for (int ni = 0; ni < 8; ni++) {
                const int r = wn * 64 + ni * 8 + g;
                b[ni][0] = pB[r * LDS36 + kc];
                b[ni][1] = pB[r * LDS36 + kc + 4];
            }
#pragma unroll
            for (int mi = 0; mi < 2; mi++)
#pragma unroll
                for (int ni = 0; ni < 8; ni++)
                    mma1688(acc[mi][ni], a[mi], b[ni]);
        }
        __syncthreads();
    }
#undef LOAD_TILE

    // ---- epilogue ----
#pragma unroll
    for (int mi = 0; mi < 2; mi++) {
#pragma unroll
        for (int ni = 0; ni < 8; ni++) {
            const int m = bm + wm * 32 + mi * 16 + g;
            const int n = bn + wn * 64 + ni * 8 + tg * 2;
            const float b0 = bias[n], b1 = bias[n + 1];
#pragma unroll
            for (int h = 0; h < 2; h++) {
                const int mm = m + h * 8;
                float v0 = acc[mi][ni][h * 2 + 0] + b0;
                float v1 = acc[mi][ni][h * 2 + 1] + b1;
                if (EPI == EPI_RELU) {
                    v0 = roundtf(fmaxf(v0, 0.0f));
                    v1 = roundtf(fmaxf(v1, 0.0f));
                }
                if (EPI == EPI_RES) {
                    const float* rp = res + (size_t)mm * N + n;
                    v0 += rp[0]; v1 += rp[1];
                }
                float* cp = C + (size_t)mm * N + n;
                cp[0] = v0; cp[1] = v1;
            }
        }
    }
}

// ---------------- fp32 SGEMM (embed, K=80), writes h exact + h_t rounded -----
__global__ __launch_bounds__(256) void embed_kernel(
    const float* __restrict__ A, const float* __restrict__ B,
    const float* __restrict__ bias,
    float* __restrict__ C, float* __restrict__ Ct, int M, int N, int K)
{
    __shared__ float As[16][132];
    __shared__ float Bs[16][132];

    const int tid = threadIdx.x;
    const int bm = blockIdx.y * 128;
    const int bn = blockIdx.x * 128;

    const int lr = tid >> 2;
    const int lc = (tid & 3) * 4;
    const int ty = tid >> 4;
    const int tx = tid & 15;

    float acc[8][8];
#pragma unroll
    for (int i = 0; i < 8; i++)
#pragma unroll
        for (int j = 0; j < 8; j++) acc[i][j] = 0.0f;

    for (int k0 = 0; k0 < K; k0 += 16) {
#pragma unroll
        for (int p = 0; p < 2; p++) {
            const int row = lr + p * 64;
            float4 a = *(const float4*)(A + (size_t)(bm + row) * K + k0 + lc);
            float4 b = *(const float4*)(B + (size_t)(bn + row) * K + k0 + lc);
            As[lc + 0][row] = a.x; As[lc + 1][row] = a.y;
            As[lc + 2][row] = a.z; As[lc + 3][row] = a.w;
            Bs[lc + 0][row] = b.x; Bs[lc + 1][row] = b.y;
            Bs[lc + 2][row] = b.z; Bs[lc + 3][row] = b.w;
        }
        __syncthreads();
#pragma unroll
        for (int kk = 0; kk < 16; kk++) {
            float a[8], b[8];
            *(float4*)(a)     = *(const float4*)&As[kk][ty * 8];
            *(float4*)(a + 4) = *(const float4*)&As[kk][ty * 8 + 4];
            *(float4*)(b)     = *(const float4*)&Bs[kk][tx * 8];
            *(float4*)(b + 4) = *(const float4*)&Bs[kk][tx * 8 + 4];
#pragma unroll
            for (int i = 0; i < 8; i++)
#pragma unroll
                for (int j = 0; j < 8; j++)
                    acc[i][j] += a[i] * b[j];
        }
        __syncthreads();
    }

    const int m0 = bm + ty * 8;
    const int n0 = bn + tx * 8;
    float bv[8];
#pragma unroll
    for (int j = 0; j < 8; j++) bv[j] = bias[n0 + j];

#pragma unroll
    for (int i = 0; i < 8; i++) {
        const int m = m0 + i;
        const int s = m & (SMAX - 1);
#pragma unroll
        for (int j = 0; j < 8; j++) {
            const int n = n0 + j;
            float v = acc[i][j] + bv[j];
            const int de = n & ~1;
            float ang = (float)s * expf((float)de * (-9.210340371976184f / 512.0f));
            v += (n & 1) ? cosf(ang) : sinf(ang);
            const size_t ix = (size_t)m * N + n;
            C[ix]  = v;
            Ct[ix] = roundtf(v);
        }
    }
}

// =============================================================================
// Flash-style tensor-core attention (R6 core); writes ctx tf32-rounded.
// =============================================================================
#define ATQ   64
#define APAD  72
#define APLE  (64 * APAD)
#define ATTN_SMEM (6 * APLE * 2)   // 55296 B

__global__ __launch_bounds__(128) void fattn_kernel(
    const float* __restrict__ qkv, const int* __restrict__ lens,
    float* __restrict__ ctx)
{
    extern __shared__ bf16 sa[];
    bf16* sQh = sa;
    bf16* sQl = sa + APLE;
    bf16* sKh = sa + 2 * APLE;
    bf16* sKl = sa + 3 * APLE;
    bf16* sVh = sa + 4 * APLE;   // transposed: [dh][key]
    bf16* sVl = sa + 5 * APLE;

    const int qt = blockIdx.x;
    const int hd = blockIdx.y;
    const int b  = blockIdx.z;
    const int tid  = threadIdx.x;
    const int w    = tid >> 5;
    const int lane = tid & 31;
    const int g    = lane >> 2;
    const int tg   = lane & 3;
    const int len  = lens[b];

    const float* base = qkv + (size_t)b * SMAX * (3 * DMODEL);

#pragma unroll
    for (int p = 0; p < 8; p++) {
        const int cid = p * 128 + tid;
        const int r  = cid >> 4;
        const int c4 = (cid & 15) * 4;
        float4 v = *(const float4*)(base + (size_t)(qt * ATQ + r) * (3 * DMODEL) + hd * DH + c4);
        cvt_store4(sQh + r * APAD + c4, sQl + r * APAD + c4, v);
    }

    float sfr[8][4];
    float ofr[8][4];
#pragma unroll
    for (int j = 0; j < 8; j++)
#pragma unroll
        for (int c = 0; c < 4; c++) ofr[j][c] = 0.0f;
    float m0 = -1e30f, m1 = -1e30f, l0 = 0.0f, l1 = 0.0f;

    const int qrow = w * 16;

    for (int kt = 0; kt < 8; kt++) {
        __syncthreads();
#pragma unroll
        for (int p = 0; p < 8; p++) {
            const int cid = p * 128 + tid;
            const int r  = cid >> 4;
            const int c4 = (cid & 15) * 4;
            const float* rowp = base + (size_t)(kt * 64 + r) * (3 * DMODEL) + hd * DH;
            float4 kv = *(const float4*)(rowp + DMODEL + c4);
            cvt_store4(sKh + r * APAD + c4, sKl + r * APAD + c4, kv);
            float4 vv = *(const float4*)(rowp + 2 * DMODEL + c4);
            float vf[4] = {vv.x, vv.y, vv.z, vv.w};
#pragma unroll
            for (int i = 0; i < 4; i++) {
                bf16 hh, ll;
                split1(vf[i], hh, ll);
                sVh[(c4 + i) * APAD + r] = hh;
                sVl[(c4 + i) * APAD + r] = ll;
            }
        }
        __syncthreads();

#pragma unroll
        for (int j = 0; j < 8; j++)
#pragma unroll
            for (int c = 0; c < 4; c++) sfr[j][c] = 0.0f;

#pragma unroll
        for (int kc = 0; kc < 4; kc++) {
            const int kcol = kc * 16 + 2 * tg;
            uint32_t aQh[4], aQl[4];
            const bf16* q0 = sQh + (qrow + g) * APAD + kcol;
            aQh[0] = ld32(q0);
            aQh[1] = ld32(q0 + 8 * APAD);
            aQh[2] = ld32(q0 + 8);
            aQh[3] = ld32(q0 + 8 * APAD + 8);
            const bf16* q1 = sQl + (qrow + g) * APAD + kcol;
            aQl[0] = ld32(q1);
            aQl[1] = ld32(q1 + 8 * APAD);
            aQl[2] = ld32(q1 + 8);
            aQl[3] = ld32(q1 + 8 * APAD + 8);
#pragma unroll
            for (int j = 0; j < 8; j++) {
                uint32_t bh[2], bl[2];
                const bf16* k0 = sKh + (j * 8 + g) * APAD + kcol;
                bh[0] = ld32(k0); bh[1] = ld32(k0 + 8);
                const bf16* k1 = sKl + (j * 8 + g) * APAD + kcol;
                bl[0] = ld32(k1); bl[1] = ld32(k1 + 8);
                mma16816(sfr[j], aQh, bh);
                mma16816(sfr[j], aQh, bl);
                mma16816(sfr[j], aQl, bh);
            }
        }

        float tmax0 = -1e30f, tmax1 = -1e30f;
#pragma unroll
        for (int j = 0; j < 8; j++) {
            const int col = kt * 64 + j * 8 + 2 * tg;
            const bool v0 = col < len, v1 = (col + 1) < len;
            sfr[j][0] = v0 ? sfr[j][0] * 0.125f : -1e9f;
            sfr[j][1] = v1 ? sfr[j][1] * 0.125f : -1e9f;
            sfr[j][2] = v0 ? sfr[j][2] * 0.125f : -1e9f;
            sfr[j][3] = v1 ? sfr[j][3] * 0.125f : -1e9f;
            tmax0 = fmaxf(tmax0, fmaxf(sfr[j][0], sfr[j][1]));
            tmax1 = fmaxf(tmax1, fmaxf(sfr[j][2], sfr[j][3]));
        }
        tmax0 = fmaxf(tmax0, __shfl_xor_sync(0xffffffffu, tmax0, 1));
        tmax0 = fmaxf(tmax0, __shfl_xor_sync(0xffffffffu, tmax0, 2));
        tmax1 = fmaxf(tmax1, __shfl_xor_sync(0xffffffffu, tmax1, 1));
        tmax1 = fmaxf(tmax1, __shfl_xor_sync(0xffffffffu, tmax1, 2));

        const float nm0 = fmaxf(m0, tmax0), nm1 = fmaxf(m1, tmax1);
        const float al0 = expf(m0 - nm0), al1 = expf(m1 - nm1);
        m0 = nm0; m1 = nm1;

        float rs0 = 0.0f, rs1 = 0.0f;
#pragma unroll
        for (int j = 0; j < 8; j++) {
            sfr[j][0] = expf(sfr[j][0] - nm0);
            sfr[j][1] = expf(sfr[j][1] - nm0);
            sfr[j][2] = expf(sfr[j][2] - nm1);
            sfr[j][3] = expf(sfr[j][3] - nm1);
            rs0 += sfr[j][0] + sfr[j][1];
            rs1 += sfr[j][2] + sfr[j][3];
        }
        rs0 += __shfl_xor_sync(0xffffffffu, rs0, 1);
        rs0 += __shfl_xor_sync(0xffffffffu, rs0, 2);
        rs1 += __shfl_xor_sync(0xffffffffu, rs1, 1);
        rs1 += __shfl_xor_sync(0xffffffffu, rs1, 2);
        l0 = l0 * al0 + rs0;
        l1 = l1 * al1 + rs1;

#pragma unroll
        for (int j = 0; j < 8; j++) {
            ofr[j][0] *= al0; ofr[j][1] *= al0;
            ofr[j][2] *= al1; ofr[j][3] *= al1;
        }

#pragma unroll
        for (int kc = 0; kc < 4; kc++) {
            uint32_t aPh[4], aPl[4];
            packsplit2(sfr[2 * kc][0],     sfr[2 * kc][1],     aPh[0], aPl[0]);
            packsplit2(sfr[2 * kc][2],     sfr[2 * kc][3],     aPh[1], aPl[1]);
            packsplit2(sfr[2 * kc + 1][0], sfr[2 * kc + 1][1], aPh[2], aPl[2]);
            packsplit2(sfr[2 * kc + 1][2], sfr[2 * kc + 1][3], aPh[3], aPl[3]);
            const int kcol = kc * 16 + 2 * tg;
#pragma unroll
            for (int j = 0; j < 8; j++) {
                uint32_t bh[2], bl[2];
                const bf16* v0 = sVh + (j * 8 + g) * APAD + kcol;
                bh[0] = ld32(v0); bh[1] = ld32(v0 + 8);
                const bf16* v1 = sVl + (j * 8 + g) * APAD + kcol;
                bl[0] = ld32(v1); bl[1] = ld32(v1 + 8);
                mma16816(ofr[j], aPh, bh);
                mma16816(ofr[j], aPh, bl);
                mma16816(ofr[j], aPl, bh);
            }
        }
    }

    const float inv0 = 1.0f / l0, inv1 = 1.0f / l1;
    const int q0 = qt * ATQ + qrow + g;
#pragma unroll
    for (int j = 0; j < 8; j++) {
        const int col = hd * DH + j * 8 + 2 * tg;
        float* p0 = ctx + ((size_t)b * SMAX + q0) * DMODEL + col;
        p0[0] = roundtf(ofr[j][0] * inv0);
        p0[1] = roundtf(ofr[j][1] * inv0);
        float* p1 = ctx + ((size_t)b * SMAX + q0 + 8) * DMODEL + col;
        p1[0] = roundtf(ofr[j][2] * inv1);
        p1[1] = roundtf(ofr[j][3] * inv1);
    }
}

// ---------------- LayerNorm (in place) + rounded copy -------------------------
__global__ __launch_bounds__(128) void ln_kernel(
    float* __restrict__ h, const float* __restrict__ g, const float* __restrict__ bta,
    float* __restrict__ ht)
{
    __shared__ float red[8];
    const int row = blockIdx.x;
    const int t = threadIdx.x;
    float* p = h + (size_t)row * DMODEL + t * 4;
    float4 v = *(float4*)p;
    float s  = v.x + v.y + v.z + v.w;
    float ss = v.x * v.x + v.y * v.y + v.z * v.z + v.w * v.w;
#pragma unroll
    for (int o = 16; o; o >>= 1) {
        s  += __shfl_xor_sync(0xffffffffu, s, o);
        ss += __shfl_xor_sync(0xffffffffu, ss, o);
    }
    const int w = t >> 5;
    if ((t & 31) == 0) { red[w] = s; red[4 + w] = ss; }
    __syncthreads();
    s  = red[0] + red[1] + red[2] + red[3];
    ss = red[4] + red[5] + red[6] + red[7];
    const float mean = s * (1.0f / DMODEL);
    const float var  = ss * (1.0f / DMODEL) - mean * mean;
    const float rstd = rsqrtf(var + 1e-5f);
    float4 gg = *(const float4*)(g + t * 4);
    float4 bb = *(const float4*)(bta + t * 4);
    v.x = (v.x - mean) * rstd * gg.x + bb.x;
    v.y = (v.y - mean) * rstd * gg.y + bb.y;
    v.z = (v.z - mean) * rstd * gg.z + bb.z;
    v.w = (v.w - mean) * rstd * gg.w + bb.w;
    *(float4*)p = v;
    *(float4*)(ht + (size_t)row * DMODEL + t * 4) = roundtf4(v);
}

// ---------------- two-phase masked mean pooling ------------------------------
__global__ __launch_bounds__(128) void pool_part_kernel(
    const float* __restrict__ h, const int* __restrict__ lens, float* __restrict__ part)
{
    const int b = blockIdx.x;
    const int ch = blockIdx.y;
    const int d = threadIdx.x * 4;
    const int len = lens[b];
    const int t0 = ch * 64;
    int nt = len - t0;
    if (nt > 64) nt = 64;
    float4 s = {0.f, 0.f, 0.f, 0.f};
    for (int t = 0; t < nt; t++) {
        float4 v = *(const float4*)(h + ((size_t)b * SMAX + t0 + t) * DMODEL + d);
        s.x += v.x; s.y += v.y; s.z += v.z; s.w += v.w;
    }
    *(float4*)(part + (size_t)(b * 8 + ch) * DMODEL + d) = s;
}

__global__ __launch_bounds__(DMODEL) void pool_final_kernel(
    const float* __restrict__ part, const int* __restrict__ lens,
    float* __restrict__ out, int out_size)
{
    const int b = blockIdx.x;
    const int d = threadIdx.x;
    float s = 0.0f;
#pragma unroll
    for (int c = 0; c < 8; c++) s += part[(size_t)(b * 8 + c) * DMODEL + d];
    out[b * DMODEL + d] = s / (float)lens[b];
    if (d == 0 && out_size >= BATCH * DMODEL + BATCH)
        out[BATCH * DMODEL + b] = (float)lens[b];
}

// ---------------- launch ------------------------------------------------------
extern "C" void kernel_launch(void* const* d_in, const int* in_sizes, int n_in,
                              void* d_out, int out_size)
{
    (void)in_sizes; (void)n_in;
    const float* x     = (const float*)d_in[0];
    const int*   lens  = (const int*)  d_in[1];
    const float* We    = (const float*)d_in[2];
    const float* be    = (const float*)d_in[3];
    const float* Wqkv  = (const float*)d_in[4];
    const float* bqkv  = (const float*)d_in[5];
    const float* Wo    = (const float*)d_in[6];
    const float* bo    = (const float*)d_in[7];
    const float* ln1g  = (const float*)d_in[8];
    const float* ln1b  = (const float*)d_in[9];
    const float* W1    = (const float*)d_in[10];
    const float* b1    = (const float*)d_in[11];
    const float* W2    = (const float*)d_in[12];
    const float* b2    = (const float*)d_in[13];
    const float* ln2g  = (const float*)d_in[14];
    const float* ln2b  = (const float*)d_in[15];
    float* out = (float*)d_out;

    void *ph, *pht, *pqkv, *pctx, *pff, *ppool;
    void *pwq, *pwo, *pw1, *pw2;
    cudaGetSymbolAddress(&ph,    g_h);
    cudaGetSymbolAddress(&pht,   g_ht);
    cudaGetSymbolAddress(&pqkv,  g_qkv);
    cudaGetSymbolAddress(&pctx,  g_ctx);
    cudaGetSymbolAddress(&pff,   g_ff);
    cudaGetSymbolAddress(&ppool, g_pool);
    cudaGetSymbolAddress(&pwq,   g_wq_r);
    cudaGetSymbolAddress(&pwo,   g_wo_r);
    cudaGetSymbolAddress(&pw1,   g_w1_r);
    cudaGetSymbolAddress(&pw2,   g_w2_r);
    float* h    = (float*)ph;
    float* ht   = (float*)pht;
    float* qkv  = (float*)pqkv;
    float* ctx  = (float*)pctx;
    float* ff   = (float*)pff;
    float* pool = (float*)ppool;
    float* wq_r = (float*)pwq;
    float* wo_r = (float*)pwo;
    float* w1_r = (float*)pw1;
    float* w2_r = (float*)pw2;

    cudaFuncSetAttribute(fattn_kernel,
                         cudaFuncAttributeMaxDynamicSharedMemorySize, ATTN_SMEM);
    cudaFuncSetAttribute(bgemm_kernel<EPI_NONE>,
                         cudaFuncAttributeMaxDynamicSharedMemorySize, GSMEM);
    cudaFuncSetAttribute(bgemm_kernel<EPI_RELU>,
                         cudaFuncAttributeMaxDynamicSharedMemorySize, GSMEM);
    cudaFuncSetAttribute(bgemm_kernel<EPI_RES>,
                         cudaFuncAttributeMaxDynamicSharedMemorySize, GSMEM);

    // ---- round weights to tf32 (once per launch) ----
    round_kernel<<<NLAYERS * 3 * DMODEL * DMODEL / 1024, 256>>>(Wqkv, wq_r);
    round_kernel<<<NLAYERS * DMODEL * DMODEL / 1024, 256>>>(Wo, wo_r);
    round_kernel<<<NLAYERS * DFF * DMODEL / 1024, 256>>>(W1, w1_r);
    round_kernel<<<NLAYERS * DMODEL * DFF / 1024, 256>>>(W2, w2_r);

    // embedding + positional encoding: h (exact) + ht (rounded)
    embed_kernel<<<dim3(DMODEL / 128, NTOK / 128), 256>>>(
        x, We, be, h, ht, NTOK, DMODEL, INSZ);

    for (int l = 0; l < NLAYERS; l++) {
        const float* wq  = wq_r + (size_t)l * 3 * DMODEL * DMODEL;
        const float* bq  = bqkv + (size_t)l * 3 * DMODEL;
        const float* wo  = wo_r + (size_t)l * DMODEL * DMODEL;
        const float* bO  = bo   + (size_t)l * DMODEL;
        const float* w1  = w1_r + (size_t)l * DFF * DMODEL;
        const float* bf1 = b1   + (size_t)l * DFF;
        const float* w2  = w2_r + (size_t)l * DMODEL * DFF;
        const float* bf2 = b2   + (size_t)l * DMODEL;

        // qkv = ht @ wq^T + bq
        bgemm_kernel<EPI_NONE><<<dim3(3 * DMODEL / 128, NTOK / 128), 256, GSMEM>>>(
            ht, wq, bq, nullptr, qkv, NTOK, 3 * DMODEL, DMODEL);

        // attention -> ctx (tf32-rounded)
        fattn_kernel<<<dim3(SMAX / ATQ, NHEAD, BATCH), 128, ATTN_SMEM>>>(qkv, lens, ctx);

        // h = h + ctx @ wo^T + bo
        bgemm_kernel<EPI_RES><<<dim3(DMODEL / 128, NTOK / 128), 256, GSMEM>>>(
            ctx, wo, bO, h, h, NTOK, DMODEL, DMODEL);
        ln_kernel<<<NTOK, 128>>>(h, ln1g + l * DMODEL, ln1b + l * DMODEL, ht);

        // ff = round(relu(ht @ w1^T + b1))
        bgemm_kernel<EPI_RELU><<<dim3(DFF / 128, NTOK / 128), 256, GSMEM>>>(
            ht, w1, bf1, nullptr, ff, NTOK, DFF, DMODEL);
        // h = h + ff @ w2^T + b2
        bgemm_kernel<EPI_RES><<<dim3(DMODEL / 128, NTOK / 128), 256, GSMEM>>>(
            ff, w2, bf2, h, h, NTOK, DMODEL, DFF);
        ln_kernel<<<NTOK, 128>>>(h, ln2g + l * DMODEL, ln2b + l * DMODEL, ht);
    }

    pool_part_kernel<<<dim3(BATCH, 8), 128>>>(h, lens, pool);
    pool_final_kernel<<<BATCH, DMODEL>>>(pool, lens, out, out_size);
}

// round 13
// speedup vs baseline: 2.1871x; 1.0065x over previous
#include <cuda_runtime.h>
#include <cuda_bf16.h>
#include <cstdint>

// ---------------- problem constants ----------------
#define NLAYERS 4
#define INSZ    80
#define DMODEL  512
#define NHEAD   8
#define DH      64
#define DFF     2048
#define BATCH   16
#define SMAX    512
#define NTOK    (BATCH * SMAX)   // 8192

typedef __nv_bfloat16 bf16;

// ---------------- scratch (device globals; no allocs allowed) ----------------
__device__ float g_h  [NTOK * DMODEL];       // hidden state (exact fp32)
__device__ float g_ht [NTOK * DMODEL];       // tf32-rounded copy of h
__device__ float g_qkv[NTOK * 3 * DMODEL];   // qkv projections (fp32)
__device__ float g_ctx[NTOK * DMODEL];       // attention context (tf32-rounded)
__device__ float g_ff [NTOK * DFF];          // ff intermediate (tf32-rounded)
__device__ float g_pool[BATCH * 8 * DMODEL]; // pooling partials

// tf32-rounded weight copies
__device__ float g_wq_r[NLAYERS * 3 * DMODEL * DMODEL];
__device__ float g_wo_r[NLAYERS * DMODEL * DMODEL];
__device__ float g_w1_r[NLAYERS * DFF * DMODEL];
__device__ float g_w2_r[NLAYERS * DMODEL * DFF];

enum { EPI_NONE = 0, EPI_PE = 1, EPI_RELU = 2, EPI_RES = 3 };

// ---------------- helpers -----------------------------------------------------
__device__ __forceinline__ void mma16816(float* d, const uint32_t* a, const uint32_t* b) {
    asm volatile(
        "mma.sync.aligned.m16n8k16.row.col.f32.bf16.bf16.f32 "
        "{%0,%1,%2,%3},{%4,%5,%6,%7},{%8,%9},{%0,%1,%2,%3};\n"
        : "+f"(d[0]), "+f"(d[1]), "+f"(d[2]), "+f"(d[3])
        : "r"(a[0]), "r"(a[1]), "r"(a[2]), "r"(a[3]), "r"(b[0]), "r"(b[1]));
}

// tf32 m16n8k8 MMA (fp32 accum); operands pre-rounded fp32 bit-patterns
__device__ __forceinline__ void mma1688(float* d, const uint32_t* a, const uint32_t* b) {
    asm volatile(
        "mma.sync.aligned.m16n8k8.row.col.f32.tf32.tf32.f32 "
        "{%0,%1,%2,%3},{%4,%5,%6,%7},{%8,%9},{%0,%1,%2,%3};\n"
        : "+f"(d[0]), "+f"(d[1]), "+f"(d[2]), "+f"(d[3])
        : "r"(a[0]), "r"(a[1]), "r"(a[2]), "r"(a[3]), "r"(b[0]), "r"(b[1]));
}

__device__ __forceinline__ float roundtf(float f) {
    uint32_t u;
    asm("cvt.rna.tf32.f32 %0, %1;" : "=r"(u) : "f"(f));
    return __uint_as_float(u);
}

__device__ __forceinline__ float4 roundtf4(float4 v) {
    v.x = roundtf(v.x); v.y = roundtf(v.y);
    v.z = roundtf(v.z); v.w = roundtf(v.w);
    return v;
}

__device__ __forceinline__ uint32_t ld32(const bf16* p) {
    return *reinterpret_cast<const uint32_t*>(p);
}

__device__ __forceinline__ void split1(float v, bf16& h, bf16& l) {
    h = __float2bfloat16(v);
    l = __float2bfloat16(v - __bfloat162float(h));
}

__device__ __forceinline__ void cvt_store4(bf16* dh, bf16* dl, float4 v) {
    union { bf16 b[4]; uint2 u; } H, L;
    split1(v.x, H.b[0], L.b[0]);
    split1(v.y, H.b[1], L.b[1]);
    split1(v.z, H.b[2], L.b[2]);
    split1(v.w, H.b[3], L.b[3]);
    *reinterpret_cast<uint2*>(dh) = H.u;
    *reinterpret_cast<uint2*>(dl) = L.u;
}

__device__ __forceinline__ void packsplit2(float x, float y, uint32_t& hi, uint32_t& lo) {
    bf16 hx, lx, hy, ly;
    split1(x, hx, lx);
    split1(y, hy, ly);
    union { bf16 b[2]; uint32_t u; } H, L;
    H.b[0] = hx; H.b[1] = hy;
    L.b[0] = lx; L.b[1] = ly;
    hi = H.u; lo = L.u;
}

__device__ __forceinline__ void cp16(uint32_t saddr, const void* g) {
    asm volatile("cp.async.cg.shared.global [%0], [%1], 16;\n" :: "r"(saddr), "l"(g));
}
__device__ __forceinline__ void cp_commit() { asm volatile("cp.async.commit_group;\n"); }
template <int N>
__device__ __forceinline__ void cp_wait() {
    asm volatile("cp.async.wait_group %0;\n" :: "n"(N));
}

// ---------------- fp32 -> tf32-rounded copy kernel ---------------------------
__global__ __launch_bounds__(256) void round_kernel(
    const float* __restrict__ src, float* __restrict__ dst)
{
    const int i = (blockIdx.x * 256 + threadIdx.x) * 4;
    *(float4*)(dst + i) = roundtf4(*(const float4*)(src + i));
}

// =============================================================================
// TF32 single-pass tensor-core GEMM, 3-stage cp.async, pre-rounded operands:
//   C[M,N] = A[M,K] * B[N,K]^T + bias (+epilogue), fp32 in/out.
// 128x128 CTA tile, 256 threads, warp tile 32x64 (4m x 2n).
// ONE __syncthreads per K-tile (3 stages make the write-after-read hazard
// structurally impossible within one iteration).
// =============================================================================
#define BK    32
#define LDS36 36
#define APLNW (128 * LDS36)
#define BPLNW (128 * LDS36)
#define BUFW  (APLNW + BPLNW)
#define NSTG  3
#define GSMEM (NSTG * BUFW * 4)        // 110592 B

template <int EPI>
__global__ __launch_bounds__(256, 2) void bgemm_kernel(
    const float* __restrict__ A, const float* __restrict__ B,
    const float* __restrict__ bias, const float* __restrict__ res,
    float* __restrict__ C, int M, int N, int K)
{
    extern __shared__ uint32_t smu[];
    const uint32_t smbase = (uint32_t)__cvta_generic_to_shared(smu);

    const int tid = threadIdx.x;
    const int bm = blockIdx.y * 128;
    const int bn = blockIdx.x * 128;

    const int wid  = tid >> 5;
    const int wm   = wid & 3;       // 32-row quarter
    const int wn   = wid >> 2;      // 64-col half
    const int lane = tid & 31;
    const int g    = lane >> 2;
    const int tg   = lane & 3;

    const int lrow = tid >> 3;           // 0..31 (+32 per p)
    const int lc4  = (tid & 7) * 4;      // word col

    float acc[2][8][4];
#pragma unroll
    for (int i = 0; i < 2; i++)
#pragma unroll
        for (int j = 0; j < 8; j++)
#pragma unroll
            for (int r = 0; r < 4; r++) acc[i][j][r] = 0.0f;

    const int ntile = K / BK;

#define LOAD_TILE(T, STG)                                                         \
    {                                                                             \
        const int k0 = (T) * BK;                                                  \
        const uint32_t sb = smbase + (STG) * (BUFW * 4);                          \
        _Pragma("unroll")                                                         \
        for (int p = 0; p < 4; p++) {                                             \
            const int row = lrow + p * 32;                                        \
            cp16(sb + (row * LDS36 + lc4) * 4,                                    \
                 A + (size_t)(bm + row) * K + k0 + lc4);                          \
            cp16(sb + (APLNW + row * LDS36 + lc4) * 4,                            \
                 B + (size_t)(bn + row) * K + k0 + lc4);                          \
        }                                                                         \
    }

    LOAD_TILE(0, 0); cp_commit();
    LOAD_TILE(1, 1); cp_commit();

    int stg = 0;
    for (int t = 0; t < ntile; t++) {
        if (t + 1 < ntile) cp_wait<1>(); else cp_wait<0>();
        __syncthreads();

        // stage (t+2)%3 == stage (t-1)%3: all warps finished computing it
        // before this barrier, so the overwrite is safe.
        if (t + 2 < ntile) {
            const int s2 = (stg + 2) % NSTG;
            LOAD_TILE(t + 2, s2);
            cp_commit();
        }

        const uint32_t* pA = smu + stg * BUFW;
        const uint32_t* pB = pA + APLNW;

#pragma unroll
        for (int kk = 0; kk < 4; kk++) {
            const int kc = kk * 8 + tg;
            uint32_t a[2][4], b[8][2];
#pragma unroll
            for (int mi = 0; mi < 2; mi++) {
                const int r = wm * 32 + mi * 16 + g;
                a[mi][0] = pA[r * LDS36 + kc];
                a[mi][1] = pA[(r + 8) * LDS36 + kc];
                a[mi][2] = pA[r * LDS36 + kc + 4];
                a[mi][3] = pA[(r + 8) * LDS36 + kc + 4];
            }
#pragma unroll
            for (int ni = 0; ni < 8; ni++) {
                const int r = wn * 64 + ni * 8 + g;
                b[ni][0] = pB[r * LDS36 + kc];
                b[ni][1] = pB[r * LDS36 + kc + 4];
            }
#pragma unroll
            for (int mi = 0; mi < 2; mi++)
#pragma unroll
                for (int ni = 0; ni < 8; ni++)
                    mma1688(acc[mi][ni], a[mi], b[ni]);
        }
        stg = (stg + 1) % NSTG;
    }
#undef LOAD_TILE

    // ---- epilogue ----
#pragma unroll
    for (int mi = 0; mi < 2; mi++) {
#pragma unroll
        for (int ni = 0; ni < 8; ni++) {
            const int m = bm + wm * 32 + mi * 16 + g;
            const int n = bn + wn * 64 + ni * 8 + tg * 2;
            const float b0 = bias[n], b1 = bias[n + 1];
#pragma unroll
            for (int h = 0; h < 2; h++) {
                const int mm = m + h * 8;
                float v0 = acc[mi][ni][h * 2 + 0] + b0;
                float v1 = acc[mi][ni][h * 2 + 1] + b1;
                if (EPI == EPI_RELU) {
                    v0 = roundtf(fmaxf(v0, 0.0f));
                    v1 = roundtf(fmaxf(v1, 0.0f));
                }
                if (EPI == EPI_RES) {
                    const float* rp = res + (size_t)mm * N + n;
                    v0 += rp[0]; v1 += rp[1];
                }
                float* cp = C + (size_t)mm * N + n;
                cp[0] = v0; cp[1] = v1;
            }
        }
    }
}

// ---------------- fp32 SGEMM (embed, K=80), writes h exact + h_t rounded -----
__global__ __launch_bounds__(256) void embed_kernel(
    const float* __restrict__ A, const float* __restrict__ B,
    const float* __restrict__ bias,
    float* __restrict__ C, float* __restrict__ Ct, int M, int N, int K)
{
    __shared__ float As[16][132];
    __shared__ float Bs[16][132];

    const int tid = threadIdx.x;
    const int bm = blockIdx.y * 128;
    const int bn = blockIdx.x * 128;

    const int lr = tid >> 2;
    const int lc = (tid & 3) * 4;
    const int ty = tid >> 4;
    const int tx = tid & 15;

    float acc[8][8];
#pragma unroll
    for (int i = 0; i < 8; i++)
#pragma unroll
        for (int j = 0; j < 8; j++) acc[i][j] = 0.0f;

    for (int k0 = 0; k0 < K; k0 += 16) {
#pragma unroll
        for (int p = 0; p < 2; p++) {
            const int row = lr + p * 64;
            float4 a = *(const float4*)(A + (size_t)(bm + row) * K + k0 + lc);
            float4 b = *(const float4*)(B + (size_t)(bn + row) * K + k0 + lc);
            As[lc + 0][row] = a.x; As[lc + 1][row] = a.y;
            As[lc + 2][row] = a.z; As[lc + 3][row] = a.w;
            Bs[lc + 0][row] = b.x; Bs[lc + 1][row] = b.y;
            Bs[lc + 2][row] = b.z; Bs[lc + 3][row] = b.w;
        }
        __syncthreads();
#pragma unroll
        for (int kk = 0; kk < 16; kk++) {
            float a[8], b[8];
            *(float4*)(a)     = *(const float4*)&As[kk][ty * 8];
            *(float4*)(a + 4) = *(const float4*)&As[kk][ty * 8 + 4];
            *(float4*)(b)     = *(const float4*)&Bs[kk][tx * 8];
            *(float4*)(b + 4) = *(const float4*)&Bs[kk][tx * 8 + 4];
#pragma unroll
            for (int i = 0; i < 8; i++)
#pragma unroll
                for (int j = 0; j < 8; j++)
                    acc[i][j] += a[i] * b[j];
        }
        __syncthreads();
    }

    const int m0 = bm + ty * 8;
    const int n0 = bn + tx * 8;
    float bv[8];
#pragma unroll
    for (int j = 0; j < 8; j++) bv[j] = bias[n0 + j];

#pragma unroll
    for (int i = 0; i < 8; i++) {
        const int m = m0 + i;
        const int s = m & (SMAX - 1);
#pragma unroll
        for (int j = 0; j < 8; j++) {
            const int n = n0 + j;
            float v = acc[i][j] + bv[j];
            const int de = n & ~1;
            float ang = (float)s * expf((float)de * (-9.210340371976184f / 512.0f));
            v += (n & 1) ? cosf(ang) : sinf(ang);
            const size_t ix = (size_t)m * N + n;
            C[ix]  = v;
            Ct[ix] = roundtf(v);
        }
    }
}

// =============================================================================
// Flash-style tensor-core attention (R6 core); writes ctx tf32-rounded.
// =============================================================================
#define ATQ   64
#define APAD  72
#define APLE  (64 * APAD)
#define ATTN_SMEM (6 * APLE * 2)   // 55296 B

__global__ __launch_bounds__(128) void fattn_kernel(
    const float* __restrict__ qkv, const int* __restrict__ lens,
    float* __restrict__ ctx)
{
    extern __shared__ bf16 sa[];
    bf16* sQh = sa;
    bf16* sQl = sa + APLE;
    bf16* sKh = sa + 2 * APLE;
    bf16* sKl = sa + 3 * APLE;
    bf16* sVh = sa + 4 * APLE;   // transposed: [dh][key]
    bf16* sVl = sa + 5 * APLE;

    const int qt = blockIdx.x;
    const int hd = blockIdx.y;
    const int b  = blockIdx.z;
    const int tid  = threadIdx.x;
    const int w    = tid >> 5;
    const int lane = tid & 31;
    const int g    = lane >> 2;
    const int tg   = lane & 3;
    const int len  = lens[b];

    const float* base = qkv + (size_t)b * SMAX * (3 * DMODEL);

#pragma unroll
    for (int p = 0; p < 8; p++) {
        const int cid = p * 128 + tid;
        const int r  = cid >> 4;
        const int c4 = (cid & 15) * 4;
        float4 v = *(const float4*)(base + (size_t)(qt * ATQ + r) * (3 * DMODEL) + hd * DH + c4);
        cvt_store4(sQh + r * APAD + c4, sQl + r * APAD + c4, v);
    }

    float sfr[8][4];
    float ofr[8][4];
#pragma unroll
    for (int j = 0; j < 8; j++)
#pragma unroll
        for (int c = 0; c < 4; c++) ofr[j][c] = 0.0f;
    float m0 = -1e30f, m1 = -1e30f, l0 = 0.0f, l1 = 0.0f;

    const int qrow = w * 16;

    for (int kt = 0; kt < 8; kt++) {
        __syncthreads();
#pragma unroll
        for (int p = 0; p < 8; p++) {
            const int cid = p * 128 + tid;
            const int r  = cid >> 4;
            const int c4 = (cid & 15) * 4;
            const float* rowp = base + (size_t)(kt * 64 + r) * (3 * DMODEL) + hd * DH;
            float4 kv = *(const float4*)(rowp + DMODEL + c4);
            cvt_store4(sKh + r * APAD + c4, sKl + r * APAD + c4, kv);
            float4 vv = *(const float4*)(rowp + 2 * DMODEL + c4);
            float vf[4] = {vv.x, vv.y, vv.z, vv.w};
#pragma unroll
            for (int i = 0; i < 4; i++) {
                bf16 hh, ll;
                split1(vf[i], hh, ll);
                sVh[(c4 + i) * APAD + r] = hh;
                sVl[(c4 + i) * APAD + r] = ll;
            }
        }
        __syncthreads();

#pragma unroll
        for (int j = 0; j < 8; j++)
#pragma unroll
            for (int c = 0; c < 4; c++) sfr[j][c] = 0.0f;

#pragma unroll
        for (int kc = 0; kc < 4; kc++) {
            const int kcol = kc * 16 + 2 * tg;
            uint32_t aQh[4], aQl[4];
            const bf16* q0 = sQh + (qrow + g) * APAD + kcol;
            aQh[0] = ld32(q0);
            aQh[1] = ld32(q0 + 8 * APAD);
            aQh[2] = ld32(q0 + 8);
            aQh[3] = ld32(q0 + 8 * APAD + 8);
            const bf16* q1 = sQl + (qrow + g) * APAD + kcol;
            aQl[0] = ld32(q1);
            aQl[1] = ld32(q1 + 8 * APAD);
            aQl[2] = ld32(q1 + 8);
            aQl[3] = ld32(q1 + 8 * APAD + 8);
#pragma unroll
            for (int j = 0; j < 8; j++) {
                uint32_t bh[2], bl[2];
                const bf16* k0 = sKh + (j * 8 + g) * APAD + kcol;
                bh[0] = ld32(k0); bh[1] = ld32(k0 + 8);
                const bf16* k1 = sKl + (j * 8 + g) * APAD + kcol;
                bl[0] = ld32(k1); bl[1] = ld32(k1 + 8);
                mma16816(sfr[j], aQh, bh);
                mma16816(sfr[j], aQh, bl);
                mma16816(sfr[j], aQl, bh);
            }
        }

        float tmax0 = -1e30f, tmax1 = -1e30f;
#pragma unroll
        for (int j = 0; j < 8; j++) {
            const int col = kt * 64 + j * 8 + 2 * tg;
            const bool v0 = col < len, v1 = (col + 1) < len;
            sfr[j][0] = v0 ? sfr[j][0] * 0.125f : -1e9f;
            sfr[j][1] = v1 ? sfr[j][1] * 0.125f : -1e9f;
            sfr[j][2] = v0 ? sfr[j][2] * 0.125f : -1e9f;
            sfr[j][3] = v1 ? sfr[j][3] * 0.125f : -1e9f;
            tmax0 = fmaxf(tmax0, fmaxf(sfr[j][0], sfr[j][1]));
            tmax1 = fmaxf(tmax1, fmaxf(sfr[j][2], sfr[j][3]));
        }
        tmax0 = fmaxf(tmax0, __shfl_xor_sync(0xffffffffu, tmax0, 1));
        tmax0 = fmaxf(tmax0, __shfl_xor_sync(0xffffffffu, tmax0, 2));
        tmax1 = fmaxf(tmax1, __shfl_xor_sync(0xffffffffu, tmax1, 1));
        tmax1 = fmaxf(tmax1, __shfl_xor_sync(0xffffffffu, tmax1, 2));

        const float nm0 = fmaxf(m0, tmax0), nm1 = fmaxf(m1, tmax1);
        const float al0 = expf(m0 - nm0), al1 = expf(m1 - nm1);
        m0 = nm0; m1 = nm1;

        float rs0 = 0.0f, rs1 = 0.0f;
#pragma unroll
        for (int j = 0; j < 8; j++) {
            sfr[j][0] = expf(sfr[j][0] - nm0);
            sfr[j][1] = expf(sfr[j][1] - nm0);
            sfr[j][2] = expf(sfr[j][2] - nm1);
            sfr[j][3] = expf(sfr[j][3] - nm1);
            rs0 += sfr[j][0] + sfr[j][1];
            rs1 += sfr[j][2] + sfr[j][3];
        }
        rs0 += __shfl_xor_sync(0xffffffffu, rs0, 1);
        rs0 += __shfl_xor_sync(0xffffffffu, rs0, 2);
        rs1 += __shfl_xor_sync(0xffffffffu, rs1, 1);
        rs1 += __shfl_xor_sync(0xffffffffu, rs1, 2);
        l0 = l0 * al0 + rs0;
        l1 = l1 * al1 + rs1;

#pragma unroll
        for (int j = 0; j < 8; j++) {
            ofr[j][0] *= al0; ofr[j][1] *= al0;
            ofr[j][2] *= al1; ofr[j][3] *= al1;
        }

#pragma unroll
        for (int kc = 0; kc < 4; kc++) {
            uint32_t aPh[4], aPl[4];
            packsplit2(sfr[2 * kc][0],     sfr[2 * kc][1],     aPh[0], aPl[0]);
            packsplit2(sfr[2 * kc][2],     sfr[2 * kc][3],     aPh[1], aPl[1]);
            packsplit2(sfr[2 * kc + 1][0], sfr[2 * kc + 1][1], aPh[2], aPl[2]);
            packsplit2(sfr[2 * kc + 1][2], sfr[2 * kc + 1][3], aPh[3], aPl[3]);
            const int kcol = kc * 16 + 2 * tg;
#pragma unroll
            for (int j = 0; j < 8; j++) {
                uint32_t bh[2], bl[2];
                const bf16* v0 = sVh + (j * 8 + g) * APAD + kcol;
                bh[0] = ld32(v0); bh[1] = ld32(v0 + 8);
                const bf16* v1 = sVl + (j * 8 + g) * APAD + kcol;
                bl[0] = ld32(v1); bl[1] = ld32(v1 + 8);
                mma16816(ofr[j], aPh, bh);
                mma16816(ofr[j], aPh, bl);
                mma16816(ofr[j], aPl, bh);
            }
        }
    }

    const float inv0 = 1.0f / l0, inv1 = 1.0f / l1;
    const int q0 = qt * ATQ + qrow + g;
#pragma unroll
    for (int j = 0; j < 8; j++) {
        const int col = hd * DH + j * 8 + 2 * tg;
        float* p0 = ctx + ((size_t)b * SMAX + q0) * DMODEL + col;
        p0[0] = roundtf(ofr[j][0] * inv0);
        p0[1] = roundtf(ofr[j][1] * inv0);
        float* p1 = ctx + ((size_t)b * SMAX + q0 + 8) * DMODEL + col;
        p1[0] = roundtf(ofr[j][2] * inv1);
        p1[1] = roundtf(ofr[j][3] * inv1);
    }
}

// ---------------- LayerNorm (in place) + rounded copy -------------------------
__global__ __launch_bounds__(128) void ln_kernel(
    float* __restrict__ h, const float* __restrict__ g, const float* __restrict__ bta,
    float* __restrict__ ht)
{
    __shared__ float red[8];
    const int row = blockIdx.x;
    const int t = threadIdx.x;
    float* p = h + (size_t)row * DMODEL + t * 4;
    float4 v = *(float4*)p;
    float s  = v.x + v.y + v.z + v.w;
    float ss = v.x * v.x + v.y * v.y + v.z * v.z + v.w * v.w;
#pragma unroll
    for (int o = 16; o; o >>= 1) {
        s  += __shfl_xor_sync(0xffffffffu, s, o);
        ss += __shfl_xor_sync(0xffffffffu, ss, o);
    }
    const int w = t >> 5;
    if ((t & 31) == 0) { red[w] = s; red[4 + w] = ss; }
    __syncthreads();
    s  = red[0] + red[1] + red[2] + red[3];
    ss = red[4] + red[5] + red[6] + red[7];
    const float mean = s * (1.0f / DMODEL);
    const float var  = ss * (1.0f / DMODEL) - mean * mean;
    const float rstd = rsqrtf(var + 1e-5f);
    float4 gg = *(const float4*)(g + t * 4);
    float4 bb = *(const float4*)(bta + t * 4);
    v.x = (v.x - mean) * rstd * gg.x + bb.x;
    v.y = (v.y - mean) * rstd * gg.y + bb.y;
    v.z = (v.z - mean) * rstd * gg.z + bb.z;
    v.w = (v.w - mean) * rstd * gg.w + bb.w;
    *(float4*)p = v;
    *(float4*)(ht + (size_t)row * DMODEL + t * 4) = roundtf4(v);
}

// ---------------- two-phase masked mean pooling ------------------------------
__global__ __launch_bounds__(128) void pool_part_kernel(
    const float* __restrict__ h, const int* __restrict__ lens, float* __restrict__ part)
{
    const int b = blockIdx.x;
    const int ch = blockIdx.y;
    const int d = threadIdx.x * 4;
    const int len = lens[b];
    const int t0 = ch * 64;
    int nt = len - t0;
    if (nt > 64) nt = 64;
    float4 s = {0.f, 0.f, 0.f, 0.f};
    for (int t = 0; t < nt; t++) {
        float4 v = *(const float4*)(h + ((size_t)b * SMAX + t0 + t) * DMODEL + d);
        s.x += v.x; s.y += v.y; s.z += v.z; s.w += v.w;
    }
    *(float4*)(part + (size_t)(b * 8 + ch) * DMODEL + d) = s;
}

__global__ __launch_bounds__(DMODEL) void pool_final_kernel(
    const float* __restrict__ part, const int* __restrict__ lens,
    float* __restrict__ out, int out_size)
{
    const int b = blockIdx.x;
    const int d = threadIdx.x;
    float s = 0.0f;
#pragma unroll
    for (int c = 0; c < 8; c++) s += part[(size_t)(b * 8 + c) * DMODEL + d];
    out[b * DMODEL + d] = s / (float)lens[b];
    if (d == 0 && out_size >= BATCH * DMODEL + BATCH)
        out[BATCH * DMODEL + b] = (float)lens[b];
}

// ---------------- launch ------------------------------------------------------
extern "C" void kernel_launch(void* const* d_in, const int* in_sizes, int n_in,
                              void* d_out, int out_size)
{
    (void)in_sizes; (void)n_in;
    const float* x     = (const float*)d_in[0];
    const int*   lens  = (const int*)  d_in[1];
    const float* We    = (const float*)d_in[2];
    const float* be    = (const float*)d_in[3];
    const float* Wqkv  = (const float*)d_in[4];
    const float* bqkv  = (const float*)d_in[5];
    const float* Wo    = (const float*)d_in[6];
    const float* bo    = (const float*)d_in[7];
    const float* ln1g  = (const float*)d_in[8];
    const float* ln1b  = (const float*)d_in[9];
    const float* W1    = (const float*)d_in[10];
    const float* b1    = (const float*)d_in[11];
    const float* W2    = (const float*)d_in[12];
    const float* b2    = (const float*)d_in[13];
    const float* ln2g  = (const float*)d_in[14];
    const float* ln2b  = (const float*)d_in[15];
    float* out = (float*)d_out;

    void *ph, *pht, *pqkv, *pctx, *pff, *ppool;
    void *pwq, *pwo, *pw1, *pw2;
    cudaGetSymbolAddress(&ph,    g_h);
    cudaGetSymbolAddress(&pht,   g_ht);
    cudaGetSymbolAddress(&pqkv,  g_qkv);
    cudaGetSymbolAddress(&pctx,  g_ctx);
    cudaGetSymbolAddress(&pff,   g_ff);
    cudaGetSymbolAddress(&ppool, g_pool);
    cudaGetSymbolAddress(&pwq,   g_wq_r);
    cudaGetSymbolAddress(&pwo,   g_wo_r);
    cudaGetSymbolAddress(&pw1,   g_w1_r);
    cudaGetSymbolAddress(&pw2,   g_w2_r);
    float* h    = (float*)ph;
    float* ht   = (float*)pht;
    float* qkv  = (float*)pqkv;
    float* ctx  = (float*)pctx;
    float* ff   = (float*)pff;
    float* pool = (float*)ppool;
    float* wq_r = (float*)pwq;
    float* wo_r = (float*)pwo;
    float* w1_r = (float*)pw1;
    float* w2_r = (float*)pw2;

    cudaFuncSetAttribute(fattn_kernel,
                         cudaFuncAttributeMaxDynamicSharedMemorySize, ATTN_SMEM);
    cudaFuncSetAttribute(bgemm_kernel<EPI_NONE>,
                         cudaFuncAttributeMaxDynamicSharedMemorySize, GSMEM);
    cudaFuncSetAttribute(bgemm_kernel<EPI_RELU>,
                         cudaFuncAttributeMaxDynamicSharedMemorySize, GSMEM);
    cudaFuncSetAttribute(bgemm_kernel<EPI_RES>,
                         cudaFuncAttributeMaxDynamicSharedMemorySize, GSMEM);

    // ---- round weights to tf32 (once per launch) ----
    round_kernel<<<NLAYERS * 3 * DMODEL * DMODEL / 1024, 256>>>(Wqkv, wq_r);
    round_kernel<<<NLAYERS * DMODEL * DMODEL / 1024, 256>>>(Wo, wo_r);
    round_kernel<<<NLAYERS * DFF * DMODEL / 1024, 256>>>(W1, w1_r);
    round_kernel<<<NLAYERS * DMODEL * DFF / 1024, 256>>>(W2, w2_r);

    // embedding + positional encoding: h (exact) + ht (rounded)
    embed_kernel<<<dim3(DMODEL / 128, NTOK / 128), 256>>>(
        x, We, be, h, ht, NTOK, DMODEL, INSZ);

    for (int l = 0; l < NLAYERS; l++) {
        const float* wq  = wq_r + (size_t)l * 3 * DMODEL * DMODEL;
        const float* bq  = bqkv + (size_t)l * 3 * DMODEL;
        const float* wo  = wo_r + (size_t)l * DMODEL * DMODEL;
        const float* bO  = bo   + (size_t)l * DMODEL;
        const float* w1  = w1_r + (size_t)l * DFF * DMODEL;
        const float* bf1 = b1   + (size_t)l * DFF;
        const float* w2  = w2_r + (size_t)l * DMODEL * DFF;
        const float* bf2 = b2   + (size_t)l * DMODEL;

        // qkv = ht @ wq^T + bq
        bgemm_kernel<EPI_NONE><<<dim3(3 * DMODEL / 128, NTOK / 128), 256, GSMEM>>>(
            ht, wq, bq, nullptr, qkv, NTOK, 3 * DMODEL, DMODEL);

        // attention -> ctx (tf32-rounded)
        fattn_kernel<<<dim3(SMAX / ATQ, NHEAD, BATCH), 128, ATTN_SMEM>>>(qkv, lens, ctx);

        // h = h + ctx @ wo^T + bo
        bgemm_kernel<EPI_RES><<<dim3(DMODEL / 128, NTOK / 128), 256, GSMEM>>>(
            ctx, wo, bO, h, h, NTOK, DMODEL, DMODEL);
        ln_kernel<<<NTOK, 128>>>(h, ln1g + l * DMODEL, ln1b + l * DMODEL, ht);

        // ff = round(relu(ht @ w1^T + b1))
        bgemm_kernel<EPI_RELU><<<dim3(DFF / 128, NTOK / 128), 256, GSMEM>>>(
            ht, w1, bf1, nullptr, ff, NTOK, DFF, DMODEL);
        // h = h + ff @ w2^T + b2
        bgemm_kernel<EPI_RES><<<dim3(DMODEL / 128, NTOK / 128), 256, GSMEM>>>(
            ff, w2, bf2, h, h, NTOK, DMODEL, DFF);
        ln_kernel<<<NTOK, 128>>>(h, ln2g + l * DMODEL, ln2b + l * DMODEL, ht);
    }

    pool_part_kernel<<<dim3(BATCH, 8), 128>>>(h, lens, pool);
    pool_final_kernel<<<BATCH, DMODEL>>>(pool, lens, out, out_size);
}

// round 14
// speedup vs baseline: 2.2680x; 1.0370x over previous
#include <cuda_runtime.h>
#include <cuda_bf16.h>
#include <cstdint>

// ---------------- problem constants ----------------
#define NLAYERS 4
#define INSZ    80
#define DMODEL  512
#define NHEAD   8
#define DH      64
#define DFF     2048
#define BATCH   16
#define SMAX    512
#define NTOK    (BATCH * SMAX)   // 8192

typedef __nv_bfloat16 bf16;

// ---------------- scratch (device globals; no allocs allowed) ----------------
__device__ float g_h  [NTOK * DMODEL];       // hidden state (exact fp32)
__device__ float g_ht [NTOK * DMODEL];       // tf32-rounded copy of h
__device__ float g_qkv[NTOK * 3 * DMODEL];   // qkv projections (tf32-rounded)
__device__ float g_ctx[NTOK * DMODEL];       // attention context (tf32-rounded)
__device__ float g_ff [NTOK * DFF];          // ff intermediate (tf32-rounded)
__device__ float g_pool[BATCH * 8 * DMODEL]; // pooling partials

// tf32-rounded weight copies
__device__ float g_wq_r[NLAYERS * 3 * DMODEL * DMODEL];
__device__ float g_wo_r[NLAYERS * DMODEL * DMODEL];
__device__ float g_w1_r[NLAYERS * DFF * DMODEL];
__device__ float g_w2_r[NLAYERS * DMODEL * DFF];

enum { EPI_NONE = 0, EPI_PE = 1, EPI_RELU = 2, EPI_RES = 3, EPI_QKV = 4 };

// ---------------- helpers -----------------------------------------------------
// tf32 m16n8k8 MMA (fp32 accum); operands pre-rounded fp32 bit-patterns
__device__ __forceinline__ void mma1688(float* d, const uint32_t* a, const uint32_t* b) {
    asm volatile(
        "mma.sync.aligned.m16n8k8.row.col.f32.tf32.tf32.f32 "
        "{%0,%1,%2,%3},{%4,%5,%6,%7},{%8,%9},{%0,%1,%2,%3};\n"
        : "+f"(d[0]), "+f"(d[1]), "+f"(d[2]), "+f"(d[3])
        : "r"(a[0]), "r"(a[1]), "r"(a[2]), "r"(a[3]), "r"(b[0]), "r"(b[1]));
}

__device__ __forceinline__ float roundtf(float f) {
    uint32_t u;
    asm("cvt.rna.tf32.f32 %0, %1;" : "=r"(u) : "f"(f));
    return __uint_as_float(u);
}

__device__ __forceinline__ float4 roundtf4(float4 v) {
    v.x = roundtf(v.x); v.y = roundtf(v.y);
    v.z = roundtf(v.z); v.w = roundtf(v.w);
    return v;
}

__device__ __forceinline__ void cp16(uint32_t saddr, const void* g) {
    asm volatile("cp.async.cg.shared.global [%0], [%1], 16;\n" :: "r"(saddr), "l"(g));
}
__device__ __forceinline__ void cp_commit() { asm volatile("cp.async.commit_group;\n"); }
template <int N>
__device__ __forceinline__ void cp_wait() {
    asm volatile("cp.async.wait_group %0;\n" :: "n"(N));
}

// ---------------- fp32 -> tf32-rounded copy kernel ---------------------------
__global__ __launch_bounds__(256) void round_kernel(
    const float* __restrict__ src, float* __restrict__ dst)
{
    const int i = (blockIdx.x * 256 + threadIdx.x) * 4;
    *(float4*)(dst + i) = roundtf4(*(const float4*)(src + i));
}

// =============================================================================
// TF32 single-pass tensor-core GEMM, 3-stage cp.async, pre-rounded operands.
// 128x128 CTA tile, 256 threads, warp tile 32x64 (4m x 2n). (R13, proven)
// =============================================================================
#define BK    32
#define LDS36 36
#define APLNW (128 * LDS36)
#define BPLNW (128 * LDS36)
#define BUFW  (APLNW + BPLNW)
#define NSTG  3
#define GSMEM (NSTG * BUFW * 4)        // 110592 B

template <int EPI>
__global__ __launch_bounds__(256, 2) void bgemm_kernel(
    const float* __restrict__ A, const float* __restrict__ B,
    const float* __restrict__ bias, const float* __restrict__ res,
    float* __restrict__ C, int M, int N, int K)
{
    extern __shared__ uint32_t smu[];
    const uint32_t smbase = (uint32_t)__cvta_generic_to_shared(smu);

    const int tid = threadIdx.x;
    const int bm = blockIdx.y * 128;
    const int bn = blockIdx.x * 128;

    const int wid  = tid >> 5;
    const int wm   = wid & 3;
    const int wn   = wid >> 2;
    const int lane = tid & 31;
    const int g    = lane >> 2;
    const int tg   = lane & 3;

    const int lrow = tid >> 3;
    const int lc4  = (tid & 7) * 4;

    float acc[2][8][4];
#pragma unroll
    for (int i = 0; i < 2; i++)
#pragma unroll
        for (int j = 0; j < 8; j++)
#pragma unroll
            for (int r = 0; r < 4; r++) acc[i][j][r] = 0.0f;

    const int ntile = K / BK;

#define LOAD_TILE(T, STG)                                                         \
    {                                                                             \
        const int k0 = (T) * BK;                                                  \
        const uint32_t sb = smbase + (STG) * (BUFW * 4);                          \
        _Pragma("unroll")                                                         \
        for (int p = 0; p < 4; p++) {                                             \
            const int row = lrow + p * 32;                                        \
            cp16(sb + (row * LDS36 + lc4) * 4,                                    \
                 A + (size_t)(bm + row) * K + k0 + lc4);                          \
            cp16(sb + (APLNW + row * LDS36 + lc4) * 4,                            \
                 B + (size_t)(bn + row) * K + k0 + lc4);                          \
        }                                                                         \
    }

    LOAD_TILE(0, 0); cp_commit();
    LOAD_TILE(1, 1); cp_commit();

    int stg = 0;
    for (int t = 0; t < ntile; t++) {
        if (t + 1 < ntile) cp_wait<1>(); else cp_wait<0>();
        __syncthreads();

        if (t + 2 < ntile) {
            const int s2 = (stg + 2) % NSTG;
            LOAD_TILE(t + 2, s2);
            cp_commit();
        }

        const uint32_t* pA = smu + stg * BUFW;
        const uint32_t* pB = pA + APLNW;

#pragma unroll
        for (int kk = 0; kk < 4; kk++) {
            const int kc = kk * 8 + tg;
            uint32_t a[2][4], b[8][2];
#pragma unroll
            for (int mi = 0; mi < 2; mi++) {
                const int r = wm * 32 + mi * 16 + g;
                a[mi][0] = pA[r * LDS36 + kc];
                a[mi][1] = pA[(r + 8) * LDS36 + kc];
                a[mi][2] = pA[r * LDS36 + kc + 4];
                a[mi][3] = pA[(r + 8) * LDS36 + kc + 4];
            }
#pragma unroll
            for (int ni = 0; ni < 8; ni++) {
                const int r = wn * 64 + ni * 8 + g;
                b[ni][0] = pB[r * LDS36 + kc];
                b[ni][1] = pB[r * LDS36 + kc + 4];
            }
#pragma unroll
            for (int mi = 0; mi < 2; mi++)
#pragma unroll
                for (int ni = 0; ni < 8; ni++)
                    mma1688(acc[mi][ni], a[mi], b[ni]);
        }
        stg = (stg + 1) % NSTG;
    }
#undef LOAD_TILE

    // ---- epilogue ----
#pragma unroll
    for (int mi = 0; mi < 2; mi++) {
#pragma unroll
        for (int ni = 0; ni < 8; ni++) {
            const int m = bm + wm * 32 + mi * 16 + g;
            const int n = bn + wn * 64 + ni * 8 + tg * 2;
            const float b0 = bias[n], b1 = bias[n + 1];
#pragma unroll
            for (int h = 0; h < 2; h++) {
                const int mm = m + h * 8;
                float v0 = acc[mi][ni][h * 2 + 0] + b0;
                float v1 = acc[mi][ni][h * 2 + 1] + b1;
                if (EPI == EPI_RELU) {
                    v0 = roundtf(fmaxf(v0, 0.0f));
                    v1 = roundtf(fmaxf(v1, 0.0f));
                }
                if (EPI == EPI_QKV) {
                    v0 = roundtf(v0);
                    v1 = roundtf(v1);
                }
                if (EPI == EPI_RES) {
                    const float* rp = res + (size_t)mm * N + n;
                    v0 += rp[0]; v1 += rp[1];
                }
                float* cp = C + (size_t)mm * N + n;
                cp[0] = v0; cp[1] = v1;
            }
        }
    }
}

// ---------------- fp32 SGEMM (embed, K=80), writes h exact + h_t rounded -----
__global__ __launch_bounds__(256) void embed_kernel(
    const float* __restrict__ A, const float* __restrict__ B,
    const float* __restrict__ bias,
    float* __restrict__ C, float* __restrict__ Ct, int M, int N, int K)
{
    __shared__ float As[16][132];
    __shared__ float Bs[16][132];

    const int tid = threadIdx.x;
    const int bm = blockIdx.y * 128;
    const int bn = blockIdx.x * 128;

    const int lr = tid >> 2;
    const int lc = (tid & 3) * 4;
    const int ty = tid >> 4;
    const int tx = tid & 15;

    float acc[8][8];
#pragma unroll
    for (int i = 0; i < 8; i++)
#pragma unroll
        for (int j = 0; j < 8; j++) acc[i][j] = 0.0f;

    for (int k0 = 0; k0 < K; k0 += 16) {
#pragma unroll
        for (int p = 0; p < 2; p++) {
            const int row = lr + p * 64;
            float4 a = *(const float4*)(A + (size_t)(bm + row) * K + k0 + lc);
            float4 b = *(const float4*)(B + (size_t)(bn + row) * K + k0 + lc);
            As[lc + 0][row] = a.x; As[lc + 1][row] = a.y;
            As[lc + 2][row] = a.z; As[lc + 3][row] = a.w;
            Bs[lc + 0][row] = b.x; Bs[lc + 1][row] = b.y;
            Bs[lc + 2][row] = b.z; Bs[lc + 3][row] = b.w;
        }
        __syncthreads();
#pragma unroll
        for (int kk = 0; kk < 16; kk++) {
            float a[8], b[8];
            *(float4*)(a)     = *(const float4*)&As[kk][ty * 8];
            *(float4*)(a + 4) = *(const float4*)&As[kk][ty * 8 + 4];
            *(float4*)(b)     = *(const float4*)&Bs[kk][tx * 8];
            *(float4*)(b + 4) = *(const float4*)&Bs[kk][tx * 8 + 4];
#pragma unroll
            for (int i = 0; i < 8; i++)
#pragma unroll
                for (int j = 0; j < 8; j++)
                    acc[i][j] += a[i] * b[j];
        }
        __syncthreads();
    }

    const int m0 = bm + ty * 8;
    const int n0 = bn + tx * 8;
    float bv[8];
#pragma unroll
    for (int j = 0; j < 8; j++) bv[j] = bias[n0 + j];

#pragma unroll
    for (int i = 0; i < 8; i++) {
        const int m = m0 + i;
        const int s = m & (SMAX - 1);
#pragma unroll
        for (int j = 0; j < 8; j++) {
            const int n = n0 + j;
            float v = acc[i][j] + bv[j];
            const int de = n & ~1;
            float ang = (float)s * expf((float)de * (-9.210340371976184f / 512.0f));
            v += (n & 1) ? cosf(ang) : sinf(ang);
            const size_t ix = (size_t)m * N + n;
            C[ix]  = v;
            Ct[ix] = roundtf(v);
        }
    }
}

// =============================================================================
// Flash-style TF32 attention. CTA = (64 q, head, batch), 128 thr (4 warps).
// qkv is pre-rounded tf32 (EPI_QKV) -> loaders are plain copies.
// QK^T and P·V single-pass m16n8k8 tf32; P rounded via warp-private smem pane.
// =============================================================================
#define ATQ   64
#define ALD   68                       // fp32 words per row (64 + 4 pad)
#define APL   (64 * ALD)               // words per pane
#define ATTN_SMEM (4 * APL * 4)        // Q,K,V,P panes: 69632 B

__global__ __launch_bounds__(128) void fattn_kernel(
    const float* __restrict__ qkv, const int* __restrict__ lens,
    float* __restrict__ ctx)
{
    extern __shared__ float sf[];
    float* sQ = sf;
    float* sK = sf + APL;
    float* sV = sf + 2 * APL;          // transposed: [dh][key]
    float* sP = sf + 3 * APL;          // [q][key]
    const uint32_t* pQ = (const uint32_t*)sQ;
    const uint32_t* pK = (const uint32_t*)sK;
    const uint32_t* pV = (const uint32_t*)sV;
    const uint32_t* pP = (const uint32_t*)sP;

    const int qt = blockIdx.x;
    const int hd = blockIdx.y;
    const int b  = blockIdx.z;
    const int tid  = threadIdx.x;
    const int w    = tid >> 5;
    const int lane = tid & 31;
    const int g    = lane >> 2;
    const int tg   = lane & 3;
    const int len  = lens[b];

    const float* base = qkv + (size_t)b * SMAX * (3 * DMODEL);

    // ---- load Q tile [64 x 64] (already tf32-rounded) ----
#pragma unroll
    for (int p = 0; p < 8; p++) {
        const int cid = p * 128 + tid;
        const int r  = cid >> 4;
        const int c4 = (cid & 15) * 4;
        *(float4*)(sQ + r * ALD + c4) =
            *(const float4*)(base + (size_t)(qt * ATQ + r) * (3 * DMODEL) + hd * DH + c4);
    }

    float sfr[8][4];
    float ofr[8][4];
#pragma unroll
    for (int j = 0; j < 8; j++)
#pragma unroll
        for (int c = 0; c < 4; c++) ofr[j][c] = 0.0f;
    float m0 = -1e30f, m1 = -1e30f, l0 = 0.0f, l1 = 0.0f;

    const int qrow = w * 16;

    for (int kt = 0; kt < 8; kt++) {
        __syncthreads();
        // ---- load K tile + V tile (transposed), plain copies ----
#pragma unroll
        for (int p = 0; p < 8; p++) {
            const int cid = p * 128 + tid;
            const int r  = cid >> 4;
            const int c4 = (cid & 15) * 4;
            const float* rowp = base + (size_t)(kt * 64 + r) * (3 * DMODEL) + hd * DH;
            *(float4*)(sK + r * ALD + c4) = *(const float4*)(rowp + DMODEL + c4);
            float4 vv = *(const float4*)(rowp + 2 * DMODEL + c4);
            sV[(c4 + 0) * ALD + r] = vv.x;
            sV[(c4 + 1) * ALD + r] = vv.y;
            sV[(c4 + 2) * ALD + r] = vv.z;
            sV[(c4 + 3) * ALD + r] = vv.w;
        }
        __syncthreads();

        // ---- S = Q K^T (single-pass tf32) ----
#pragma unroll
        for (int j = 0; j < 8; j++)
#pragma unroll
            for (int c = 0; c < 4; c++) sfr[j][c] = 0.0f;

#pragma unroll
        for (int kc = 0; kc < 8; kc++) {
            const int kcol = kc * 8 + tg;
            uint32_t a[4];
            a[0] = pQ[(qrow + g) * ALD + kcol];
            a[1] = pQ[(qrow + 8 + g) * ALD + kcol];
            a[2] = pQ[(qrow + g) * ALD + kcol + 4];
            a[3] = pQ[(qrow + 8 + g) * ALD + kcol + 4];
#pragma unroll
            for (int j = 0; j < 8; j++) {
                uint32_t bfr[2];
                bfr[0] = pK[(j * 8 + g) * ALD + kcol];
                bfr[1] = pK[(j * 8 + g) * ALD + kcol + 4];
                mma1688(sfr[j], a, bfr);
            }
        }

        // ---- scale + mask + online softmax update ----
        float tmax0 = -1e30f, tmax1 = -1e30f;
#pragma unroll
        for (int j = 0; j < 8; j++) {
            const int col = kt * 64 + j * 8 + 2 * tg;
            const bool v0 = col < len, v1 = (col + 1) < len;
            sfr[j][0] = v0 ? sfr[j][0] * 0.125f : -1e9f;
            sfr[j][1] = v1 ? sfr[j][1] * 0.125f : -1e9f;
            sfr[j][2] = v0 ? sfr[j][2] * 0.125f : -1e9f;
            sfr[j][3] = v1 ? sfr[j][3] * 0.125f : -1e9f;
            tmax0 = fmaxf(tmax0, fmaxf(sfr[j][0], sfr[j][1]));
            tmax1 = fmaxf(tmax1, fmaxf(sfr[j][2], sfr[j][3]));
        }
        tmax0 = fmaxf(tmax0, __shfl_xor_sync(0xffffffffu, tmax0, 1));
        tmax0 = fmaxf(tmax0, __shfl_xor_sync(0xffffffffu, tmax0, 2));
        tmax1 = fmaxf(tmax1, __shfl_xor_sync(0xffffffffu, tmax1, 1));
        tmax1 = fmaxf(tmax1, __shfl_xor_sync(0xffffffffu, tmax1, 2));

        const float nm0 = fmaxf(m0, tmax0), nm1 = fmaxf(m1, tmax1);
        const float al0 = expf(m0 - nm0), al1 = expf(m1 - nm1);
        m0 = nm0; m1 = nm1;

        float rs0 = 0.0f, rs1 = 0.0f;
#pragma unroll
        for (int j = 0; j < 8; j++) {
            sfr[j][0] = expf(sfr[j][0] - nm0);
            sfr[j][1] = expf(sfr[j][1] - nm0);
            sfr[j][2] = expf(sfr[j][2] - nm1);
            sfr[j][3] = expf(sfr[j][3] - nm1);
            rs0 += sfr[j][0] + sfr[j][1];
            rs1 += sfr[j][2] + sfr[j][3];
        }
        rs0 += __shfl_xor_sync(0xffffffffu, rs0, 1);
        rs0 += __shfl_xor_sync(0xffffffffu, rs0, 2);
        rs1 += __shfl_xor_sync(0xffffffffu, rs1, 1);
        rs1 += __shfl_xor_sync(0xffffffffu, rs1, 2);
        l0 = l0 * al0 + rs0;
        l1 = l1 * al1 + rs1;

#pragma unroll
        for (int j = 0; j < 8; j++) {
            ofr[j][0] *= al0; ofr[j][1] *= al0;
            ofr[j][2] *= al1; ofr[j][3] *= al1;
        }

        // ---- round P into warp-private smem pane ----
#pragma unroll
        for (int j = 0; j < 8; j++) {
            const int c0 = j * 8 + 2 * tg;
            sP[(qrow + g) * ALD + c0]         = roundtf(sfr[j][0]);
            sP[(qrow + g) * ALD + c0 + 1]     = roundtf(sfr[j][1]);
            sP[(qrow + 8 + g) * ALD + c0]     = roundtf(sfr[j][2]);
            sP[(qrow + 8 + g) * ALD + c0 + 1] = roundtf(sfr[j][3]);
        }
        __syncwarp();

        // ---- O += P V (single-pass tf32) ----
#pragma unroll
        for (int kc = 0; kc < 8; kc++) {
            const int kcol = kc * 8 + tg;
            uint32_t aP[4];
            aP[0] = pP[(qrow + g) * ALD + kcol];
            aP[1] = pP[(qrow + 8 + g) * ALD + kcol];
            aP[2] = pP[(qrow + g) * ALD + kcol + 4];
            aP[3] = pP[(qrow + 8 + g) * ALD + kcol + 4];
#pragma unroll
            for (int j = 0; j < 8; j++) {
                uint32_t bV[2];
                bV[0] = pV[(j * 8 + g) * ALD + kcol];
                bV[1] = pV[(j * 8 + g) * ALD + kcol + 4];
                mma1688(ofr[j], aP, bV);
            }
        }
    }

    // ---- finalize: O /= l, write ctx tf32-rounded ----
    const float inv0 = 1.0f / l0, inv1 = 1.0f / l1;
    const int q0 = qt * ATQ + qrow + g;
#pragma unroll
    for (int j = 0; j < 8; j++) {
        const int col = hd * DH + j * 8 + 2 * tg;
        float* p0 = ctx + ((size_t)b * SMAX + q0) * DMODEL + col;
        p0[0] = roundtf(ofr[j][0] * inv0);
        p0[1] = roundtf(ofr[j][1] * inv0);
        float* p1 = ctx + ((size_t)b * SMAX + q0 + 8) * DMODEL + col;
        p1[0] = roundtf(ofr[j][2] * inv1);
        p1[1] = roundtf(ofr[j][3] * inv1);
    }
}

// ---------------- LayerNorm (in place) + rounded copy -------------------------
__global__ __launch_bounds__(128) void ln_kernel(
    float* __restrict__ h, const float* __restrict__ g, const float* __restrict__ bta,
    float* __restrict__ ht)
{
    __shared__ float red[8];
    const int row = blockIdx.x;
    const int t = threadIdx.x;
    float* p = h + (size_t)row * DMODEL + t * 4;
    float4 v = *(float4*)p;
    float s  = v.x + v.y + v.z + v.w;
    float ss = v.x * v.x + v.y * v.y + v.z * v.z + v.w * v.w;
#pragma unroll
    for (int o = 16; o; o >>= 1) {
        s  += __shfl_xor_sync(0xffffffffu, s, o);
        ss += __shfl_xor_sync(0xffffffffu, ss, o);
    }
    const int w = t >> 5;
    if ((t & 31) == 0) { red[w] = s; red[4 + w] = ss; }
    __syncthreads();
    s  = red[0] + red[1] + red[2] + red[3];
    ss = red[4] + red[5] + red[6] + red[7];
    const float mean = s * (1.0f / DMODEL);
    const float var  = ss * (1.0f / DMODEL) - mean * mean;
    const float rstd = rsqrtf(var + 1e-5f);
    float4 gg = *(const float4*)(g + t * 4);
    float4 bb = *(const float4*)(bta + t * 4);
    v.x = (v.x - mean) * rstd * gg.x + bb.x;
    v.y = (v.y - mean) * rstd * gg.y + bb.y;
    v.z = (v.z - mean) * rstd * gg.z + bb.z;
    v.w = (v.w - mean) * rstd * gg.w + bb.w;
    *(float4*)p = v;
    *(float4*)(ht + (size_t)row * DMODEL + t * 4) = roundtf4(v);
}

// ---------------- two-phase masked mean pooling ------------------------------
__global__ __launch_bounds__(128) void pool_part_kernel(
    const float* __restrict__ h, const int* __restrict__ lens, float* __restrict__ part)
{
    const int b = blockIdx.x;
    const int ch = blockIdx.y;
    const int d = threadIdx.x * 4;
    const int len = lens[b];
    const int t0 = ch * 64;
    int nt = len - t0;
    if (nt > 64) nt = 64;
    float4 s = {0.f, 0.f, 0.f, 0.f};
    for (int t = 0; t < nt; t++) {
        float4 v = *(const float4*)(h + ((size_t)b * SMAX + t0 + t) * DMODEL + d);
        s.x += v.x; s.y += v.y; s.z += v.z; s.w += v.w;
    }
    *(float4*)(part + (size_t)(b * 8 + ch) * DMODEL + d) = s;
}

__global__ __launch_bounds__(DMODEL) void pool_final_kernel(
    const float* __restrict__ part, const int* __restrict__ lens,
    float* __restrict__ out, int out_size)
{
    const int b = blockIdx.x;
    const int d = threadIdx.x;
    float s = 0.0f;
#pragma unroll
    for (int c = 0; c < 8; c++) s += part[(size_t)(b * 8 + c) * DMODEL + d];
    out[b * DMODEL + d] = s / (float)lens[b];
    if (d == 0 && out_size >= BATCH * DMODEL + BATCH)
        out[BATCH * DMODEL + b] = (float)lens[b];
}

// ---------------- launch ------------------------------------------------------
extern "C" void kernel_launch(void* const* d_in, const int* in_sizes, int n_in,
                              void* d_out, int out_size)
{
    (void)in_sizes; (void)n_in;
    const float* x     = (const float*)d_in[0];
    const int*   lens  = (const int*)  d_in[1];
    const float* We    = (const float*)d_in[2];
    const float* be    = (const float*)d_in[3];
    const float* Wqkv  = (const float*)d_in[4];
    const float* bqkv  = (const float*)d_in[5];
    const float* Wo    = (const float*)d_in[6];
    const float* bo    = (const float*)d_in[7];
    const float* ln1g  = (const float*)d_in[8];
    const float* ln1b  = (const float*)d_in[9];
    const float* W1    = (const float*)d_in[10];
    const float* b1    = (const float*)d_in[11];
    const float* W2    = (const float*)d_in[12];
    const float* b2    = (const float*)d_in[13];
    const float* ln2g  = (const float*)d_in[14];
    const float* ln2b  = (const float*)d_in[15];
    float* out = (float*)d_out;

    void *ph, *pht, *pqkv, *pctx, *pff, *ppool;
    void *pwq, *pwo, *pw1, *pw2;
    cudaGetSymbolAddress(&ph,    g_h);
    cudaGetSymbolAddress(&pht,   g_ht);
    cudaGetSymbolAddress(&pqkv,  g_qkv);
    cudaGetSymbolAddress(&pctx,  g_ctx);
    cudaGetSymbolAddress(&pff,   g_ff);
    cudaGetSymbolAddress(&ppool, g_pool);
    cudaGetSymbolAddress(&pwq,   g_wq_r);
    cudaGetSymbolAddress(&pwo,   g_wo_r);
    cudaGetSymbolAddress(&pw1,   g_w1_r);
    cudaGetSymbolAddress(&pw2,   g_w2_r);
    float* h    = (float*)ph;
    float* ht   = (float*)pht;
    float* qkv  = (float*)pqkv;
    float* ctx  = (float*)pctx;
    float* ff   = (float*)pff;
    float* pool = (float*)ppool;
    float* wq_r = (float*)pwq;
    float* wo_r = (float*)pwo;
    float* w1_r = (float*)pw1;
    float* w2_r = (float*)pw2;

    cudaFuncSetAttribute(fattn_kernel,
                         cudaFuncAttributeMaxDynamicSharedMemorySize, ATTN_SMEM);
    cudaFuncSetAttribute(bgemm_kernel<EPI_QKV>,
                         cudaFuncAttributeMaxDynamicSharedMemorySize, GSMEM);
    cudaFuncSetAttribute(bgemm_kernel<EPI_RELU>,
                         cudaFuncAttributeMaxDynamicSharedMemorySize, GSMEM);
    cudaFuncSetAttribute(bgemm_kernel<EPI_RES>,
                         cudaFuncAttributeMaxDynamicSharedMemorySize, GSMEM);

    // ---- round weights to tf32 (once per launch) ----
    round_kernel<<<NLAYERS * 3 * DMODEL * DMODEL / 1024, 256>>>(Wqkv, wq_r);
    round_kernel<<<NLAYERS * DMODEL * DMODEL / 1024, 256>>>(Wo, wo_r);
    round_kernel<<<NLAYERS * DFF * DMODEL / 1024, 256>>>(W1, w1_r);
    round_kernel<<<NLAYERS * DMODEL * DFF / 1024, 256>>>(W2, w2_r);

    // embedding + positional encoding: h (exact) + ht (rounded)
    embed_kernel<<<dim3(DMODEL / 128, NTOK / 128), 256>>>(
        x, We, be, h, ht, NTOK, DMODEL, INSZ);

    for (int l = 0; l < NLAYERS; l++) {
        const float* wq  = wq_r + (size_t)l * 3 * DMODEL * DMODEL;
        const float* bq  = bqkv + (size_t)l * 3 * DMODEL;
        const float* wo  = wo_r + (size_t)l * DMODEL * DMODEL;
        const float* bO  = bo   + (size_t)l * DMODEL;
        const float* w1  = w1_r + (size_t)l * DFF * DMODEL;
        const float* bf1 = b1   + (size_t)l * DFF;
        const float* w2  = w2_r + (size_t)l * DMODEL * DFF;
        const float* bf2 = b2   + (size_t)l * DMODEL;

        // qkv = round(ht @ wq^T + bq)  (tf32 out, feeds attention directly)
        bgemm_kernel<EPI_QKV><<<dim3(3 * DMODEL / 128, NTOK / 128), 256, GSMEM>>>(
            ht, wq, bq, nullptr, qkv, NTOK, 3 * DMODEL, DMODEL);

        // attention -> ctx (tf32-rounded)
        fattn_kernel<<<dim3(SMAX / ATQ, NHEAD, BATCH), 128, ATTN_SMEM>>>(qkv, lens, ctx);

        // h = h + ctx @ wo^T + bo
        bgemm_kernel<EPI_RES><<<dim3(DMODEL / 128, NTOK / 128), 256, GSMEM>>>(
            ctx, wo, bO, h, h, NTOK, DMODEL, DMODEL);
        ln_kernel<<<NTOK, 128>>>(h, ln1g + l * DMODEL, ln1b + l * DMODEL, ht);

        // ff = round(relu(ht @ w1^T + b1))
        bgemm_kernel<EPI_RELU><<<dim3(DFF / 128, NTOK / 128), 256, GSMEM>>>(
            ht, w1, bf1, nullptr, ff, NTOK, DFF, DMODEL);
        // h = h + ff @ w2^T + b2
        bgemm_kernel<EPI_RES><<<dim3(DMODEL / 128, NTOK / 128), 256, GSMEM>>>(
            ff, w2, bf2, h, h, NTOK, DMODEL, DFF);
        ln_kernel<<<NTOK, 128>>>(h, ln2g + l * DMODEL, ln2b + l * DMODEL, ht);
    }

    pool_part_kernel<<<dim3(BATCH, 8), 128>>>(h, lens, pool);
    pool_final_kernel<<<BATCH, DMODEL>>>(pool, lens, out, out_size);
}

// round 15
// speedup vs baseline: 2.3017x; 1.0149x over previous
#include <cuda_runtime.h>
#include <cuda_bf16.h>
#include <cstdint>

// ---------------- problem constants ----------------
#define NLAYERS 4
#define INSZ    80
#define DMODEL  512
#define NHEAD   8
#define DH      64
#define DFF     2048
#define BATCH   16
#define SMAX    512
#define NTOK    (BATCH * SMAX)   // 8192

typedef __nv_bfloat16 bf16;

// ---------------- scratch (device globals; no allocs allowed) ----------------
__device__ float g_h  [NTOK * DMODEL];       // hidden state (exact fp32)
__device__ float g_ht [NTOK * DMODEL];       // tf32-rounded copy of h
__device__ float g_qkv[NTOK * 3 * DMODEL];   // qkv projections (tf32-rounded)
__device__ float g_ctx[NTOK * DMODEL];       // attention context (tf32-rounded)
__device__ float g_ff [NTOK * DFF];          // ff intermediate (tf32-rounded)
__device__ float g_pool[BATCH * 8 * DMODEL]; // pooling partials

// tf32-rounded weight copies
__device__ float g_wq_r[NLAYERS * 3 * DMODEL * DMODEL];
__device__ float g_wo_r[NLAYERS * DMODEL * DMODEL];
__device__ float g_w1_r[NLAYERS * DFF * DMODEL];
__device__ float g_w2_r[NLAYERS * DMODEL * DFF];

enum { EPI_NONE = 0, EPI_PE = 1, EPI_RELU = 2, EPI_RES = 3, EPI_QKV = 4 };

// ---------------- helpers -----------------------------------------------------
// tf32 m16n8k8 MMA (fp32 accum); operands pre-rounded fp32 bit-patterns
__device__ __forceinline__ void mma1688(float* d, const uint32_t* a, const uint32_t* b) {
    asm volatile(
        "mma.sync.aligned.m16n8k8.row.col.f32.tf32.tf32.f32 "
        "{%0,%1,%2,%3},{%4,%5,%6,%7},{%8,%9},{%0,%1,%2,%3};\n"
        : "+f"(d[0]), "+f"(d[1]), "+f"(d[2]), "+f"(d[3])
        : "r"(a[0]), "r"(a[1]), "r"(a[2]), "r"(a[3]), "r"(b[0]), "r"(b[1]));
}

__device__ __forceinline__ float roundtf(float f) {
    uint32_t u;
    asm("cvt.rna.tf32.f32 %0, %1;" : "=r"(u) : "f"(f));
    return __uint_as_float(u);
}

__device__ __forceinline__ float4 roundtf4(float4 v) {
    v.x = roundtf(v.x); v.y = roundtf(v.y);
    v.z = roundtf(v.z); v.w = roundtf(v.w);
    return v;
}

__device__ __forceinline__ void cp16(uint32_t saddr, const void* g) {
    asm volatile("cp.async.cg.shared.global [%0], [%1], 16;\n" :: "r"(saddr), "l"(g));
}
__device__ __forceinline__ void cp_commit() { asm volatile("cp.async.commit_group;\n"); }
template <int N>
__device__ __forceinline__ void cp_wait() {
    asm volatile("cp.async.wait_group %0;\n" :: "n"(N));
}

// ---------------- fp32 -> tf32-rounded copy kernel ---------------------------
__global__ __launch_bounds__(256) void round_kernel(
    const float* __restrict__ src, float* __restrict__ dst)
{
    const int i = (blockIdx.x * 256 + threadIdx.x) * 4;
    *(float4*)(dst + i) = roundtf4(*(const float4*)(src + i));
}

// =============================================================================
// TF32 single-pass tensor-core GEMM, 3-stage cp.async, pre-rounded operands.
// 128x128 CTA tile, 256 threads, warp tile 32x64 (4m x 2n). (R13, proven)
// =============================================================================
#define BK    32
#define LDS36 36
#define APLNW (128 * LDS36)
#define BPLNW (128 * LDS36)
#define BUFW  (APLNW + BPLNW)
#define NSTG  3
#define GSMEM (NSTG * BUFW * 4)        // 110592 B

template <int EPI>
__global__ __launch_bounds__(256, 2) void bgemm_kernel(
    const float* __restrict__ A, const float* __restrict__ B,
    const float* __restrict__ bias, const float* __restrict__ res,
    float* __restrict__ C, int M, int N, int K)
{
    extern __shared__ uint32_t smu[];
    const uint32_t smbase = (uint32_t)__cvta_generic_to_shared(smu);

    const int tid = threadIdx.x;
    const int bm = blockIdx.y * 128;
    const int bn = blockIdx.x * 128;

    const int wid  = tid >> 5;
    const int wm   = wid & 3;
    const int wn   = wid >> 2;
    const int lane = tid & 31;
    const int g    = lane >> 2;
    const int tg   = lane & 3;

    const int lrow = tid >> 3;
    const int lc4  = (tid & 7) * 4;

    float acc[2][8][4];
#pragma unroll
    for (int i = 0; i < 2; i++)
#pragma unroll
        for (int j = 0; j < 8; j++)
#pragma unroll
            for (int r = 0; r < 4; r++) acc[i][j][r] = 0.0f;

    const int ntile = K / BK;

#define LOAD_TILE(T, STG)                                                         \
    {                                                                             \
        const int k0 = (T) * BK;                                                  \
        const uint32_t sb = smbase + (STG) * (BUFW * 4);                          \
        _Pragma("unroll")                                                         \
        for (int p = 0; p < 4; p++) {                                             \
            const int row = lrow + p * 32;                                        \
            cp16(sb + (row * LDS36 + lc4) * 4,                                    \
                 A + (size_t)(bm + row) * K + k0 + lc4);                          \
            cp16(sb + (APLNW + row * LDS36 + lc4) * 4,                            \
                 B + (size_t)(bn + row) * K + k0 + lc4);                          \
        }                                                                         \
    }

    LOAD_TILE(0, 0); cp_commit();
    LOAD_TILE(1, 1); cp_commit();

    int stg = 0;
    for (int t = 0; t < ntile; t++) {
        if (t + 1 < ntile) cp_wait<1>(); else cp_wait<0>();
        __syncthreads();

        if (t + 2 < ntile) {
            const int s2 = (stg + 2) % NSTG;
            LOAD_TILE(t + 2, s2);
            cp_commit();
        }

        const uint32_t* pA = smu + stg * BUFW;
        const uint32_t* pB = pA + APLNW;

#pragma unroll
        for (int kk = 0; kk < 4; kk++) {
            const int kc = kk * 8 + tg;
            uint32_t a[2][4], b[8][2];
#pragma unroll
            for (int mi = 0; mi < 2; mi++) {
                const int r = wm * 32 + mi * 16 + g;
                a[mi][0] = pA[r * LDS36 + kc];
                a[mi][1] = pA[(r + 8) * LDS36 + kc];
                a[mi][2] = pA[r * LDS36 + kc + 4];
                a[mi][3] = pA[(r + 8) * LDS36 + kc + 4];
            }
#pragma unroll
            for (int ni = 0; ni < 8; ni++) {
                const int r = wn * 64 + ni * 8 + g;
                b[ni][0] = pB[r * LDS36 + kc];
                b[ni][1] = pB[r * LDS36 + kc + 4];
            }
#pragma unroll
            for (int mi = 0; mi < 2; mi++)
#pragma unroll
                for (int ni = 0; ni < 8; ni++)
                    mma1688(acc[mi][ni], a[mi], b[ni]);
        }
        stg = (stg + 1) % NSTG;
    }
#undef LOAD_TILE

    // ---- epilogue ----
#pragma unroll
    for (int mi = 0; mi < 2; mi++) {
#pragma unroll
        for (int ni = 0; ni < 8; ni++) {
            const int m = bm + wm * 32 + mi * 16 + g;
            const int n = bn + wn * 64 + ni * 8 + tg * 2;
            const float b0 = bias[n], b1 = bias[n + 1];
#pragma unroll
            for (int h = 0; h < 2; h++) {
                const int mm = m + h * 8;
                float v0 = acc[mi][ni][h * 2 + 0] + b0;
                float v1 = acc[mi][ni][h * 2 + 1] + b1;
                if (EPI == EPI_RELU) {
                    v0 = roundtf(fmaxf(v0, 0.0f));
                    v1 = roundtf(fmaxf(v1, 0.0f));
                }
                if (EPI == EPI_QKV) {
                    v0 = roundtf(v0);
                    v1 = roundtf(v1);
                }
                if (EPI == EPI_RES) {
                    const float* rp = res + (size_t)mm * N + n;
                    v0 += rp[0]; v1 += rp[1];
                }
                float* cp = C + (size_t)mm * N + n;
                cp[0] = v0; cp[1] = v1;
            }
        }
    }
}

// ---------------- fp32 SGEMM (embed, K=80), writes h exact + h_t rounded -----
__global__ __launch_bounds__(256) void embed_kernel(
    const float* __restrict__ A, const float* __restrict__ B,
    const float* __restrict__ bias,
    float* __restrict__ C, float* __restrict__ Ct, int M, int N, int K)
{
    __shared__ float As[16][132];
    __shared__ float Bs[16][132];

    const int tid = threadIdx.x;
    const int bm = blockIdx.y * 128;
    const int bn = blockIdx.x * 128;

    const int lr = tid >> 2;
    const int lc = (tid & 3) * 4;
    const int ty = tid >> 4;
    const int tx = tid & 15;

    float acc[8][8];
#pragma unroll
    for (int i = 0; i < 8; i++)
#pragma unroll
        for (int j = 0; j < 8; j++) acc[i][j] = 0.0f;

    for (int k0 = 0; k0 < K; k0 += 16) {
#pragma unroll
        for (int p = 0; p < 2; p++) {
            const int row = lr + p * 64;
            float4 a = *(const float4*)(A + (size_t)(bm + row) * K + k0 + lc);
            float4 b = *(const float4*)(B + (size_t)(bn + row) * K + k0 + lc);
            As[lc + 0][row] = a.x; As[lc + 1][row] = a.y;
            As[lc + 2][row] = a.z; As[lc + 3][row] = a.w;
            Bs[lc + 0][row] = b.x; Bs[lc + 1][row] = b.y;
            Bs[lc + 2][row] = b.z; Bs[lc + 3][row] = b.w;
        }
        __syncthreads();
#pragma unroll
        for (int kk = 0; kk < 16; kk++) {
            float a[8], b[8];
            *(float4*)(a)     = *(const float4*)&As[kk][ty * 8];
            *(float4*)(a + 4) = *(const float4*)&As[kk][ty * 8 + 4];
            *(float4*)(b)     = *(const float4*)&Bs[kk][tx * 8];
            *(float4*)(b + 4) = *(const float4*)&Bs[kk][tx * 8 + 4];
#pragma unroll
            for (int i = 0; i < 8; i++)
#pragma unroll
                for (int j = 0; j < 8; j++)
                    acc[i][j] += a[i] * b[j];
        }
        __syncthreads();
    }

    const int m0 = bm + ty * 8;
    const int n0 = bn + tx * 8;
    float bv[8];
#pragma unroll
    for (int j = 0; j < 8; j++) bv[j] = bias[n0 + j];

#pragma unroll
    for (int i = 0; i < 8; i++) {
        const int m = m0 + i;
        const int s = m & (SMAX - 1);
#pragma unroll
        for (int j = 0; j < 8; j++) {
            const int n = n0 + j;
            float v = acc[i][j] + bv[j];
            const int de = n & ~1;
            float ang = (float)s * expf((float)de * (-9.210340371976184f / 512.0f));
            v += (n & 1) ? cosf(ang) : sinf(ang);
            const size_t ix = (size_t)m * N + n;
            C[ix]  = v;
            Ct[ix] = roundtf(v);
        }
    }
}

// =============================================================================
// Flash-style TF32 attention. CTA = (128 q, head, batch), 256 thr (8 warps).
// qkv is pre-rounded tf32 (EPI_QKV) -> loaders are plain copies.
// ATQ=128 halves the per-(b,h) K/V gmem reload factor vs ATQ=64.
// =============================================================================
#define ATQ   128
#define ALD   68                       // fp32 words per row (64 + 4 pad)
#define AQPL  (128 * ALD)              // Q / P pane words
#define AKPL  (64 * ALD)               // K / V pane words
#define ATTN_SMEM ((2 * AQPL + 2 * AKPL) * 4)   // 104448 B

__global__ __launch_bounds__(256) void fattn_kernel(
    const float* __restrict__ qkv, const int* __restrict__ lens,
    float* __restrict__ ctx)
{
    extern __shared__ float sf[];
    float* sQ = sf;                    // [128][68]
    float* sK = sf + AQPL;             // [64][68]
    float* sV = sf + AQPL + AKPL;      // transposed: [dh][key]
    float* sP = sf + AQPL + 2 * AKPL;  // [128][68]
    const uint32_t* pQ = (const uint32_t*)sQ;
    const uint32_t* pK = (const uint32_t*)sK;
    const uint32_t* pV = (const uint32_t*)sV;
    const uint32_t* pP = (const uint32_t*)sP;

    const int qt = blockIdx.x;
    const int hd = blockIdx.y;
    const int b  = blockIdx.z;
    const int tid  = threadIdx.x;
    const int w    = tid >> 5;
    const int lane = tid & 31;
    const int g    = lane >> 2;
    const int tg   = lane & 3;
    const int len  = lens[b];

    const float* base = qkv + (size_t)b * SMAX * (3 * DMODEL);

    // ---- load Q tile [128 x 64] (already tf32-rounded) ----
#pragma unroll
    for (int p = 0; p < 8; p++) {
        const int cid = p * 256 + tid;
        const int r  = cid >> 4;
        const int c4 = (cid & 15) * 4;
        *(float4*)(sQ + r * ALD + c4) =
            *(const float4*)(base + (size_t)(qt * ATQ + r) * (3 * DMODEL) + hd * DH + c4);
    }

    float sfr[8][4];
    float ofr[8][4];
#pragma unroll
    for (int j = 0; j < 8; j++)
#pragma unroll
        for (int c = 0; c < 4; c++) ofr[j][c] = 0.0f;
    float m0 = -1e30f, m1 = -1e30f, l0 = 0.0f, l1 = 0.0f;

    const int qrow = w * 16;

    for (int kt = 0; kt < 8; kt++) {
        __syncthreads();
        // ---- load K tile + V tile (transposed), plain copies ----
#pragma unroll
        for (int p = 0; p < 4; p++) {
            const int cid = p * 256 + tid;
            const int r  = cid >> 4;
            const int c4 = (cid & 15) * 4;
            const float* rowp = base + (size_t)(kt * 64 + r) * (3 * DMODEL) + hd * DH;
            *(float4*)(sK + r * ALD + c4) = *(const float4*)(rowp + DMODEL + c4);
            float4 vv = *(const float4*)(rowp + 2 * DMODEL + c4);
            sV[(c4 + 0) * ALD + r] = vv.x;
            sV[(c4 + 1) * ALD + r] = vv.y;
            sV[(c4 + 2) * ALD + r] = vv.z;
            sV[(c4 + 3) * ALD + r] = vv.w;
        }
        __syncthreads();

        // ---- S = Q K^T (single-pass tf32) ----
#pragma unroll
        for (int j = 0; j < 8; j++)
#pragma unroll
            for (int c = 0; c < 4; c++) sfr[j][c] = 0.0f;

#pragma unroll
        for (int kc = 0; kc < 8; kc++) {
            const int kcol = kc * 8 + tg;
            uint32_t a[4];
            a[0] = pQ[(qrow + g) * ALD + kcol];
            a[1] = pQ[(qrow + 8 + g) * ALD + kcol];
            a[2] = pQ[(qrow + g) * ALD + kcol + 4];
            a[3] = pQ[(qrow + 8 + g) * ALD + kcol + 4];
#pragma unroll
            for (int j = 0; j < 8; j++) {
                uint32_t bfr[2];
                bfr[0] = pK[(j * 8 + g) * ALD + kcol];
                bfr[1] = pK[(j * 8 + g) * ALD + kcol + 4];
                mma1688(sfr[j], a, bfr);
            }
        }

        // ---- scale + mask + online softmax update ----
        float tmax0 = -1e30f, tmax1 = -1e30f;
#pragma unroll
        for (int j = 0; j < 8; j++) {
            const int col = kt * 64 + j * 8 + 2 * tg;
            const bool v0 = col < len, v1 = (col + 1) < len;
            sfr[j][0] = v0 ? sfr[j][0] * 0.125f : -1e9f;
            sfr[j][1] = v1 ? sfr[j][1] * 0.125f : -1e9f;
            sfr[j][2] = v0 ? sfr[j][2] * 0.125f : -1e9f;
            sfr[j][3] = v1 ? sfr[j][3] * 0.125f : -1e9f;
            tmax0 = fmaxf(tmax0, fmaxf(sfr[j][0], sfr[j][1]));
            tmax1 = fmaxf(tmax1, fmaxf(sfr[j][2], sfr[j][3]));
        }
        tmax0 = fmaxf(tmax0, __shfl_xor_sync(0xffffffffu, tmax0, 1));
        tmax0 = fmaxf(tmax0, __shfl_xor_sync(0xffffffffu, tmax0, 2));
        tmax1 = fmaxf(tmax1, __shfl_xor_sync(0xffffffffu, tmax1, 1));
        tmax1 = fmaxf(tmax1, __shfl_xor_sync(0xffffffffu, tmax1, 2));

        const float nm0 = fmaxf(m0, tmax0), nm1 = fmaxf(m1, tmax1);
        const float al0 = expf(m0 - nm0), al1 = expf(m1 - nm1);
        m0 = nm0; m1 = nm1;

        float rs0 = 0.0f, rs1 = 0.0f;
#pragma unroll
        for (int j = 0; j < 8; j++) {
            sfr[j][0] = expf(sfr[j][0] - nm0);
            sfr[j][1] = expf(sfr[j][1] - nm0);
            sfr[j][2] = expf(sfr[j][2] - nm1);
            sfr[j][3] = expf(sfr[j][3] - nm1);
            rs0 += sfr[j][0] + sfr[j][1];
            rs1 += sfr[j][2] + sfr[j][3];
        }
        rs0 += __shfl_xor_sync(0xffffffffu, rs0, 1);
        rs0 += __shfl_xor_sync(0xffffffffu, rs0, 2);
        rs1 += __shfl_xor_sync(0xffffffffu, rs1, 1);
        rs1 += __shfl_xor_sync(0xffffffffu, rs1, 2);
        l0 = l0 * al0 + rs0;
        l1 = l1 * al1 + rs1;

#pragma unroll
        for (int j = 0; j < 8; j++) {
            ofr[j][0] *= al0; ofr[j][1] *= al0;
            ofr[j][2] *= al1; ofr[j][3] *= al1;
        }

        // ---- round P into warp-private smem pane ----
#pragma unroll
        for (int j = 0; j < 8; j++) {
            const int c0 = j * 8 + 2 * tg;
            sP[(qrow + g) * ALD + c0]         = roundtf(sfr[j][0]);
            sP[(qrow + g) * ALD + c0 + 1]     = roundtf(sfr[j][1]);
            sP[(qrow + 8 + g) * ALD + c0]     = roundtf(sfr[j][2]);
            sP[(qrow + 8 + g) * ALD + c0 + 1] = roundtf(sfr[j][3]);
        }
        __syncwarp();

        // ---- O += P V (single-pass tf32) ----
#pragma unroll
        for (int kc = 0; kc < 8; kc++) {
            const int kcol = kc * 8 + tg;
            uint32_t aP[4];
            aP[0] = pP[(qrow + g) * ALD + kcol];
            aP[1] = pP[(qrow + 8 + g) * ALD + kcol];
            aP[2] = pP[(qrow + g) * ALD + kcol + 4];
            aP[3] = pP[(qrow + 8 + g) * ALD + kcol + 4];
#pragma unroll
            for (int j = 0; j < 8; j++) {
                uint32_t bV[2];
                bV[0] = pV[(j * 8 + g) * ALD + kcol];
                bV[1] = pV[(j * 8 + g) * ALD + kcol + 4];
                mma1688(ofr[j], aP, bV);
            }
        }
    }

    // ---- finalize: O /= l, write ctx tf32-rounded ----
    const float inv0 = 1.0f / l0, inv1 = 1.0f / l1;
    const int q0 = qt * ATQ + qrow + g;
#pragma unroll
    for (int j = 0; j < 8; j++) {
        const int col = hd * DH + j * 8 + 2 * tg;
        float* p0 = ctx + ((size_t)b * SMAX + q0) * DMODEL + col;
        p0[0] = roundtf(ofr[j][0] * inv0);
        p0[1] = roundtf(ofr[j][1] * inv0);
        float* p1 = ctx + ((size_t)b * SMAX + q0 + 8) * DMODEL + col;
        p1[0] = roundtf(ofr[j][2] * inv1);
        p1[1] = roundtf(ofr[j][3] * inv1);
    }
}

// ---------------- LayerNorm (in place) + rounded copy -------------------------
__global__ __launch_bounds__(128) void ln_kernel(
    float* __restrict__ h, const float* __restrict__ g, const float* __restrict__ bta,
    float* __restrict__ ht)
{
    __shared__ float red[8];
    const int row = blockIdx.x;
    const int t = threadIdx.x;
    float* p = h + (size_t)row * DMODEL + t * 4;
    float4 v = *(float4*)p;
    float s  = v.x + v.y + v.z + v.w;
    float ss = v.x * v.x + v.y * v.y + v.z * v.z + v.w * v.w;
#pragma unroll
    for (int o = 16; o; o >>= 1) {
        s  += __shfl_xor_sync(0xffffffffu, s, o);
        ss += __shfl_xor_sync(0xffffffffu, ss, o);
    }
    const int w = t >> 5;
    if ((t & 31) == 0) { red[w] = s; red[4 + w] = ss; }
    __syncthreads();
    s  = red[0] + red[1] + red[2] + red[3];
    ss = red[4] + red[5] + red[6] + red[7];
    const float mean = s * (1.0f / DMODEL);
    const float var  = ss * (1.0f / DMODEL) - mean * mean;
    const float rstd = rsqrtf(var + 1e-5f);
    float4 gg = *(const float4*)(g + t * 4);
    float4 bb = *(const float4*)(bta + t * 4);
    v.x = (v.x - mean) * rstd * gg.x + bb.x;
    v.y = (v.y - mean) * rstd * gg.y + bb.y;
    v.z = (v.z - mean) * rstd * gg.z + bb.z;
    v.w = (v.w - mean) * rstd * gg.w + bb.w;
    *(float4*)p = v;
    *(float4*)(ht + (size_t)row * DMODEL + t * 4) = roundtf4(v);
}

// ---------------- two-phase masked mean pooling ------------------------------
__global__ __launch_bounds__(128) void pool_part_kernel(
    const float* __restrict__ h, const int* __restrict__ lens, float* __restrict__ part)
{
    const int b = blockIdx.x;
    const int ch = blockIdx.y;
    const int d = threadIdx.x * 4;
    const int len = lens[b];
    const int t0 = ch * 64;
    int nt = len - t0;
    if (nt > 64) nt = 64;
    float4 s = {0.f, 0.f, 0.f, 0.f};
    for (int t = 0; t < nt; t++) {
        float4 v = *(const float4*)(h + ((size_t)b * SMAX + t0 + t) * DMODEL + d);
        s.x += v.x; s.y += v.y; s.z += v.z; s.w += v.w;
    }
    *(float4*)(part + (size_t)(b * 8 + ch) * DMODEL + d) = s;
}

__global__ __launch_bounds__(DMODEL) void pool_final_kernel(
    const float* __restrict__ part, const int* __restrict__ lens,
    float* __restrict__ out, int out_size)
{
    const int b = blockIdx.x;
    const int d = threadIdx.x;
    float s = 0.0f;
#pragma unroll
    for (int c = 0; c < 8; c++) s += part[(size_t)(b * 8 + c) * DMODEL + d];
    out[b * DMODEL + d] = s / (float)lens[b];
    if (d == 0 && out_size >= BATCH * DMODEL + BATCH)
        out[BATCH * DMODEL + b] = (float)lens[b];
}

// ---------------- launch ------------------------------------------------------
extern "C" void kernel_launch(void* const* d_in, const int* in_sizes, int n_in,
                              void* d_out, int out_size)
{
    (void)in_sizes; (void)n_in;
    const float* x     = (const float*)d_in[0];
    const int*   lens  = (const int*)  d_in[1];
    const float* We    = (const float*)d_in[2];
    const float* be    = (const float*)d_in[3];
    const float* Wqkv  = (const float*)d_in[4];
    const float* bqkv  = (const float*)d_in[5];
    const float* Wo    = (const float*)d_in[6];
    const float* bo    = (const float*)d_in[7];
    const float* ln1g  = (const float*)d_in[8];
    const float* ln1b  = (const float*)d_in[9];
    const float* W1    = (const float*)d_in[10];
    const float* b1    = (const float*)d_in[11];
    const float* W2    = (const float*)d_in[12];
    const float* b2    = (const float*)d_in[13];
    const float* ln2g  = (const float*)d_in[14];
    const float* ln2b  = (const float*)d_in[15];
    float* out = (float*)d_out;

    void *ph, *pht, *pqkv, *pctx, *pff, *ppool;
    void *pwq, *pwo, *pw1, *pw2;
    cudaGetSymbolAddress(&ph,    g_h);
    cudaGetSymbolAddress(&pht,   g_ht);
    cudaGetSymbolAddress(&pqkv,  g_qkv);
    cudaGetSymbolAddress(&pctx,  g_ctx);
    cudaGetSymbolAddress(&pff,   g_ff);
    cudaGetSymbolAddress(&ppool, g_pool);
    cudaGetSymbolAddress(&pwq,   g_wq_r);
    cudaGetSymbolAddress(&pwo,   g_wo_r);
    cudaGetSymbolAddress(&pw1,   g_w1_r);
    cudaGetSymbolAddress(&pw2,   g_w2_r);
    float* h    = (float*)ph;
    float* ht   = (float*)pht;
    float* qkv  = (float*)pqkv;
    float* ctx  = (float*)pctx;
    float* ff   = (float*)pff;
    float* pool = (float*)ppool;
    float* wq_r = (float*)pwq;
    float* wo_r = (float*)pwo;
    float* w1_r = (float*)pw1;
    float* w2_r = (float*)pw2;

    cudaFuncSetAttribute(fattn_kernel,
                         cudaFuncAttributeMaxDynamicSharedMemorySize, ATTN_SMEM);
    cudaFuncSetAttribute(bgemm_kernel<EPI_QKV>,
                         cudaFuncAttributeMaxDynamicSharedMemorySize, GSMEM);
    cudaFuncSetAttribute(bgemm_kernel<EPI_RELU>,
                         cudaFuncAttributeMaxDynamicSharedMemorySize, GSMEM);
    cudaFuncSetAttribute(bgemm_kernel<EPI_RES>,
                         cudaFuncAttributeMaxDynamicSharedMemorySize, GSMEM);

    // ---- round weights to tf32 (once per launch) ----
    round_kernel<<<NLAYERS * 3 * DMODEL * DMODEL / 1024, 256>>>(Wqkv, wq_r);
    round_kernel<<<NLAYERS * DMODEL * DMODEL / 1024, 256>>>(Wo, wo_r);
    round_kernel<<<NLAYERS * DFF * DMODEL / 1024, 256>>>(W1, w1_r);
    round_kernel<<<NLAYERS * DMODEL * DFF / 1024, 256>>>(W2, w2_r);

    // embedding + positional encoding: h (exact) + ht (rounded)
    embed_kernel<<<dim3(DMODEL / 128, NTOK / 128), 256>>>(
        x, We, be, h, ht, NTOK, DMODEL, INSZ);

    for (int l = 0; l < NLAYERS; l++) {
        const float* wq  = wq_r + (size_t)l * 3 * DMODEL * DMODEL;
        const float* bq  = bqkv + (size_t)l * 3 * DMODEL;
        const float* wo  = wo_r + (size_t)l * DMODEL * DMODEL;
        const float* bO  = bo   + (size_t)l * DMODEL;
        const float* w1  = w1_r + (size_t)l * DFF * DMODEL;
        const float* bf1 = b1   + (size_t)l * DFF;
        const float* w2  = w2_r + (size_t)l * DMODEL * DFF;
        const float* bf2 = b2   + (size_t)l * DMODEL;

        // qkv = round(ht @ wq^T + bq)
        bgemm_kernel<EPI_QKV><<<dim3(3 * DMODEL / 128, NTOK / 128), 256, GSMEM>>>(
            ht, wq, bq, nullptr, qkv, NTOK, 3 * DMODEL, DMODEL);

        // attention -> ctx (tf32-rounded)
        fattn_kernel<<<dim3(SMAX / ATQ, NHEAD, BATCH), 256, ATTN_SMEM>>>(qkv, lens, ctx);

        // h = h + ctx @ wo^T + bo
        bgemm_kernel<EPI_RES><<<dim3(DMODEL / 128, NTOK / 128), 256, GSMEM>>>(
            ctx, wo, bO, h, h, NTOK, DMODEL, DMODEL);
        ln_kernel<<<NTOK, 128>>>(h, ln1g + l * DMODEL, ln1b + l * DMODEL, ht);

        // ff = round(relu(ht @ w1^T + b1))
        bgemm_kernel<EPI_RELU><<<dim3(DFF / 128, NTOK / 128), 256, GSMEM>>>(
            ht, w1, bf1, nullptr, ff, NTOK, DFF, DMODEL);
        // h = h + ff @ w2^T + b2
        bgemm_kernel<EPI_RES><<<dim3(DMODEL / 128, NTOK / 128), 256, GSMEM>>>(
            ff, w2, bf2, h, h, NTOK, DMODEL, DFF);
        ln_kernel<<<NTOK, 128>>>(h, ln2g + l * DMODEL, ln2b + l * DMODEL, ht);
    }

    pool_part_kernel<<<dim3(BATCH, 8), 128>>>(h, lens, pool);
    pool_final_kernel<<<BATCH, DMODEL>>>(pool, lens, out, out_size);
}